// round 1
// baseline (speedup 1.0000x reference)
#include <cuda_runtime.h>
#include <math.h>

#define DUMMY_CLASS 100

// Problem sizes
#define NB   32
#define NLQ  1024
#define NT   1024
#define ND   1024
#define NK1  1025          // T+1 (with dummy row)
#define SLD  1028          // padded leading dim for attn (16B aligned)

// ---------------- scratch (device globals: no allocation allowed) ------------
__device__ float g_qp  [33554432];            // (B*LQ, D)
__device__ float g_kp  [33554432];            // (B*T,  D)
__device__ float g_kf  [33587200];            // (B, T+1, D)
__device__ float g_vsel[33554432];            // (B, T, D)
__device__ float g_attn[33685504];            // (B*LQ, SLD), 1025 valid cols
__device__ float g_aout[33554432];            // attention output (B*LQ, D)
__device__ float g_x1  [33554432];            // out*residual
__device__ float g_x2  [33554432];            // residual-out
__device__ float g_xcat[67108864];            // (B*LQ, 2048) = [o1|o2|residual]
__device__ int   g_pos [1024];
__device__ int   g_mask[1024];

// ---------------- pos / mask scan -------------------------------------------
__global__ void pos_kernel(const int* __restrict__ supp) {
    __shared__ int s[1024];
    int t = threadIdx.x;
    int m = (supp[t] != DUMMY_CLASS) ? 1 : 0;
    g_mask[t] = m;
    s[t] = m;
    __syncthreads();
    for (int off = 1; off < 1024; off <<= 1) {
        int v = (t >= off) ? s[t - off] : 0;
        __syncthreads();
        s[t] += v;
        __syncthreads();
    }
    int p = s[t] - 1;
    g_pos[t] = p < 0 ? 0 : p;
}

// ---------------- gather: build kf (with dummy) and v_sel --------------------
__global__ void gather_kernel(const float* __restrict__ v,
                              const float* __restrict__ dummy) {
    int t = blockIdx.x;          // 0..1024
    int b = blockIdx.y;          // 0..31
    int c = threadIdx.x;         // float4 index, 0..255
    float4 dv = ((const float4*)dummy)[c];
    long long kfIdx = ((long long)b * NK1 + t) * 256 + c;
    if (t == NT) {
        ((float4*)g_kf)[kfIdx] = dv;
        return;
    }
    int m = g_mask[t];
    int p = g_pos[t];
    long long src = ((long long)b * NT + p) * 256 + c;
    float4 kv, vv;
    if (m) {
        kv = ((const float4*)g_kp)[src];
        vv = ((const float4*)v)[src];
    } else {
        kv = dv;
        vv = make_float4(0.f, 0.f, 0.f, 0.f);
    }
    ((float4*)g_kf)[kfIdx] = kv;
    long long vIdx = ((long long)b * NT + t) * 256 + c;
    ((float4*)g_vsel)[vIdx] = vv;
}

// ---------------- NT GEMM: C = A * B^T (+bias)(+relu) ------------------------
// A: (M,K) row-major lda, B: (N,K) row-major ldb. 128x128x8 tile, 256 thr, 8x8.
__global__ void __launch_bounds__(256, 2) gemm_nt_kernel(
    const float* __restrict__ A, int lda, long long sA,
    const float* __restrict__ Bm, int ldb, long long sB,
    float* __restrict__ C, int ldc, long long sC,
    int M, int N, int K,
    const float* __restrict__ bias, int relu)
{
    __shared__ float As[8][128];
    __shared__ float Bs[8][128];
    const int bz = blockIdx.z;
    A  += (long long)bz * sA;
    Bm += (long long)bz * sB;
    C  += (long long)bz * sC;
    const int tid = threadIdx.x;
    const int tx = tid & 15, ty = tid >> 4;
    const int lrow = tid >> 1;
    const int lcol = (tid & 1) << 2;
    const int gar = blockIdx.y * 128 + lrow;
    const int gbr = blockIdx.x * 128 + lrow;
    const bool aok = gar < M;
    const bool bok = gbr < N;
    const float* Aptr = A  + (long long)gar * lda + lcol;
    const float* Bptr = Bm + (long long)gbr * ldb + lcol;

    float acc[8][8];
#pragma unroll
    for (int i = 0; i < 8; i++)
#pragma unroll
        for (int j = 0; j < 8; j++) acc[i][j] = 0.f;

    for (int k0 = 0; k0 < K; k0 += 8) {
        float4 av = aok ? *(const float4*)(Aptr + k0) : make_float4(0,0,0,0);
        float4 bv = bok ? *(const float4*)(Bptr + k0) : make_float4(0,0,0,0);
        As[lcol + 0][lrow] = av.x; As[lcol + 1][lrow] = av.y;
        As[lcol + 2][lrow] = av.z; As[lcol + 3][lrow] = av.w;
        Bs[lcol + 0][lrow] = bv.x; Bs[lcol + 1][lrow] = bv.y;
        Bs[lcol + 2][lrow] = bv.z; Bs[lcol + 3][lrow] = bv.w;
        __syncthreads();
#pragma unroll
        for (int kk = 0; kk < 8; kk++) {
            float a[8], b[8];
            *(float4*)(a)     = *(const float4*)(&As[kk][ty * 8]);
            *(float4*)(a + 4) = *(const float4*)(&As[kk][ty * 8 + 4]);
            *(float4*)(b)     = *(const float4*)(&Bs[kk][tx * 8]);
            *(float4*)(b + 4) = *(const float4*)(&Bs[kk][tx * 8 + 4]);
#pragma unroll
            for (int i = 0; i < 8; i++)
#pragma unroll
                for (int j = 0; j < 8; j++)
                    acc[i][j] = fmaf(a[i], b[j], acc[i][j]);
        }
        __syncthreads();
    }
#pragma unroll
    for (int i = 0; i < 8; i++) {
        int gi = blockIdx.y * 128 + ty * 8 + i;
        if (gi >= M) continue;
#pragma unroll
        for (int j = 0; j < 8; j++) {
            int gj = blockIdx.x * 128 + tx * 8 + j;
            if (gj >= N) continue;
            float vv = acc[i][j];
            if (bias) vv += bias[gj];
            if (relu && vv < 0.f) vv = 0.f;
            C[(long long)gi * ldc + gj] = vv;
        }
    }
}

// ---------------- NN GEMM: C = A * B -----------------------------------------
// A: (M,K) row-major lda, B: (K,N) row-major ldb.
__global__ void __launch_bounds__(256, 2) gemm_nn_kernel(
    const float* __restrict__ A, int lda, long long sA,
    const float* __restrict__ Bm, int ldb, long long sB,
    float* __restrict__ C, int ldc, long long sC,
    int M, int N, int K)
{
    __shared__ float As[8][128];
    __shared__ float Bs[8][128];
    const int bz = blockIdx.z;
    A  += (long long)bz * sA;
    Bm += (long long)bz * sB;
    C  += (long long)bz * sC;
    const int tid = threadIdx.x;
    const int tx = tid & 15, ty = tid >> 4;
    const int lrow = tid >> 1;
    const int lcol = (tid & 1) << 2;
    const int gar = blockIdx.y * 128 + lrow;
    const bool aok = gar < M;
    const float* Aptr = A + (long long)gar * lda + lcol;
    const int bkr = tid >> 5;             // 0..7 (k)
    const int bnc = (tid & 31) << 2;      // 0..124 (n)
    const int gbc = blockIdx.x * 128 + bnc;
    const bool bok = gbc < N;
    const float* Bptr = Bm + (long long)bkr * ldb + gbc;

    float acc[8][8];
#pragma unroll
    for (int i = 0; i < 8; i++)
#pragma unroll
        for (int j = 0; j < 8; j++) acc[i][j] = 0.f;

    for (int k0 = 0; k0 < K; k0 += 8) {
        float4 av = aok ? *(const float4*)(Aptr + k0) : make_float4(0,0,0,0);
        float4 bv = bok ? *(const float4*)(Bptr + (long long)k0 * ldb)
                        : make_float4(0,0,0,0);
        As[lcol + 0][lrow] = av.x; As[lcol + 1][lrow] = av.y;
        As[lcol + 2][lrow] = av.z; As[lcol + 3][lrow] = av.w;
        *(float4*)(&Bs[bkr][bnc]) = bv;
        __syncthreads();
#pragma unroll
        for (int kk = 0; kk < 8; kk++) {
            float a[8], b[8];
            *(float4*)(a)     = *(const float4*)(&As[kk][ty * 8]);
            *(float4*)(a + 4) = *(const float4*)(&As[kk][ty * 8 + 4]);
            *(float4*)(b)     = *(const float4*)(&Bs[kk][tx * 8]);
            *(float4*)(b + 4) = *(const float4*)(&Bs[kk][tx * 8 + 4]);
#pragma unroll
            for (int i = 0; i < 8; i++)
#pragma unroll
                for (int j = 0; j < 8; j++)
                    acc[i][j] = fmaf(a[i], b[j], acc[i][j]);
        }
        __syncthreads();
    }
#pragma unroll
    for (int i = 0; i < 8; i++) {
        int gi = blockIdx.y * 128 + ty * 8 + i;
        if (gi >= M) continue;
#pragma unroll
        for (int j = 0; j < 8; j++) {
            int gj = blockIdx.x * 128 + tx * 8 + j;
            if (gj >= N) continue;
            C[(long long)gi * ldc + gj] = acc[i][j];
        }
    }
}

// ---------------- softmax over rows of length 1025 (temperature 32) ----------
__global__ void softmax_kernel() {
    const long long r = blockIdx.x;
    float* p = g_attn + r * SLD;
    const int tid = threadIdx.x;
    __shared__ float s1[8];
    __shared__ float s2[8];

    float lm = -3.4e38f;
    for (int j = tid; j < NK1; j += 256) lm = fmaxf(lm, p[j]);
#pragma unroll
    for (int o = 16; o; o >>= 1) lm = fmaxf(lm, __shfl_xor_sync(0xffffffffu, lm, o));
    if ((tid & 31) == 0) s1[tid >> 5] = lm;
    __syncthreads();
    float m = s1[0];
#pragma unroll
    for (int i = 1; i < 8; i++) m = fmaxf(m, s1[i]);

    const float invT = 0.03125f;   // 1/sqrt(1024)
    float ls = 0.f;
    for (int j = tid; j < NK1; j += 256) {
        float e = __expf((p[j] - m) * invT);
        p[j] = e;
        ls += e;
    }
#pragma unroll
    for (int o = 16; o; o >>= 1) ls += __shfl_xor_sync(0xffffffffu, ls, o);
    if ((tid & 31) == 0) s2[tid >> 5] = ls;
    __syncthreads();
    float s = 0.f;
#pragma unroll
    for (int i = 0; i < 8; i++) s += s2[i];
    float inv = 1.f / s;
    for (int j = tid; j < NK1; j += 256) p[j] *= inv;
}

// ---------------- elementwise: x1 = out*q, x2 = q-out, xcat[:,1024:] = q ------
__global__ void ew_kernel(const float* __restrict__ q) {
    long long i = (long long)blockIdx.x * 256 + threadIdx.x;  // float4 index
    float4 o = ((const float4*)g_aout)[i];
    float4 qq = ((const float4*)q)[i];
    float4 a, b;
    a.x = o.x * qq.x; a.y = o.y * qq.y; a.z = o.z * qq.z; a.w = o.w * qq.w;
    b.x = qq.x - o.x; b.y = qq.y - o.y; b.z = qq.z - o.z; b.w = qq.w - o.w;
    ((float4*)g_x1)[i] = a;
    ((float4*)g_x2)[i] = b;
    long long row  = i >> 8;          // 256 float4 per 1024-row
    long long col4 = i & 255;
    ((float4*)g_xcat)[row * 512 + 256 + col4] = qq;
}

// ---------------- host launcher ----------------------------------------------
extern "C" void kernel_launch(void* const* d_in, const int* in_sizes, int n_in,
                              void* d_out, int out_size) {
    const float* q     = (const float*)d_in[0];
    const float* k     = (const float*)d_in[1];
    const float* v     = (const float*)d_in[2];
    const float* tsp   = (const float*)d_in[3];
    const int*   supp  = (const int*)  d_in[4];
    const float* w_qk  = (const float*)d_in[5];
    const float* dummy = (const float*)d_in[6];
    const float* w1    = (const float*)d_in[7];
    const float* b1    = (const float*)d_in[8];
    const float* w2    = (const float*)d_in[9];
    const float* b2    = (const float*)d_in[10];
    const float* w3    = (const float*)d_in[11];
    const float* b3    = (const float*)d_in[12];
    float* outp = (float*)d_out;
    float* tsp_outp = outp + (long long)NB * NLQ * ND;   // second output

    float *qp, *kp, *kf, *vsel, *attn, *aout, *x1, *x2, *xcat;
    cudaGetSymbolAddress((void**)&qp,   g_qp);
    cudaGetSymbolAddress((void**)&kp,   g_kp);
    cudaGetSymbolAddress((void**)&kf,   g_kf);
    cudaGetSymbolAddress((void**)&vsel, g_vsel);
    cudaGetSymbolAddress((void**)&attn, g_attn);
    cudaGetSymbolAddress((void**)&aout, g_aout);
    cudaGetSymbolAddress((void**)&x1,   g_x1);
    cudaGetSymbolAddress((void**)&x2,   g_x2);
    cudaGetSymbolAddress((void**)&xcat, g_xcat);

    // 1) mask/pos scan
    pos_kernel<<<1, 1024>>>(supp);

    // 2) qp = q @ Wqk^T   (32768,1024,1024)
    gemm_nt_kernel<<<dim3(8, 256, 1), 256>>>(
        q, ND, 0, w_qk, ND, 0, qp, ND, 0, NB * NLQ, ND, ND, nullptr, 0);

    // 3) kp = k @ Wqk^T
    gemm_nt_kernel<<<dim3(8, 256, 1), 256>>>(
        k, ND, 0, w_qk, ND, 0, kp, ND, 0, NB * NT, ND, ND, nullptr, 0);

    // 4) gather kf / v_sel
    gather_kernel<<<dim3(NK1, NB, 1), 256>>>(v, dummy);

    // 5) scores = qp @ kf^T (batched, N=1025, C ld=1028)
    gemm_nt_kernel<<<dim3(9, 8, NB), 256>>>(
        qp, ND, (long long)NLQ * ND,
        kf, ND, (long long)NK1 * ND,
        attn, SLD, (long long)NLQ * SLD,
        NLQ, NK1, ND, nullptr, 0);

    // 6) softmax (temperature folded)
    softmax_kernel<<<NB * NLQ, 256>>>();

    // 7) out = attn[:,:,:T] @ v_sel
    gemm_nn_kernel<<<dim3(8, 8, NB), 256>>>(
        attn, SLD, (long long)NLQ * SLD,
        vsel, ND, (long long)NT * ND,
        aout, ND, (long long)NLQ * ND,
        NLQ, ND, NT);

    // 8) tsp_out = attn[:,:,:T] @ tsp  -> second output
    gemm_nn_kernel<<<dim3(8, 8, NB), 256>>>(
        attn, SLD, (long long)NLQ * SLD,
        tsp, ND, (long long)NT * ND,
        tsp_outp, ND, (long long)NLQ * ND,
        NLQ, ND, NT);

    // 9) x1 = out*q, x2 = q-out, xcat[:,1024:2048] = q
    ew_kernel<<<32768, 256>>>(q);

    // 10) o1 = relu(x1 @ w1^T + b1) -> xcat[:, 0:512]
    gemm_nt_kernel<<<dim3(4, 256, 1), 256>>>(
        x1, ND, 0, w1, ND, 0, xcat, 2048, 0, NB * NLQ, 512, ND, b1, 1);

    // 11) o2 = relu(x2 @ w2^T + b2) -> xcat[:, 512:1024]
    gemm_nt_kernel<<<dim3(4, 256, 1), 256>>>(
        x2, ND, 0, w2, ND, 0, xcat + 512, 2048, 0, NB * NLQ, 512, ND, b2, 1);

    // 12) output = xcat @ w3^T + b3 -> first output
    gemm_nt_kernel<<<dim3(8, 256, 1), 256>>>(
        xcat, 2048, 0, w3, 2048, 0, outp, ND, 0, NB * NLQ, ND, 2048, b3, 0);
}

// round 4
// speedup vs baseline: 2.4776x; 2.4776x over previous
#include <cuda_runtime.h>
#include <cuda_bf16.h>
#include <stdint.h>

#define DUMMY_CLASS 100
#define NB   32
#define NLQ  1024
#define NT   1024
#define ND   1024
#define NK1  1025
#define SLD  1028
#define KFROWS 1280

typedef __nv_bfloat16 bf16;

// ---------------- scratch (device globals; no allocation allowed) ------------
__device__ __align__(16) bf16 g_xcat_hi[67108864];
__device__ __align__(16) bf16 g_xcat_lo[67108864];
__device__ __align__(16) bf16 g_k_hi  [33554432];
__device__ __align__(16) bf16 g_k_lo  [33554432];
__device__ __align__(16) bf16 g_wqk_hi[1048576];
__device__ __align__(16) bf16 g_wqk_lo[1048576];
__device__ __align__(16) bf16 g_w1_hi [524288];
__device__ __align__(16) bf16 g_w1_lo [524288];
__device__ __align__(16) bf16 g_w2_hi [524288];
__device__ __align__(16) bf16 g_w2_lo [524288];
__device__ __align__(16) bf16 g_w3_hi [2097152];
__device__ __align__(16) bf16 g_w3_lo [2097152];
__device__ __align__(16) bf16 g_dum_hi[1024];
__device__ __align__(16) bf16 g_dum_lo[1024];
__device__ __align__(16) bf16 g_qp_hi [33554432];
__device__ __align__(16) bf16 g_qp_lo [33554432];
__device__ __align__(16) bf16 g_kp_hi [33554432];
__device__ __align__(16) bf16 g_kp_lo [33554432];
__device__ __align__(16) bf16 g_kf_hi [41943040];   // 32*1280*1024
__device__ __align__(16) bf16 g_kf_lo [41943040];
__device__ __align__(16) bf16 g_vT_hi [33554432];
__device__ __align__(16) bf16 g_vT_lo [33554432];
__device__ __align__(16) bf16 g_tT_hi [33554432];
__device__ __align__(16) bf16 g_tT_lo [33554432];
__device__ float g_attn[33685504];                   // 32*1024*1028
__device__ __align__(16) bf16 g_at_hi [33554432];
__device__ __align__(16) bf16 g_at_lo [33554432];
__device__ float g_aout[33554432];
__device__ __align__(16) bf16 g_x1_hi [33554432];
__device__ __align__(16) bf16 g_x1_lo [33554432];
__device__ __align__(16) bf16 g_x2_hi [33554432];
__device__ __align__(16) bf16 g_x2_lo [33554432];
__device__ int g_pos [1024];
__device__ int g_mask[1024];

// ---------------- helpers ----------------------------------------------------
__device__ __forceinline__ uint32_t smem_u32(const void* p) {
    uint32_t a;
    asm("{ .reg .u64 t; cvta.to.shared.u64 t, %1; cvt.u32.u64 %0, t; }"
        : "=r"(a) : "l"(p));
    return a;
}
__device__ __forceinline__ void cp16(uint32_t dst, const void* src) {
    asm volatile("cp.async.cg.shared.global [%0], [%1], 16;"
                 :: "r"(dst), "l"(src) : "memory");
}
__device__ __forceinline__ void cp_commit() {
    asm volatile("cp.async.commit_group;" ::: "memory");
}
__device__ __forceinline__ void ldm4(uint32_t* r, uint32_t addr) {
    asm volatile("ldmatrix.sync.aligned.m8n8.x4.shared.b16 {%0,%1,%2,%3}, [%4];"
                 : "=r"(r[0]), "=r"(r[1]), "=r"(r[2]), "=r"(r[3]) : "r"(addr));
}
__device__ __forceinline__ void mma16816(float* c, const uint32_t* a, const uint32_t* b) {
    asm volatile("mma.sync.aligned.m16n8k16.row.col.f32.bf16.bf16.f32 "
                 "{%0,%1,%2,%3}, {%4,%5,%6,%7}, {%8,%9}, {%0,%1,%2,%3};"
                 : "+f"(c[0]), "+f"(c[1]), "+f"(c[2]), "+f"(c[3])
                 : "r"(a[0]), "r"(a[1]), "r"(a[2]), "r"(a[3]), "r"(b[0]), "r"(b[1]));
}
__device__ __forceinline__ void hilo(float v, bf16& h, bf16& l) {
    h = __float2bfloat16_rn(v);
    l = __float2bfloat16_rn(v - __bfloat162float(h));
}
__device__ __forceinline__ uint32_t pack2(bf16 a, bf16 b) {
    return (uint32_t)__bfloat16_as_ushort(a) | ((uint32_t)__bfloat16_as_ushort(b) << 16);
}

// ---------------- pos / mask scan --------------------------------------------
__global__ void pos_kernel(const int* __restrict__ supp) {
    __shared__ int s[1024];
    int t = threadIdx.x;
    int m = (supp[t] != DUMMY_CLASS) ? 1 : 0;
    g_mask[t] = m;
    s[t] = m;
    __syncthreads();
    for (int off = 1; off < 1024; off <<= 1) {
        int v = (t >= off) ? s[t - off] : 0;
        __syncthreads();
        s[t] += v;
        __syncthreads();
    }
    int p = s[t] - 1;
    g_pos[t] = p < 0 ? 0 : p;
}

// ---------------- fp32 -> bf16 hi/lo conversion ------------------------------
__global__ void conv_kernel(const float* __restrict__ src,
                            bf16* __restrict__ hi, bf16* __restrict__ lo,
                            int cols4, int lddst) {
    int i4 = blockIdx.x * 256 + threadIdx.x;
    float4 v = ((const float4*)src)[i4];
    long long row = i4 / cols4;
    int c4 = i4 % cols4;
    long long o = row * (long long)lddst + (long long)c4 * 4;
    bf16 h0, h1, h2, h3, l0, l1, l2, l3;
    hilo(v.x, h0, l0); hilo(v.y, h1, l1); hilo(v.z, h2, l2); hilo(v.w, h3, l3);
    uint2 uh; uh.x = pack2(h0, h1); uh.y = pack2(h2, h3);
    uint2 ul; ul.x = pack2(l0, l1); ul.y = pack2(l2, l3);
    *(uint2*)(hi + o) = uh;
    *(uint2*)(lo + o) = ul;
}

// ---------------- gather: build kf hi/lo from kp hi/lo -----------------------
__global__ void gather_kf_kernel() {
    int t = blockIdx.x;      // 0..1024
    int b = blockIdx.y;
    int tid = threadIdx.x;   // 256
    const uint4* sh;
    const uint4* sl;
    if (t == NT || g_mask[t] == 0) {
        sh = (const uint4*)g_dum_hi;
        sl = (const uint4*)g_dum_lo;
    } else {
        long long ro = ((long long)b * NT + g_pos[t]) * ND;
        sh = (const uint4*)(g_kp_hi + ro);
        sl = (const uint4*)(g_kp_lo + ro);
    }
    long long doff = ((long long)b * KFROWS + t) * ND;
    if (tid < 128) ((uint4*)(g_kf_hi + doff))[tid] = sh[tid];
    else           ((uint4*)(g_kf_lo + doff))[tid - 128] = sl[tid - 128];
}

// ---------------- transpose + convert (optionally gathered) ------------------
__global__ void transpose_conv_kernel(const float* __restrict__ src,
                                      bf16* __restrict__ dhi, bf16* __restrict__ dlo,
                                      int gathered) {
    __shared__ float tile[64][65];
    int b = blockIdx.z;
    int t0 = blockIdx.y * 64;
    int d0 = blockIdx.x * 64;
    int tid = threadIdx.x;
#pragma unroll
    for (int j = 0; j < 4; j++) {
        int i = tid + j * 256;
        int r = i >> 4;
        int c4 = i & 15;
        int tg = t0 + r;
        int srow = tg;
        bool z = false;
        if (gathered) { z = (g_mask[tg] == 0); srow = g_pos[tg]; }
        float4 v = z ? make_float4(0.f, 0.f, 0.f, 0.f)
                     : ((const float4*)src)[((long long)b * NT + srow) * 256 + (d0 >> 2) + c4];
        tile[r][c4 * 4 + 0] = v.x; tile[r][c4 * 4 + 1] = v.y;
        tile[r][c4 * 4 + 2] = v.z; tile[r][c4 * 4 + 3] = v.w;
    }
    __syncthreads();
#pragma unroll
    for (int j = 0; j < 4; j++) {
        int i = tid + j * 256;
        int r = i >> 4;
        int c4 = i & 15;
        bf16 h[4], l[4];
#pragma unroll
        for (int e = 0; e < 4; e++) hilo(tile[c4 * 4 + e][r], h[e], l[e]);
        long long o = ((long long)b * ND + d0 + r) * (long long)NT + t0 + c4 * 4;
        uint2 uh; uh.x = pack2(h[0], h[1]); uh.y = pack2(h[2], h[3]);
        uint2 ul; ul.x = pack2(l[0], l[1]); ul.y = pack2(l[2], l[3]);
        *(uint2*)(dhi + o) = uh;
        *(uint2*)(dlo + o) = ul;
    }
}

// ---------------- split-bf16 HMMA GEMM (NT): C = A * B^T ---------------------
// A row-major (M,K) hi/lo, B row-major (N,K) hi/lo. CTA 128x128, K-chunk 64,
// 3-stage cp.async pipeline, 8 warps each 64x32, mma.sync m16n8k16 bf16.
#define KC      64
#define STAGES  3
#define OFF_AH  0
#define OFF_AL  16384
#define OFF_BH  32768
#define OFF_BL  49152
#define STAGE_B 65536
#define SMEM_BYTES (STAGES * STAGE_B)

__global__ void __launch_bounds__(256, 1) gemm_bf_kernel(
    const bf16* __restrict__ Ahi, const bf16* __restrict__ Alo, int lda, long long sA,
    const bf16* __restrict__ Bhi, const bf16* __restrict__ Blo, int ldb, long long sB,
    float* __restrict__ Cf, bf16* __restrict__ Chi, bf16* __restrict__ Clo,
    int ldc, long long sC, int coloff,
    int N, int K, const float* __restrict__ bias, int relu)
{
    extern __shared__ __align__(1024) char smem[];
    const uint32_t sb = smem_u32(smem);
    const int tid = threadIdx.x;
    const int wid = tid >> 5;
    const int l   = tid & 31;

    const long long bz = blockIdx.z;
    const bf16* pAh = Ahi + bz * sA + (long long)(blockIdx.y * 128) * lda;
    const bf16* pAl = Alo + bz * sA + (long long)(blockIdx.y * 128) * lda;
    const bf16* pBh = Bhi + bz * sB + (long long)(blockIdx.x * 128) * ldb;
    const bf16* pBl = Blo + bz * sB + (long long)(blockIdx.x * 128) * ldb;
    const int S = K / KC;

    // cp.async assignment: 1024 chunks (16B) per tile; 256 thr x 4
    const int crow = tid >> 1;                 // rows 0..127
    const int cc0  = (tid & 1) << 2;           // chunk 0..7 (two threads/row, 4 each)

    auto load_stage = [&](int s) {
        uint32_t bp = sb + (s % STAGES) * STAGE_B;
        long long k0 = (long long)s * KC;
        const bf16* rAh = pAh + (long long)crow * lda + k0;
        const bf16* rAl = pAl + (long long)crow * lda + k0;
        const bf16* rBh = pBh + (long long)crow * ldb + k0;
        const bf16* rBl = pBl + (long long)crow * ldb + k0;
        uint32_t rowo = (uint32_t)crow * 128;
        uint32_t x = (uint32_t)(crow & 7) << 4;
#pragma unroll
        for (int j = 0; j < 4; j++) {
            int c = cc0 + j;
            uint32_t o = rowo + (((uint32_t)c << 4) ^ x);
            cp16(bp + OFF_AH + o, rAh + c * 8);
            cp16(bp + OFF_AL + o, rAl + c * 8);
            cp16(bp + OFF_BH + o, rBh + c * 8);
            cp16(bp + OFF_BL + o, rBl + c * 8);
        }
    };

    load_stage(0); cp_commit();
    load_stage(1); cp_commit();

    // per-lane ldmatrix bases
    const int wm = wid & 1;          // 0..1 -> 64-row half
    const int wn = wid >> 1;         // 0..3 -> 32-col quarter
    const int arow = wm * 64 + (l & 15);
    const uint32_t aco = ((uint32_t)(l >> 4) << 4);          // +0/16 B (k half)
    const uint32_t axor = (uint32_t)(arow & 7) << 4;
    const int brow = wn * 32 + (l & 7) + ((l >> 4) << 3);
    const uint32_t bco = ((uint32_t)((l >> 3) & 1) << 4);
    const uint32_t bxor = (uint32_t)(brow & 7) << 4;

    float acc[4][4][4];
#pragma unroll
    for (int mf = 0; mf < 4; mf++)
#pragma unroll
        for (int nf = 0; nf < 4; nf++)
#pragma unroll
            for (int e = 0; e < 4; e++) acc[mf][nf][e] = 0.f;

    for (int s = 0; s < S; s++) {
        if (s == S - 1) asm volatile("cp.async.wait_group 0;" ::: "memory");
        else            asm volatile("cp.async.wait_group 1;" ::: "memory");
        __syncthreads();
        if (s + 2 < S) { load_stage(s + 2); cp_commit(); }

        uint32_t bp = sb + (s % STAGES) * STAGE_B;
        uint32_t aBase = bp + OFF_AH + (uint32_t)arow * 128;
        uint32_t aBaseL = bp + OFF_AL + (uint32_t)arow * 128;
        uint32_t bBase = bp + OFF_BH + (uint32_t)brow * 128;
        uint32_t bBaseL = bp + OFF_BL + (uint32_t)brow * 128;

#pragma unroll
        for (int k16 = 0; k16 < KC / 16; k16++) {
            uint32_t ak = (((uint32_t)k16 << 5) + aco) ^ axor;
            uint32_t bk = (((uint32_t)k16 << 5) + bco) ^ bxor;
            uint32_t ah[4][4], al[4][4], bh[4][2], bl[4][2];
#pragma unroll
            for (int mf = 0; mf < 4; mf++) {
                ldm4(ah[mf], aBase  + (uint32_t)(mf * 16) * 128 + ak);
                ldm4(al[mf], aBaseL + (uint32_t)(mf * 16) * 128 + ak);
            }
#pragma unroll
            for (int g = 0; g < 2; g++) {
                uint32_t r[4];
                ldm4(r, bBase + (uint32_t)(g * 16) * 128 + bk);
                bh[g*2][0] = r[0]; bh[g*2][1] = r[1];
                bh[g*2+1][0] = r[2]; bh[g*2+1][1] = r[3];
                ldm4(r, bBaseL + (uint32_t)(g * 16) * 128 + bk);
                bl[g*2][0] = r[0]; bl[g*2][1] = r[1];
                bl[g*2+1][0] = r[2]; bl[g*2+1][1] = r[3];
            }
#pragma unroll
            for (int mf = 0; mf < 4; mf++)
#pragma unroll
                for (int nf = 0; nf < 4; nf++) {
                    mma16816(acc[mf][nf], ah[mf], bh[nf]);
                    mma16816(acc[mf][nf], ah[mf], bl[nf]);
                    mma16816(acc[mf][nf], al[mf], bh[nf]);
                }
        }
        __syncthreads();
    }

    // ---- epilogue: lane holds (r, c)=(mf*16 + l>>2 [+8], nf*8 + 2*(l&3)) ----
    float* pCf = Cf ? Cf + bz * sC : (float*)0;
    bf16* pCh = Chi ? Chi + bz * sC : (bf16*)0;
    bf16* pCl = Clo ? Clo + bz * sC : (bf16*)0;
    const int gi0 = blockIdx.y * 128 + wm * 64 + (l >> 2);
    const int gj0 = blockIdx.x * 128 + wn * 32 + 2 * (l & 3);
#pragma unroll
    for (int mf = 0; mf < 4; mf++) {
        int gi = gi0 + mf * 16;
#pragma unroll
        for (int nf = 0; nf < 4; nf++) {
            int gj = gj0 + nf * 8;
            float v0 = acc[mf][nf][0], v1 = acc[mf][nf][1];
            float v2 = acc[mf][nf][2], v3 = acc[mf][nf][3];
            if (bias) {
                float b0 = (gj < N) ? bias[gj] : 0.f;
                float b1 = (gj + 1 < N) ? bias[gj + 1] : 0.f;
                v0 += b0; v1 += b1; v2 += b0; v3 += b1;
            }
            if (relu) {
                v0 = fmaxf(v0, 0.f); v1 = fmaxf(v1, 0.f);
                v2 = fmaxf(v2, 0.f); v3 = fmaxf(v3, 0.f);
            }
            long long o0 = (long long)gi * ldc + coloff + gj;
            long long o1 = o0 + (long long)8 * ldc;
            if (pCf) {
                if (gj + 1 < N) {
                    *(float2*)(pCf + o0) = make_float2(v0, v1);
                    *(float2*)(pCf + o1) = make_float2(v2, v3);
                } else if (gj < N) {
                    pCf[o0] = v0; pCf[o1] = v2;
                }
            } else if (gj + 1 < N || gj < N) {
                bf16 h0, h1, h2, h3, l0, l1, l2, l3;
                hilo(v0, h0, l0); hilo(v1, h1, l1);
                hilo(v2, h2, l2); hilo(v3, h3, l3);
                *(uint32_t*)(pCh + o0) = pack2(h0, h1);
                *(uint32_t*)(pCl + o0) = pack2(l0, l1);
                *(uint32_t*)(pCh + o1) = pack2(h2, h3);
                *(uint32_t*)(pCl + o1) = pack2(l2, l3);
            }
        }
    }
}

// ---------------- softmax: fp32 scores -> bf16 hi/lo attn --------------------
__global__ void softmax_kernel() {
    const long long r = blockIdx.x;
    float* p = g_attn + r * SLD;
    const int tid = threadIdx.x;
    __shared__ float s1[8];
    __shared__ float s2[8];

    float lm = -3.4e38f;
    for (int j = tid; j < NK1; j += 256) lm = fmaxf(lm, p[j]);
#pragma unroll
    for (int o = 16; o; o >>= 1) lm = fmaxf(lm, __shfl_xor_sync(0xffffffffu, lm, o));
    if ((tid & 31) == 0) s1[tid >> 5] = lm;
    __syncthreads();
    float m = s1[0];
#pragma unroll
    for (int i = 1; i < 8; i++) m = fmaxf(m, s1[i]);

    const float invT = 0.03125f;
    float ls = 0.f;
    for (int j = tid; j < NK1; j += 256) {
        float e = __expf((p[j] - m) * invT);
        p[j] = e;
        ls += e;
    }
#pragma unroll
    for (int o = 16; o; o >>= 1) ls += __shfl_xor_sync(0xffffffffu, ls, o);
    if ((tid & 31) == 0) s2[tid >> 5] = ls;
    __syncthreads();
    float s = 0.f;
#pragma unroll
    for (int i = 0; i < 8; i++) s += s2[i];
    float inv = 1.f / s;
    long long ob = r * (long long)NT;
    for (int j = tid; j < NT; j += 256) {
        float v = p[j] * inv;
        bf16 h, l; hilo(v, h, l);
        g_at_hi[ob + j] = h;
        g_at_lo[ob + j] = l;
    }
}

// ---------------- elementwise: x1 = out*q, x2 = q-out (hi/lo) ----------------
__global__ void ew_kernel(const float* __restrict__ q) {
    long long i = (long long)blockIdx.x * 256 + threadIdx.x;
    float4 o = ((const float4*)g_aout)[i];
    float4 qq = ((const float4*)q)[i];
    float a0 = o.x * qq.x, a1 = o.y * qq.y, a2 = o.z * qq.z, a3 = o.w * qq.w;
    float b0 = qq.x - o.x, b1 = qq.y - o.y, b2 = qq.z - o.z, b3 = qq.w - o.w;
    bf16 h0, h1, h2, h3, l0, l1, l2, l3;
    long long off = i * 4;
    hilo(a0, h0, l0); hilo(a1, h1, l1); hilo(a2, h2, l2); hilo(a3, h3, l3);
    { uint2 uh; uh.x = pack2(h0, h1); uh.y = pack2(h2, h3);
      uint2 ul; ul.x = pack2(l0, l1); ul.y = pack2(l2, l3);
      *(uint2*)(g_x1_hi + off) = uh; *(uint2*)(g_x1_lo + off) = ul; }
    hilo(b0, h0, l0); hilo(b1, h1, l1); hilo(b2, h2, l2); hilo(b3, h3, l3);
    { uint2 uh; uh.x = pack2(h0, h1); uh.y = pack2(h2, h3);
      uint2 ul; ul.x = pack2(l0, l1); ul.y = pack2(l2, l3);
      *(uint2*)(g_x2_hi + off) = uh; *(uint2*)(g_x2_lo + off) = ul; }
}

// ---------------- host launcher ----------------------------------------------
extern "C" void kernel_launch(void* const* d_in, const int* in_sizes, int n_in,
                              void* d_out, int out_size) {
    const float* q     = (const float*)d_in[0];
    const float* k     = (const float*)d_in[1];
    const float* v     = (const float*)d_in[2];
    const float* tsp   = (const float*)d_in[3];
    const int*   supp  = (const int*)  d_in[4];
    const float* w_qk  = (const float*)d_in[5];
    const float* dummy = (const float*)d_in[6];
    const float* w1    = (const float*)d_in[7];
    const float* b1    = (const float*)d_in[8];
    const float* w2    = (const float*)d_in[9];
    const float* b2    = (const float*)d_in[10];
    const float* w3    = (const float*)d_in[11];
    const float* b3    = (const float*)d_in[12];
    float* outp = (float*)d_out;
    float* tsp_outp = outp + (long long)NB * NLQ * ND;

    cudaFuncSetAttribute(gemm_bf_kernel,
                         cudaFuncAttributeMaxDynamicSharedMemorySize, SMEM_BYTES);

    bf16 *xcat_hi, *xcat_lo, *k_hi, *k_lo, *wqk_hi, *wqk_lo;
    bf16 *w1_hi, *w1_lo, *w2_hi, *w2_lo, *w3_hi, *w3_lo, *dum_hi, *dum_lo;
    bf16 *qp_hi, *qp_lo, *kp_hi, *kp_lo, *kf_hi, *kf_lo;
    bf16 *vT_hi, *vT_lo, *tT_hi, *tT_lo, *at_hi, *at_lo;
    bf16 *x1_hi, *x1_lo, *x2_hi, *x2_lo;
    float *attn, *aout;
    cudaGetSymbolAddress((void**)&xcat_hi, g_xcat_hi);
    cudaGetSymbolAddress((void**)&xcat_lo, g_xcat_lo);
    cudaGetSymbolAddress((void**)&k_hi, g_k_hi);
    cudaGetSymbolAddress((void**)&k_lo, g_k_lo);
    cudaGetSymbolAddress((void**)&wqk_hi, g_wqk_hi);
    cudaGetSymbolAddress((void**)&wqk_lo, g_wqk_lo);
    cudaGetSymbolAddress((void**)&w1_hi, g_w1_hi);
    cudaGetSymbolAddress((void**)&w1_lo, g_w1_lo);
    cudaGetSymbolAddress((void**)&w2_hi, g_w2_hi);
    cudaGetSymbolAddress((void**)&w2_lo, g_w2_lo);
    cudaGetSymbolAddress((void**)&w3_hi, g_w3_hi);
    cudaGetSymbolAddress((void**)&w3_lo, g_w3_lo);
    cudaGetSymbolAddress((void**)&dum_hi, g_dum_hi);
    cudaGetSymbolAddress((void**)&dum_lo, g_dum_lo);
    cudaGetSymbolAddress((void**)&qp_hi, g_qp_hi);
    cudaGetSymbolAddress((void**)&qp_lo, g_qp_lo);
    cudaGetSymbolAddress((void**)&kp_hi, g_kp_hi);
    cudaGetSymbolAddress((void**)&kp_lo, g_kp_lo);
    cudaGetSymbolAddress((void**)&kf_hi, g_kf_hi);
    cudaGetSymbolAddress((void**)&kf_lo, g_kf_lo);
    cudaGetSymbolAddress((void**)&vT_hi, g_vT_hi);
    cudaGetSymbolAddress((void**)&vT_lo, g_vT_lo);
    cudaGetSymbolAddress((void**)&tT_hi, g_tT_hi);
    cudaGetSymbolAddress((void**)&tT_lo, g_tT_lo);
    cudaGetSymbolAddress((void**)&at_hi, g_at_hi);
    cudaGetSymbolAddress((void**)&at_lo, g_at_lo);
    cudaGetSymbolAddress((void**)&x1_hi, g_x1_hi);
    cudaGetSymbolAddress((void**)&x1_lo, g_x1_lo);
    cudaGetSymbolAddress((void**)&x2_hi, g_x2_hi);
    cudaGetSymbolAddress((void**)&x2_lo, g_x2_lo);
    cudaGetSymbolAddress((void**)&attn, g_attn);
    cudaGetSymbolAddress((void**)&aout, g_aout);

    // 1) pos/mask
    pos_kernel<<<1, 1024>>>(supp);

    // 2) conversions
    conv_kernel<<<32768, 256>>>(q, xcat_hi + 1024, xcat_lo + 1024, 256, 2048);
    conv_kernel<<<32768, 256>>>(k, k_hi, k_lo, 256, 1024);
    conv_kernel<<<1024, 256>>>(w_qk, wqk_hi, wqk_lo, 256, 1024);
    conv_kernel<<<512, 256>>>(w1, w1_hi, w1_lo, 256, 1024);
    conv_kernel<<<512, 256>>>(w2, w2_hi, w2_lo, 256, 1024);
    conv_kernel<<<2048, 256>>>(w3, w3_hi, w3_lo, 512, 2048);
    conv_kernel<<<1, 256>>>(dummy, dum_hi, dum_lo, 256, 1024);

    // 3) qp = q @ Wqk^T  (hi/lo out)
    gemm_bf_kernel<<<dim3(8, 256, 1), 256, SMEM_BYTES>>>(
        xcat_hi + 1024, xcat_lo + 1024, 2048, 0,
        wqk_hi, wqk_lo, 1024, 0,
        (float*)0, qp_hi, qp_lo, 1024, 0, 0, 1024, 1024, (const float*)0, 0);

    // 4) kp = k @ Wqk^T  (hi/lo out)
    gemm_bf_kernel<<<dim3(8, 256, 1), 256, SMEM_BYTES>>>(
        k_hi, k_lo, 1024, 0,
        wqk_hi, wqk_lo, 1024, 0,
        (float*)0, kp_hi, kp_lo, 1024, 0, 0, 1024, 1024, (const float*)0, 0);

    // 5) gather kf, build vT/tT
    gather_kf_kernel<<<dim3(NK1, NB, 1), 256>>>();
    transpose_conv_kernel<<<dim3(16, 16, NB), 256>>>(v, vT_hi, vT_lo, 1);
    transpose_conv_kernel<<<dim3(16, 16, NB), 256>>>(tsp, tT_hi, tT_lo, 0);

    // 6) scores = qp @ kf^T  (fp32 out, N=1025; kf has 1280 rows allocated)
    gemm_bf_kernel<<<dim3(9, 8, NB), 256, SMEM_BYTES>>>(
        qp_hi, qp_lo, 1024, (long long)NLQ * ND,
        kf_hi, kf_lo, 1024, (long long)KFROWS * ND,
        attn, (bf16*)0, (bf16*)0, SLD, (long long)NLQ * SLD, 0,
        NK1, 1024, (const float*)0, 0);

    // 7) softmax -> attn hi/lo
    softmax_kernel<<<NB * NLQ, 256>>>();

    // 8) out = attn @ v_sel  (fp32)
    gemm_bf_kernel<<<dim3(8, 8, NB), 256, SMEM_BYTES>>>(
        at_hi, at_lo, 1024, (long long)NLQ * ND,
        vT_hi, vT_lo, 1024, (long long)ND * NT,
        aout, (bf16*)0, (bf16*)0, 1024, (long long)NLQ * ND, 0,
        1024, 1024, (const float*)0, 0);

    // 9) tsp_out = attn @ tsp -> second output
    gemm_bf_kernel<<<dim3(8, 8, NB), 256, SMEM_BYTES>>>(
        at_hi, at_lo, 1024, (long long)NLQ * ND,
        tT_hi, tT_lo, 1024, (long long)ND * NT,
        tsp_outp, (bf16*)0, (bf16*)0, 1024, (long long)NLQ * ND, 0,
        1024, 1024, (const float*)0, 0);

    // 10) x1 = out*q, x2 = q-out (hi/lo)
    ew_kernel<<<32768, 256>>>(q);

    // 11) o1 = relu(x1 @ w1^T + b1) -> xcat[:, 0:512] (hi/lo)
    gemm_bf_kernel<<<dim3(4, 256, 1), 256, SMEM_BYTES>>>(
        x1_hi, x1_lo, 1024, 0,
        w1_hi, w1_lo, 1024, 0,
        (float*)0, xcat_hi, xcat_lo, 2048, 0, 0, 512, 1024, b1, 1);

    // 12) o2 = relu(x2 @ w2^T + b2) -> xcat[:, 512:1024] (hi/lo)
    gemm_bf_kernel<<<dim3(4, 256, 1), 256, SMEM_BYTES>>>(
        x2_hi, x2_lo, 1024, 0,
        w2_hi, w2_lo, 1024, 0,
        (float*)0, xcat_hi, xcat_lo, 2048, 0, 512, 512, 1024, b2, 1);

    // 13) output = xcat @ w3^T + b3 -> first output (fp32)
    gemm_bf_kernel<<<dim3(8, 256, 1), 256, SMEM_BYTES>>>(
        xcat_hi, xcat_lo, 2048, 0,
        w3_hi, w3_lo, 2048, 0,
        outp, (bf16*)0, (bf16*)0, 1024, 0, 0, 1024, 2048, b3, 0);
}

// round 5
// speedup vs baseline: 3.4599x; 1.3965x over previous
#include <cuda_runtime.h>
#include <cuda_fp16.h>
#include <stdint.h>

#define DUMMY_CLASS 100
#define NB   32
#define NLQ  1024
#define NT   1024
#define ND   1024
#define NK1  1025
#define SLD  1028
#define KFROWS 1280

// ---------------- scratch (device globals; no allocation allowed) ------------
__device__ __align__(16) half g_xcat_hi[67108864];  // (B*LQ, 2048): [o1|o2|q]
__device__ __align__(16) half g_k_hi  [33554432];
__device__ __align__(16) half g_wqk_hi[1048576];
__device__ __align__(16) half g_wqk_lo[1048576];
__device__ __align__(16) half g_w1_hi [524288];
__device__ __align__(16) half g_w1_lo [524288];
__device__ __align__(16) half g_w2_hi [524288];
__device__ __align__(16) half g_w2_lo [524288];
__device__ __align__(16) half g_w3_hi [2097152];
__device__ __align__(16) half g_w3_lo [2097152];
__device__ __align__(16) half g_dum_hi[1024];
__device__ __align__(16) half g_dum_lo[1024];
__device__ __align__(16) half g_qp_hi [33554432];
__device__ __align__(16) half g_kp_hi [33554432];
__device__ __align__(16) half g_kp_lo [33554432];
__device__ __align__(16) half g_kf_hi [41943040];   // 32*1280*1024
__device__ __align__(16) half g_kf_lo [41943040];
__device__ __align__(16) half g_vT_hi [33554432];
__device__ __align__(16) half g_vT_lo [33554432];
__device__ __align__(16) half g_tT_hi [33554432];
__device__ __align__(16) half g_tT_lo [33554432];
__device__ float g_attn[33685504];                   // 32*1024*1028
__device__ __align__(16) half g_at_hi [33554432];
__device__ __align__(16) half g_x1_hi [33554432];
__device__ __align__(16) half g_x2_hi [33554432];
__device__ int g_pos [1024];
__device__ int g_mask[1024];

// ---------------- helpers ----------------------------------------------------
__device__ __forceinline__ uint32_t smem_u32(const void* p) {
    uint32_t a;
    asm("{ .reg .u64 t; cvta.to.shared.u64 t, %1; cvt.u32.u64 %0, t; }"
        : "=r"(a) : "l"(p));
    return a;
}
__device__ __forceinline__ void cp16(uint32_t dst, const void* src) {
    asm volatile("cp.async.cg.shared.global [%0], [%1], 16;"
                 :: "r"(dst), "l"(src) : "memory");
}
__device__ __forceinline__ void cp_commit() {
    asm volatile("cp.async.commit_group;" ::: "memory");
}
__device__ __forceinline__ void ldm4(uint32_t* r, uint32_t addr) {
    asm volatile("ldmatrix.sync.aligned.m8n8.x4.shared.b16 {%0,%1,%2,%3}, [%4];"
                 : "=r"(r[0]), "=r"(r[1]), "=r"(r[2]), "=r"(r[3]) : "r"(addr));
}
__device__ __forceinline__ void mma16816(float* c, const uint32_t* a, const uint32_t* b) {
    asm volatile("mma.sync.aligned.m16n8k16.row.col.f32.f16.f16.f32 "
                 "{%0,%1,%2,%3}, {%4,%5,%6,%7}, {%8,%9}, {%0,%1,%2,%3};"
                 : "+f"(c[0]), "+f"(c[1]), "+f"(c[2]), "+f"(c[3])
                 : "r"(a[0]), "r"(a[1]), "r"(a[2]), "r"(a[3]), "r"(b[0]), "r"(b[1]));
}
__device__ __forceinline__ void hilo(float v, half& h, half& l) {
    h = __float2half_rn(v);
    l = __float2half_rn(v - __half2float(h));
}
__device__ __forceinline__ uint32_t pack2(half a, half b) {
    return (uint32_t)__half_as_ushort(a) | ((uint32_t)__half_as_ushort(b) << 16);
}

// ---------------- pos / mask scan --------------------------------------------
__global__ void pos_kernel(const int* __restrict__ supp) {
    __shared__ int s[1024];
    int t = threadIdx.x;
    int m = (supp[t] != DUMMY_CLASS) ? 1 : 0;
    g_mask[t] = m;
    s[t] = m;
    __syncthreads();
    for (int off = 1; off < 1024; off <<= 1) {
        int v = (t >= off) ? s[t - off] : 0;
        __syncthreads();
        s[t] += v;
        __syncthreads();
    }
    int p = s[t] - 1;
    g_pos[t] = p < 0 ? 0 : p;
}

// ---------------- fp32 -> fp16 hi(/lo) conversion ----------------------------
__global__ void conv_kernel(const float* __restrict__ src,
                            half* __restrict__ hi, half* __restrict__ lo,
                            int cols4, int lddst) {
    int i4 = blockIdx.x * 256 + threadIdx.x;
    float4 v = ((const float4*)src)[i4];
    long long row = i4 / cols4;
    int c4 = i4 % cols4;
    long long o = row * (long long)lddst + (long long)c4 * 4;
    half h0, h1, h2, h3, l0, l1, l2, l3;
    hilo(v.x, h0, l0); hilo(v.y, h1, l1); hilo(v.z, h2, l2); hilo(v.w, h3, l3);
    uint2 uh; uh.x = pack2(h0, h1); uh.y = pack2(h2, h3);
    *(uint2*)(hi + o) = uh;
    if (lo) {
        uint2 ul; ul.x = pack2(l0, l1); ul.y = pack2(l2, l3);
        *(uint2*)(lo + o) = ul;
    }
}

// ---------------- gather: build kf hi/lo from kp hi/lo -----------------------
__global__ void gather_kf_kernel() {
    int t = blockIdx.x;      // 0..1024
    int b = blockIdx.y;
    int tid = threadIdx.x;   // 256
    const uint4* sh;
    const uint4* sl;
    if (t == NT || g_mask[t] == 0) {
        sh = (const uint4*)g_dum_hi;
        sl = (const uint4*)g_dum_lo;
    } else {
        long long ro = ((long long)b * NT + g_pos[t]) * ND;
        sh = (const uint4*)(g_kp_hi + ro);
        sl = (const uint4*)(g_kp_lo + ro);
    }
    long long doff = ((long long)b * KFROWS + t) * ND;
    if (tid < 128) ((uint4*)(g_kf_hi + doff))[tid] = sh[tid];
    else           ((uint4*)(g_kf_lo + doff))[tid - 128] = sl[tid - 128];
}

// ---------------- transpose + convert (optionally gathered) ------------------
__global__ void transpose_conv_kernel(const float* __restrict__ src,
                                      half* __restrict__ dhi, half* __restrict__ dlo,
                                      int gathered) {
    __shared__ float tile[64][65];
    int b = blockIdx.z;
    int t0 = blockIdx.y * 64;
    int d0 = blockIdx.x * 64;
    int tid = threadIdx.x;
#pragma unroll
    for (int j = 0; j < 4; j++) {
        int i = tid + j * 256;
        int r = i >> 4;
        int c4 = i & 15;
        int tg = t0 + r;
        int srow = tg;
        bool z = false;
        if (gathered) { z = (g_mask[tg] == 0); srow = g_pos[tg]; }
        float4 v = z ? make_float4(0.f, 0.f, 0.f, 0.f)
                     : ((const float4*)src)[((long long)b * NT + srow) * 256 + (d0 >> 2) + c4];
        tile[r][c4 * 4 + 0] = v.x; tile[r][c4 * 4 + 1] = v.y;
        tile[r][c4 * 4 + 2] = v.z; tile[r][c4 * 4 + 3] = v.w;
    }
    __syncthreads();
#pragma unroll
    for (int j = 0; j < 4; j++) {
        int i = tid + j * 256;
        int r = i >> 4;
        int c4 = i & 15;
        half h[4], l[4];
#pragma unroll
        for (int e = 0; e < 4; e++) hilo(tile[c4 * 4 + e][r], h[e], l[e]);
        long long o = ((long long)b * ND + d0 + r) * (long long)NT + t0 + c4 * 4;
        uint2 uh; uh.x = pack2(h[0], h[1]); uh.y = pack2(h[2], h[3]);
        uint2 ul; ul.x = pack2(l[0], l[1]); ul.y = pack2(l[2], l[3]);
        *(uint2*)(dhi + o) = uh;
        *(uint2*)(dlo + o) = ul;
    }
}

// ---------------- split-fp16 HMMA GEMM (NT): C = A * B^T ---------------------
// A row-major (M,K) hi only; B row-major (N,K) hi/lo. C = Ah*Bh^T + Ah*Bl^T.
// CTA 128x128, K-chunk 64, 4-stage cp.async pipeline, 8 warps (64x32 each).
// mode: 0 = fp32 C (+bias), 1 = fp16-hi C (+bias+relu), 2 = fp16 hi+lo C,
//       3 = fused: out -> x1=out*q (X1), x2=q-out (X2), fp16 hi.
#define KC      64
#define STAGES  4
#define OFF_AH  0
#define OFF_BH  16384
#define OFF_BL  32768
#define STAGE_B 49152
#define SMEM_BYTES (STAGES * STAGE_B)

__global__ void __launch_bounds__(256, 1) gemm_fp16_kernel(
    const half* __restrict__ Ahi, int lda, long long sA,
    const half* __restrict__ Bhi, const half* __restrict__ Blo, int ldb, long long sB,
    float* __restrict__ Cf, half* __restrict__ Chi, half* __restrict__ Clo,
    half* __restrict__ X1, half* __restrict__ X2, const float* __restrict__ qsrc,
    int ldc, long long sC, int coloff,
    int N, int K, const float* __restrict__ bias, int relu, int mode)
{
    extern __shared__ __align__(1024) char smem[];
    const uint32_t sb = smem_u32(smem);
    const int tid = threadIdx.x;
    const int wid = tid >> 5;
    const int l   = tid & 31;

    const long long bz = blockIdx.z;
    const half* pAh = Ahi + bz * sA + (long long)(blockIdx.y * 128) * lda;
    const half* pBh = Bhi + bz * sB + (long long)(blockIdx.x * 128) * ldb;
    const half* pBl = Blo + bz * sB + (long long)(blockIdx.x * 128) * ldb;
    const int S = K / KC;

    const int crow = tid >> 1;
    const int cc0  = (tid & 1) << 2;

    auto load_stage = [&](int s) {
        uint32_t bp = sb + (s & (STAGES - 1)) * STAGE_B;
        long long k0 = (long long)s * KC;
        const half* rAh = pAh + (long long)crow * lda + k0;
        const half* rBh = pBh + (long long)crow * ldb + k0;
        const half* rBl = pBl + (long long)crow * ldb + k0;
        uint32_t rowo = (uint32_t)crow * 128;
        uint32_t x = (uint32_t)(crow & 7) << 4;
#pragma unroll
        for (int j = 0; j < 4; j++) {
            int c = cc0 + j;
            uint32_t o = rowo + (((uint32_t)c << 4) ^ x);
            cp16(bp + OFF_AH + o, rAh + c * 8);
            cp16(bp + OFF_BH + o, rBh + c * 8);
            cp16(bp + OFF_BL + o, rBl + c * 8);
        }
    };

    load_stage(0); cp_commit();
    load_stage(1); cp_commit();
    load_stage(2); cp_commit();

    const int wm = wid & 1;
    const int wn = wid >> 1;
    const int arow = wm * 64 + (l & 15);
    const uint32_t aco = ((uint32_t)(l >> 4) << 4);
    const uint32_t axor = (uint32_t)(arow & 7) << 4;
    const int brow = wn * 32 + (l & 7) + ((l >> 4) << 3);
    const uint32_t bco = ((uint32_t)((l >> 3) & 1) << 4);
    const uint32_t bxor = (uint32_t)(brow & 7) << 4;

    float acc[4][4][4];
#pragma unroll
    for (int mf = 0; mf < 4; mf++)
#pragma unroll
        for (int nf = 0; nf < 4; nf++)
#pragma unroll
            for (int e = 0; e < 4; e++) acc[mf][nf][e] = 0.f;

    for (int s = 0; s < S; s++) {
        int rem = S - 1 - s;
        if (rem >= 2)      asm volatile("cp.async.wait_group 2;" ::: "memory");
        else if (rem == 1) asm volatile("cp.async.wait_group 1;" ::: "memory");
        else               asm volatile("cp.async.wait_group 0;" ::: "memory");
        __syncthreads();
        if (s + 3 < S) { load_stage(s + 3); cp_commit(); }

        uint32_t bp = sb + (s & (STAGES - 1)) * STAGE_B;
        uint32_t aBase = bp + OFF_AH + (uint32_t)arow * 128;
        uint32_t bBaseH = bp + OFF_BH + (uint32_t)brow * 128;
        uint32_t bBaseL = bp + OFF_BL + (uint32_t)brow * 128;

#pragma unroll
        for (int k16 = 0; k16 < KC / 16; k16++) {
            uint32_t ak = (((uint32_t)k16 << 5) + aco) ^ axor;
            uint32_t bk = (((uint32_t)k16 << 5) + bco) ^ bxor;
            uint32_t ah[4][4], bh[4][2], bl[4][2];
#pragma unroll
            for (int mf = 0; mf < 4; mf++)
                ldm4(ah[mf], aBase + (uint32_t)(mf * 16) * 128 + ak);
#pragma unroll
            for (int g = 0; g < 2; g++) {
                uint32_t r[4];
                ldm4(r, bBaseH + (uint32_t)(g * 16) * 128 + bk);
                bh[g*2][0] = r[0]; bh[g*2][1] = r[1];
                bh[g*2+1][0] = r[2]; bh[g*2+1][1] = r[3];
                ldm4(r, bBaseL + (uint32_t)(g * 16) * 128 + bk);
                bl[g*2][0] = r[0]; bl[g*2][1] = r[1];
                bl[g*2+1][0] = r[2]; bl[g*2+1][1] = r[3];
            }
#pragma unroll
            for (int mf = 0; mf < 4; mf++)
#pragma unroll
                for (int nf = 0; nf < 4; nf++) {
                    mma16816(acc[mf][nf], ah[mf], bh[nf]);
                    mma16816(acc[mf][nf], ah[mf], bl[nf]);
                }
        }
        __syncthreads();
    }

    // ---- epilogue: lane holds rows gi0, gi0+8; cols gj0, gj0+1 --------------
    const int gi0 = blockIdx.y * 128 + wm * 64 + (l >> 2);
    const int gj0 = blockIdx.x * 128 + wn * 32 + 2 * (l & 3);
#pragma unroll
    for (int mf = 0; mf < 4; mf++) {
        int gi = gi0 + mf * 16;
#pragma unroll
        for (int nf = 0; nf < 4; nf++) {
            int gj = gj0 + nf * 8;
            float v0 = acc[mf][nf][0], v1 = acc[mf][nf][1];
            float v2 = acc[mf][nf][2], v3 = acc[mf][nf][3];
            if (bias) {
                float b0 = (gj < N) ? bias[gj] : 0.f;
                float b1 = (gj + 1 < N) ? bias[gj + 1] : 0.f;
                v0 += b0; v1 += b1; v2 += b0; v3 += b1;
            }
            if (relu) {
                v0 = fmaxf(v0, 0.f); v1 = fmaxf(v1, 0.f);
                v2 = fmaxf(v2, 0.f); v3 = fmaxf(v3, 0.f);
            }
            long long o0 = bz * sC + (long long)gi * ldc + coloff + gj;
            long long o1 = o0 + (long long)8 * ldc;
            if (mode == 0) {
                if (gj + 1 < N) {
                    *(float2*)(Cf + o0) = make_float2(v0, v1);
                    *(float2*)(Cf + o1) = make_float2(v2, v3);
                } else if (gj < N) {
                    Cf[o0] = v0; Cf[o1] = v2;
                }
            } else if (mode == 1) {
                *(uint32_t*)(Chi + o0) = pack2(__float2half_rn(v0), __float2half_rn(v1));
                *(uint32_t*)(Chi + o1) = pack2(__float2half_rn(v2), __float2half_rn(v3));
            } else if (mode == 2) {
                half h0, h1, h2, h3, l0, l1, l2, l3;
                hilo(v0, h0, l0); hilo(v1, h1, l1);
                hilo(v2, h2, l2); hilo(v3, h3, l3);
                *(uint32_t*)(Chi + o0) = pack2(h0, h1);
                *(uint32_t*)(Clo + o0) = pack2(l0, l1);
                *(uint32_t*)(Chi + o1) = pack2(h2, h3);
                *(uint32_t*)(Clo + o1) = pack2(l2, l3);
            } else {
                float2 q0 = *(const float2*)(qsrc + o0);
                float2 q1 = *(const float2*)(qsrc + o1);
                *(uint32_t*)(X1 + o0) = pack2(__float2half_rn(v0 * q0.x),
                                              __float2half_rn(v1 * q0.y));
                *(uint32_t*)(X1 + o1) = pack2(__float2half_rn(v2 * q1.x),
                                              __float2half_rn(v3 * q1.y));
                *(uint32_t*)(X2 + o0) = pack2(__float2half_rn(q0.x - v0),
                                              __float2half_rn(q0.y - v1));
                *(uint32_t*)(X2 + o1) = pack2(__float2half_rn(q1.x - v2),
                                              __float2half_rn(q1.y - v3));
            }
        }
    }
}

// ---------------- softmax: fp32 scores -> fp16 attn --------------------------
__global__ void softmax_kernel() {
    const long long r = blockIdx.x;
    float* p = g_attn + r * SLD;
    const int tid = threadIdx.x;
    __shared__ float s1[8];
    __shared__ float s2[8];

    float lm = -3.4e38f;
    for (int j = tid; j < NK1; j += 256) lm = fmaxf(lm, p[j]);
#pragma unroll
    for (int o = 16; o; o >>= 1) lm = fmaxf(lm, __shfl_xor_sync(0xffffffffu, lm, o));
    if ((tid & 31) == 0) s1[tid >> 5] = lm;
    __syncthreads();
    float m = s1[0];
#pragma unroll
    for (int i = 1; i < 8; i++) m = fmaxf(m, s1[i]);

    const float invT = 0.03125f;
    float ls = 0.f;
    for (int j = tid; j < NK1; j += 256) {
        float e = __expf((p[j] - m) * invT);
        p[j] = e;
        ls += e;
    }
#pragma unroll
    for (int o = 16; o; o >>= 1) ls += __shfl_xor_sync(0xffffffffu, ls, o);
    if ((tid & 31) == 0) s2[tid >> 5] = ls;
    __syncthreads();
    float s = 0.f;
#pragma unroll
    for (int i = 0; i < 8; i++) s += s2[i];
    float inv = 1.f / s;
    long long ob = r * (long long)NT;
    for (int j = tid; j < NT; j += 256)
        g_at_hi[ob + j] = __float2half_rn(p[j] * inv);
}

// ---------------- host launcher ----------------------------------------------
extern "C" void kernel_launch(void* const* d_in, const int* in_sizes, int n_in,
                              void* d_out, int out_size) {
    const float* q     = (const float*)d_in[0];
    const float* k     = (const float*)d_in[1];
    const float* v     = (const float*)d_in[2];
    const float* tsp   = (const float*)d_in[3];
    const int*   supp  = (const int*)  d_in[4];
    const float* w_qk  = (const float*)d_in[5];
    const float* dummy = (const float*)d_in[6];
    const float* w1    = (const float*)d_in[7];
    const float* b1    = (const float*)d_in[8];
    const float* w2    = (const float*)d_in[9];
    const float* b2    = (const float*)d_in[10];
    const float* w3    = (const float*)d_in[11];
    const float* b3    = (const float*)d_in[12];
    float* outp = (float*)d_out;
    float* tsp_outp = outp + (long long)NB * NLQ * ND;

    cudaFuncSetAttribute(gemm_fp16_kernel,
                         cudaFuncAttributeMaxDynamicSharedMemorySize, SMEM_BYTES);

    half *xcat_hi, *k_hi, *wqk_hi, *wqk_lo;
    half *w1_hi, *w1_lo, *w2_hi, *w2_lo, *w3_hi, *w3_lo, *dum_hi, *dum_lo;
    half *qp_hi, *kp_hi, *kp_lo, *kf_hi, *kf_lo;
    half *vT_hi, *vT_lo, *tT_hi, *tT_lo, *at_hi, *x1_hi, *x2_hi;
    float *attn;
    cudaGetSymbolAddress((void**)&xcat_hi, g_xcat_hi);
    cudaGetSymbolAddress((void**)&k_hi, g_k_hi);
    cudaGetSymbolAddress((void**)&wqk_hi, g_wqk_hi);
    cudaGetSymbolAddress((void**)&wqk_lo, g_wqk_lo);
    cudaGetSymbolAddress((void**)&w1_hi, g_w1_hi);
    cudaGetSymbolAddress((void**)&w1_lo, g_w1_lo);
    cudaGetSymbolAddress((void**)&w2_hi, g_w2_hi);
    cudaGetSymbolAddress((void**)&w2_lo, g_w2_lo);
    cudaGetSymbolAddress((void**)&w3_hi, g_w3_hi);
    cudaGetSymbolAddress((void**)&w3_lo, g_w3_lo);
    cudaGetSymbolAddress((void**)&dum_hi, g_dum_hi);
    cudaGetSymbolAddress((void**)&dum_lo, g_dum_lo);
    cudaGetSymbolAddress((void**)&qp_hi, g_qp_hi);
    cudaGetSymbolAddress((void**)&kp_hi, g_kp_hi);
    cudaGetSymbolAddress((void**)&kp_lo, g_kp_lo);
    cudaGetSymbolAddress((void**)&kf_hi, g_kf_hi);
    cudaGetSymbolAddress((void**)&kf_lo, g_kf_lo);
    cudaGetSymbolAddress((void**)&vT_hi, g_vT_hi);
    cudaGetSymbolAddress((void**)&vT_lo, g_vT_lo);
    cudaGetSymbolAddress((void**)&tT_hi, g_tT_hi);
    cudaGetSymbolAddress((void**)&tT_lo, g_tT_lo);
    cudaGetSymbolAddress((void**)&at_hi, g_at_hi);
    cudaGetSymbolAddress((void**)&x1_hi, g_x1_hi);
    cudaGetSymbolAddress((void**)&x2_hi, g_x2_hi);
    cudaGetSymbolAddress((void**)&attn, g_attn);

    // 1) pos/mask
    pos_kernel<<<1, 1024>>>(supp);

    // 2) conversions (A-side: hi only; B-side: hi+lo)
    conv_kernel<<<32768, 256>>>(q, xcat_hi + 1024, (half*)0, 256, 2048);
    conv_kernel<<<32768, 256>>>(k, k_hi, (half*)0, 256, 1024);
    conv_kernel<<<1024, 256>>>(w_qk, wqk_hi, wqk_lo, 256, 1024);
    conv_kernel<<<512, 256>>>(w1, w1_hi, w1_lo, 256, 1024);
    conv_kernel<<<512, 256>>>(w2, w2_hi, w2_lo, 256, 1024);
    conv_kernel<<<2048, 256>>>(w3, w3_hi, w3_lo, 512, 2048);
    conv_kernel<<<1, 256>>>(dummy, dum_hi, dum_lo, 256, 1024);

    // 3) qp = q @ Wqk^T  (hi out)
    gemm_fp16_kernel<<<dim3(8, 256, 1), 256, SMEM_BYTES>>>(
        xcat_hi + 1024, 2048, 0, wqk_hi, wqk_lo, 1024, 0,
        (float*)0, qp_hi, (half*)0, (half*)0, (half*)0, (const float*)0,
        1024, 0, 0, 1024, 1024, (const float*)0, 0, 1);

    // 4) kp = k @ Wqk^T  (hi+lo out)
    gemm_fp16_kernel<<<dim3(8, 256, 1), 256, SMEM_BYTES>>>(
        k_hi, 1024, 0, wqk_hi, wqk_lo, 1024, 0,
        (float*)0, kp_hi, kp_lo, (half*)0, (half*)0, (const float*)0,
        1024, 0, 0, 1024, 1024, (const float*)0, 0, 2);

    // 5) gather kf, build vT/tT
    gather_kf_kernel<<<dim3(NK1, NB, 1), 256>>>();
    transpose_conv_kernel<<<dim3(16, 16, NB), 256>>>(v, vT_hi, vT_lo, 1);
    transpose_conv_kernel<<<dim3(16, 16, NB), 256>>>(tsp, tT_hi, tT_lo, 0);

    // 6) scores = qp @ kf^T  (fp32, N=1025)
    gemm_fp16_kernel<<<dim3(9, 8, NB), 256, SMEM_BYTES>>>(
        qp_hi, 1024, (long long)NLQ * ND, kf_hi, kf_lo, 1024, (long long)KFROWS * ND,
        attn, (half*)0, (half*)0, (half*)0, (half*)0, (const float*)0,
        SLD, (long long)NLQ * SLD, 0, NK1, 1024, (const float*)0, 0, 0);

    // 7) softmax -> attn fp16
    softmax_kernel<<<NB * NLQ, 256>>>();

    // 8) out = attn @ v_sel, fused x1 = out*q, x2 = q-out  (mode 3)
    gemm_fp16_kernel<<<dim3(8, 8, NB), 256, SMEM_BYTES>>>(
        at_hi, 1024, (long long)NLQ * ND, vT_hi, vT_lo, 1024, (long long)ND * NT,
        (float*)0, (half*)0, (half*)0, x1_hi, x2_hi, q,
        1024, (long long)NLQ * ND, 0, 1024, 1024, (const float*)0, 0, 3);

    // 9) tsp_out = attn @ tsp -> second output (fp32)
    gemm_fp16_kernel<<<dim3(8, 8, NB), 256, SMEM_BYTES>>>(
        at_hi, 1024, (long long)NLQ * ND, tT_hi, tT_lo, 1024, (long long)ND * NT,
        tsp_outp, (half*)0, (half*)0, (half*)0, (half*)0, (const float*)0,
        1024, (long long)NLQ * ND, 0, 1024, 1024, (const float*)0, 0, 0);

    // 10) o1 = relu(x1 @ w1^T + b1) -> xcat[:, 0:512] (hi)
    gemm_fp16_kernel<<<dim3(4, 256, 1), 256, SMEM_BYTES>>>(
        x1_hi, 1024, 0, w1_hi, w1_lo, 1024, 0,
        (float*)0, xcat_hi, (half*)0, (half*)0, (half*)0, (const float*)0,
        2048, 0, 0, 512, 1024, b1, 1, 1);

    // 11) o2 = relu(x2 @ w2^T + b2) -> xcat[:, 512:1024] (hi)
    gemm_fp16_kernel<<<dim3(4, 256, 1), 256, SMEM_BYTES>>>(
        x2_hi, 1024, 0, w2_hi, w2_lo, 1024, 0,
        (float*)0, xcat_hi, (half*)0, (half*)0, (half*)0, (const float*)0,
        2048, 0, 512, 512, 1024, b2, 1, 1);

    // 12) output = xcat @ w3^T + b3 -> first output (fp32)
    gemm_fp16_kernel<<<dim3(8, 256, 1), 256, SMEM_BYTES>>>(
        xcat_hi, 2048, 0, w3_hi, w3_lo, 2048, 0,
        outp, (half*)0, (half*)0, (half*)0, (half*)0, (const float*)0,
        1024, 0, 0, 1024, 2048, b3, 0, 0);
}

// round 7
// speedup vs baseline: 3.5858x; 1.0364x over previous
#include <cuda_runtime.h>
#include <cuda_fp16.h>
#include <stdint.h>

#define DUMMY_CLASS 100
#define NB   32
#define NLQ  1024
#define NT   1024
#define ND   1024

// ---------------- scratch (device globals; no allocation allowed) ------------
__device__ __align__(16) half g_xcat_hi[67108864];  // (B*LQ, 2048): [o1|o2|q]
__device__ __align__(16) half g_k_hi  [33554432];
__device__ __align__(16) half g_wqk_hi[1048576];
__device__ __align__(16) half g_wqk_lo[1048576];
__device__ __align__(16) half g_w1_hi [524288];
__device__ __align__(16) half g_w1_lo [524288];
__device__ __align__(16) half g_w2_hi [524288];
__device__ __align__(16) half g_w2_lo [524288];
__device__ __align__(16) half g_w3_hi [2097152];
__device__ __align__(16) half g_w3_lo [2097152];
__device__ __align__(16) half g_qp_hi [33554432];
__device__ __align__(16) half g_kp_hi [33554432];
__device__ __align__(16) half g_kp_lo [33554432];
__device__ __align__(16) half g_vT_hi [33554432];
__device__ __align__(16) half g_vT_lo [33554432];
__device__ __align__(16) half g_tT_hi [33554432];
__device__ __align__(16) half g_tT_lo [33554432];
__device__ float g_attn[33554432];                   // 32*1024*1024 scores
__device__ __align__(16) half g_at_hi [33554432];
__device__ __align__(16) half g_x1_hi [33554432];
__device__ __align__(16) half g_x2_hi [33554432];
__device__ int g_pos [1024];
__device__ int g_mask[1024];

// ---------------- helpers ----------------------------------------------------
__device__ __forceinline__ uint32_t smem_u32(const void* p) {
    uint32_t a;
    asm("{ .reg .u64 t; cvta.to.shared.u64 t, %1; cvt.u32.u64 %0, t; }"
        : "=r"(a) : "l"(p));
    return a;
}
__device__ __forceinline__ void cp16(uint32_t dst, const void* src) {
    asm volatile("cp.async.cg.shared.global [%0], [%1], 16;"
                 :: "r"(dst), "l"(src) : "memory");
}
__device__ __forceinline__ void cp_commit() {
    asm volatile("cp.async.commit_group;" ::: "memory");
}
__device__ __forceinline__ void ldm4(uint32_t* r, uint32_t addr) {
    asm volatile("ldmatrix.sync.aligned.m8n8.x4.shared.b16 {%0,%1,%2,%3}, [%4];"
                 : "=r"(r[0]), "=r"(r[1]), "=r"(r[2]), "=r"(r[3]) : "r"(addr));
}
__device__ __forceinline__ void mma16816(float* c, const uint32_t* a, const uint32_t* b) {
    asm volatile("mma.sync.aligned.m16n8k16.row.col.f32.f16.f16.f32 "
                 "{%0,%1,%2,%3}, {%4,%5,%6,%7}, {%8,%9}, {%0,%1,%2,%3};"
                 : "+f"(c[0]), "+f"(c[1]), "+f"(c[2]), "+f"(c[3])
                 : "r"(a[0]), "r"(a[1]), "r"(a[2]), "r"(a[3]), "r"(b[0]), "r"(b[1]));
}
__device__ __forceinline__ void hilo(float v, half& h, half& l) {
    h = __float2half_rn(v);
    l = __float2half_rn(v - __half2float(h));
}
__device__ __forceinline__ uint32_t pack2(half a, half b) {
    return (uint32_t)__half_as_ushort(a) | ((uint32_t)__half_as_ushort(b) << 16);
}

// ---------------- pos / mask scan --------------------------------------------
__global__ void pos_kernel(const int* __restrict__ supp) {
    __shared__ int s[1024];
    int t = threadIdx.x;
    int m = (supp[t] != DUMMY_CLASS) ? 1 : 0;
    g_mask[t] = m;
    s[t] = m;
    __syncthreads();
    for (int off = 1; off < 1024; off <<= 1) {
        int v = (t >= off) ? s[t - off] : 0;
        __syncthreads();
        s[t] += v;
        __syncthreads();
    }
    int p = s[t] - 1;
    g_pos[t] = p < 0 ? 0 : p;
}

// ---------------- fp32 -> fp16 hi(/lo) conversion ----------------------------
__global__ void conv_kernel(const float* __restrict__ src,
                            half* __restrict__ hi, half* __restrict__ lo,
                            int cols4, int lddst) {
    int i4 = blockIdx.x * 256 + threadIdx.x;
    float4 v = ((const float4*)src)[i4];
    long long row = i4 / cols4;
    int c4 = i4 % cols4;
    long long o = row * (long long)lddst + (long long)c4 * 4;
    half h0, h1, h2, h3, l0, l1, l2, l3;
    hilo(v.x, h0, l0); hilo(v.y, h1, l1); hilo(v.z, h2, l2); hilo(v.w, h3, l3);
    uint2 uh; uh.x = pack2(h0, h1); uh.y = pack2(h2, h3);
    *(uint2*)(hi + o) = uh;
    if (lo) {
        uint2 ul; ul.x = pack2(l0, l1); ul.y = pack2(l2, l3);
        *(uint2*)(lo + o) = ul;
    }
}

// ---------------- transpose + convert (optionally gathered) ------------------
__global__ void transpose_conv_kernel(const float* __restrict__ src,
                                      half* __restrict__ dhi, half* __restrict__ dlo,
                                      int gathered) {
    __shared__ float tile[64][65];
    int b = blockIdx.z;
    int t0 = blockIdx.y * 64;
    int d0 = blockIdx.x * 64;
    int tid = threadIdx.x;
#pragma unroll
    for (int j = 0; j < 4; j++) {
        int i = tid + j * 256;
        int r = i >> 4;
        int c4 = i & 15;
        int tg = t0 + r;
        int srow = tg;
        bool z = false;
        if (gathered) { z = (g_mask[tg] == 0); srow = g_pos[tg]; }
        float4 v = z ? make_float4(0.f, 0.f, 0.f, 0.f)
                     : ((const float4*)src)[((long long)b * NT + srow) * 256 + (d0 >> 2) + c4];
        tile[r][c4 * 4 + 0] = v.x; tile[r][c4 * 4 + 1] = v.y;
        tile[r][c4 * 4 + 2] = v.z; tile[r][c4 * 4 + 3] = v.w;
    }
    __syncthreads();
#pragma unroll
    for (int j = 0; j < 4; j++) {
        int i = tid + j * 256;
        int r = i >> 4;
        int c4 = i & 15;
        half h[4], l[4];
#pragma unroll
        for (int e = 0; e < 4; e++) hilo(tile[c4 * 4 + e][r], h[e], l[e]);
        long long o = ((long long)b * ND + d0 + r) * (long long)NT + t0 + c4 * 4;
        uint2 uh; uh.x = pack2(h[0], h[1]); uh.y = pack2(h[2], h[3]);
        uint2 ul; ul.x = pack2(l[0], l[1]); ul.y = pack2(l[2], l[3]);
        *(uint2*)(dhi + o) = uh;
        *(uint2*)(dlo + o) = ul;
    }
}

// ---------------- split-fp16 HMMA GEMM (NT): C = Ah*(Bh+Bl)^T ----------------
// CTA tile 256x128, 8 warps (4m x 2n), warp tile 64x64, K-chunk 64, 3 stages.
// mode: 0 = fp32 C (+bias), 1 = fp16-hi C (+bias+relu), 2 = fp16 hi+lo C,
//       3 = fused: out -> X1=out*q, X2=q-out (fp16 hi).
#define KC      64
#define STAGES  3
#define OFF_AH  0
#define OFF_BH  32768
#define OFF_BL  49152
#define STAGE_B 65536
#define SMEM_BYTES (STAGES * STAGE_B)

__global__ void __launch_bounds__(256, 1) gemm_fp16_kernel(
    const half* __restrict__ Ahi, int lda, long long sA,
    const half* __restrict__ Bhi, const half* __restrict__ Blo, int ldb, long long sB,
    float* __restrict__ Cf, half* __restrict__ Chi, half* __restrict__ Clo,
    half* __restrict__ X1, half* __restrict__ X2, const float* __restrict__ qsrc,
    int ldc, long long sC, int coloff,
    int K, const float* __restrict__ bias, int relu, int mode)
{
    extern __shared__ __align__(1024) char smem[];
    const uint32_t sb = smem_u32(smem);
    const int tid = threadIdx.x;
    const int wid = tid >> 5;
    const int l   = tid & 31;

    const long long bz = blockIdx.z;
    const half* pAh = Ahi + bz * sA + (long long)(blockIdx.y * 256) * lda;
    const half* pBh = Bhi + bz * sB + (long long)(blockIdx.x * 128) * ldb;
    const half* pBl = Blo + bz * sB + (long long)(blockIdx.x * 128) * ldb;
    const int S = K / KC;

    // A: thread tid loads row tid (8 x 16B chunks). B: 2 threads/row, 4 chunks.
    const int crowB = tid >> 1;
    const int ccB0  = (tid & 1) << 2;

    auto load_stage = [&](int s) {
        uint32_t bp = sb + (s % STAGES) * STAGE_B;
        long long k0 = (long long)s * KC;
        const half* rA = pAh + (long long)tid * lda + k0;
        uint32_t rowoA = (uint32_t)tid * 128;
        uint32_t xA = (uint32_t)(tid & 7) << 4;
#pragma unroll
        for (int j = 0; j < 8; j++)
            cp16(bp + OFF_AH + rowoA + (((uint32_t)j << 4) ^ xA), rA + j * 8);
        const half* rBh = pBh + (long long)crowB * ldb + k0;
        const half* rBl = pBl + (long long)crowB * ldb + k0;
        uint32_t rowoB = (uint32_t)crowB * 128;
        uint32_t xB = (uint32_t)(crowB & 7) << 4;
#pragma unroll
        for (int j = 0; j < 4; j++) {
            int c = ccB0 + j;
            uint32_t o = rowoB + (((uint32_t)c << 4) ^ xB);
            cp16(bp + OFF_BH + o, rBh + c * 8);
            cp16(bp + OFF_BL + o, rBl + c * 8);
        }
    };

    load_stage(0); cp_commit();
    load_stage(1); cp_commit();

    const int wm = wid & 3;          // 0..3 -> 64-row m block
    const int wn = wid >> 2;         // 0..1 -> 64-col n block
    const int arow = wm * 64 + (l & 15);
    const uint32_t aco = ((uint32_t)(l >> 4) << 4);
    const uint32_t axor = (uint32_t)(arow & 7) << 4;
    const int brow0 = wn * 64 + (l & 7) + ((l >> 4) << 3);
    const uint32_t bco = ((uint32_t)((l >> 3) & 1) << 4);

    float acc[4][8][4];
#pragma unroll
    for (int mf = 0; mf < 4; mf++)
#pragma unroll
        for (int nf = 0; nf < 8; nf++)
#pragma unroll
            for (int e = 0; e < 4; e++) acc[mf][nf][e] = 0.f;

    for (int s = 0; s < S; s++) {
        if (s + 1 < S) asm volatile("cp.async.wait_group 1;" ::: "memory");
        else           asm volatile("cp.async.wait_group 0;" ::: "memory");
        __syncthreads();
        if (s + 2 < S) { load_stage(s + 2); cp_commit(); }

        uint32_t bp = sb + (s % STAGES) * STAGE_B;
        uint32_t aBase = bp + OFF_AH + (uint32_t)arow * 128;
        uint32_t bBaseH = bp + OFF_BH + (uint32_t)brow0 * 128;
        uint32_t bBaseL = bp + OFF_BL + (uint32_t)brow0 * 128;

#pragma unroll
        for (int k16 = 0; k16 < KC / 16; k16++) {
            uint32_t ak = (((uint32_t)k16 << 5) + aco) ^ axor;
            uint32_t ah[4][4], bh[8][2], bl[8][2];
#pragma unroll
            for (int mf = 0; mf < 4; mf++)
                ldm4(ah[mf], aBase + (uint32_t)(mf * 16) * 128 + ak);
#pragma unroll
            for (int g = 0; g < 4; g++) {
                int br = brow0 + g * 16;
                uint32_t bk = (((uint32_t)k16 << 5) + bco) ^ ((uint32_t)(br & 7) << 4);
                uint32_t r[4];
                ldm4(r, bBaseH + (uint32_t)(g * 16) * 128 + bk);
                bh[g*2][0] = r[0]; bh[g*2][1] = r[1];
                bh[g*2+1][0] = r[2]; bh[g*2+1][1] = r[3];
                ldm4(r, bBaseL + (uint32_t)(g * 16) * 128 + bk);
                bl[g*2][0] = r[0]; bl[g*2][1] = r[1];
                bl[g*2+1][0] = r[2]; bl[g*2+1][1] = r[3];
            }
#pragma unroll
            for (int mf = 0; mf < 4; mf++)
#pragma unroll
                for (int nf = 0; nf < 8; nf++) {
                    mma16816(acc[mf][nf], ah[mf], bh[nf]);
                    mma16816(acc[mf][nf], ah[mf], bl[nf]);
                }
        }
        __syncthreads();
    }

    // ---- epilogue -----------------------------------------------------------
    const int gi0 = blockIdx.y * 256 + wm * 64 + (l >> 2);
    const int gj0 = blockIdx.x * 128 + wn * 64 + 2 * (l & 3);
#pragma unroll
    for (int mf = 0; mf < 4; mf++) {
        int gi = gi0 + mf * 16;
#pragma unroll
        for (int nf = 0; nf < 8; nf++) {
            int gj = gj0 + nf * 8;
            float v0 = acc[mf][nf][0], v1 = acc[mf][nf][1];
            float v2 = acc[mf][nf][2], v3 = acc[mf][nf][3];
            if (bias) {
                float b0 = bias[gj], b1 = bias[gj + 1];
                v0 += b0; v1 += b1; v2 += b0; v3 += b1;
            }
            if (relu) {
                v0 = fmaxf(v0, 0.f); v1 = fmaxf(v1, 0.f);
                v2 = fmaxf(v2, 0.f); v3 = fmaxf(v3, 0.f);
            }
            long long o0 = bz * sC + (long long)gi * ldc + coloff + gj;
            long long o1 = o0 + (long long)8 * ldc;
            if (mode == 0) {
                *(float2*)(Cf + o0) = make_float2(v0, v1);
                *(float2*)(Cf + o1) = make_float2(v2, v3);
            } else if (mode == 1) {
                *(uint32_t*)(Chi + o0) = pack2(__float2half_rn(v0), __float2half_rn(v1));
                *(uint32_t*)(Chi + o1) = pack2(__float2half_rn(v2), __float2half_rn(v3));
            } else if (mode == 2) {
                half h0, h1, h2, h3, l0, l1, l2, l3;
                hilo(v0, h0, l0); hilo(v1, h1, l1);
                hilo(v2, h2, l2); hilo(v3, h3, l3);
                *(uint32_t*)(Chi + o0) = pack2(h0, h1);
                *(uint32_t*)(Clo + o0) = pack2(l0, l1);
                *(uint32_t*)(Chi + o1) = pack2(h2, h3);
                *(uint32_t*)(Clo + o1) = pack2(l2, l3);
            } else {
                float2 q0 = *(const float2*)(qsrc + o0);
                float2 q1 = *(const float2*)(qsrc + o1);
                *(uint32_t*)(X1 + o0) = pack2(__float2half_rn(v0 * q0.x),
                                              __float2half_rn(v1 * q0.y));
                *(uint32_t*)(X1 + o1) = pack2(__float2half_rn(v2 * q1.x),
                                              __float2half_rn(v3 * q1.y));
                *(uint32_t*)(X2 + o0) = pack2(__float2half_rn(q0.x - v0),
                                              __float2half_rn(q0.y - v1));
                *(uint32_t*)(X2 + o1) = pack2(__float2half_rn(q1.x - v2),
                                              __float2half_rn(q1.y - v3));
            }
        }
    }
}

// ---------------- softmax with in-kernel gather + dummy column ---------------
// Row r: vals[t] = mask[t] ? scores[r][pos[t]] : sdum, plus one appended sdum.
// sdum = dot(qp_hi[r], dummy_f32). Output attn fp16 (gathered layout).
__global__ void softmax_kernel(const float* __restrict__ dummy) {
    const long long r = blockIdx.x;
    const float* srow = g_attn + r * 1024;
    const half* qrow = g_qp_hi + r * 1024;
    const int tid = threadIdx.x;
    __shared__ float sred[8];
    __shared__ float sbc;

    // sdum
    float sd = 0.f;
    for (int j = tid; j < 1024; j += 256)
        sd += __half2float(qrow[j]) * dummy[j];
#pragma unroll
    for (int o = 16; o; o >>= 1) sd += __shfl_xor_sync(0xffffffffu, sd, o);
    if ((tid & 31) == 0) sred[tid >> 5] = sd;
    __syncthreads();
    if (tid == 0) {
        float t = 0.f;
#pragma unroll
        for (int i = 0; i < 8; i++) t += sred[i];
        sbc = t;
    }
    __syncthreads();
    const float sdum = sbc;

    // gather + max
    float val[4];
    float lm = sdum;
#pragma unroll
    for (int jj = 0; jj < 4; jj++) {
        int j = tid + jj * 256;
        val[jj] = g_mask[j] ? srow[g_pos[j]] : sdum;
        lm = fmaxf(lm, val[jj]);
    }
#pragma unroll
    for (int o = 16; o; o >>= 1) lm = fmaxf(lm, __shfl_xor_sync(0xffffffffu, lm, o));
    if ((tid & 31) == 0) sred[tid >> 5] = lm;
    __syncthreads();
    float m = sred[0];
#pragma unroll
    for (int i = 1; i < 8; i++) m = fmaxf(m, sred[i]);

    // exp + sum (appended dummy row contributes once)
    const float invT = 0.03125f;
    float e[4];
    float ls = (tid == 0) ? __expf((sdum - m) * invT) : 0.f;
#pragma unroll
    for (int jj = 0; jj < 4; jj++) {
        e[jj] = __expf((val[jj] - m) * invT);
        ls += e[jj];
    }
#pragma unroll
    for (int o = 16; o; o >>= 1) ls += __shfl_xor_sync(0xffffffffu, ls, o);
    if ((tid & 31) == 0) sred[tid >> 5] = ls;
    __syncthreads();
    float s = 0.f;
#pragma unroll
    for (int i = 0; i < 8; i++) s += sred[i];
    float inv = 1.f / s;
    long long ob = r * (long long)NT;
#pragma unroll
    for (int jj = 0; jj < 4; jj++)
        g_at_hi[ob + tid + jj * 256] = __float2half_rn(e[jj] * inv);
}

// ---------------- host launcher ----------------------------------------------
extern "C" void kernel_launch(void* const* d_in, const int* in_sizes, int n_in,
                              void* d_out, int out_size) {
    const float* q     = (const float*)d_in[0];
    const float* k     = (const float*)d_in[1];
    const float* v     = (const float*)d_in[2];
    const float* tsp   = (const float*)d_in[3];
    const int*   supp  = (const int*)  d_in[4];
    const float* w_qk  = (const float*)d_in[5];
    const float* dummy = (const float*)d_in[6];
    const float* w1    = (const float*)d_in[7];
    const float* b1    = (const float*)d_in[8];
    const float* w2    = (const float*)d_in[9];
    const float* b2    = (const float*)d_in[10];
    const float* w3    = (const float*)d_in[11];
    const float* b3    = (const float*)d_in[12];
    float* outp = (float*)d_out;
    float* tsp_outp = outp + (long long)NB * NLQ * ND;

    cudaFuncSetAttribute(gemm_fp16_kernel,
                         cudaFuncAttributeMaxDynamicSharedMemorySize, SMEM_BYTES);

    half *xcat_hi, *k_hi, *wqk_hi, *wqk_lo;
    half *w1_hi, *w1_lo, *w2_hi, *w2_lo, *w3_hi, *w3_lo;
    half *qp_hi, *kp_hi, *kp_lo;
    half *vT_hi, *vT_lo, *tT_hi, *tT_lo, *at_hi, *x1_hi, *x2_hi;
    float *attn;
    cudaGetSymbolAddress((void**)&xcat_hi, g_xcat_hi);
    cudaGetSymbolAddress((void**)&k_hi, g_k_hi);
    cudaGetSymbolAddress((void**)&wqk_hi, g_wqk_hi);
    cudaGetSymbolAddress((void**)&wqk_lo, g_wqk_lo);
    cudaGetSymbolAddress((void**)&w1_hi, g_w1_hi);
    cudaGetSymbolAddress((void**)&w1_lo, g_w1_lo);
    cudaGetSymbolAddress((void**)&w2_hi, g_w2_hi);
    cudaGetSymbolAddress((void**)&w2_lo, g_w2_lo);
    cudaGetSymbolAddress((void**)&w3_hi, g_w3_hi);
    cudaGetSymbolAddress((void**)&w3_lo, g_w3_lo);
    cudaGetSymbolAddress((void**)&qp_hi, g_qp_hi);
    cudaGetSymbolAddress((void**)&kp_hi, g_kp_hi);
    cudaGetSymbolAddress((void**)&kp_lo, g_kp_lo);
    cudaGetSymbolAddress((void**)&vT_hi, g_vT_hi);
    cudaGetSymbolAddress((void**)&vT_lo, g_vT_lo);
    cudaGetSymbolAddress((void**)&tT_hi, g_tT_hi);
    cudaGetSymbolAddress((void**)&tT_lo, g_tT_lo);
    cudaGetSymbolAddress((void**)&at_hi, g_at_hi);
    cudaGetSymbolAddress((void**)&x1_hi, g_x1_hi);
    cudaGetSymbolAddress((void**)&x2_hi, g_x2_hi);
    cudaGetSymbolAddress((void**)&attn, g_attn);

    // 1) pos/mask
    pos_kernel<<<1, 1024>>>(supp);

    // 2) conversions (A-side: hi only; B-side weights: hi+lo)
    conv_kernel<<<32768, 256>>>(q, xcat_hi + 1024, (half*)0, 256, 2048);
    conv_kernel<<<32768, 256>>>(k, k_hi, (half*)0, 256, 1024);
    conv_kernel<<<1024, 256>>>(w_qk, wqk_hi, wqk_lo, 256, 1024);
    conv_kernel<<<512, 256>>>(w1, w1_hi, w1_lo, 256, 1024);
    conv_kernel<<<512, 256>>>(w2, w2_hi, w2_lo, 256, 1024);
    conv_kernel<<<2048, 256>>>(w3, w3_hi, w3_lo, 512, 2048);

    // 3) qp = q @ Wqk^T  (hi out)
    gemm_fp16_kernel<<<dim3(8, 128, 1), 256, SMEM_BYTES>>>(
        xcat_hi + 1024, 2048, 0, wqk_hi, wqk_lo, 1024, 0,
        (float*)0, qp_hi, (half*)0, (half*)0, (half*)0, (const float*)0,
        1024, 0, 0, 1024, (const float*)0, 0, 1);

    // 4) kp = k @ Wqk^T  (hi+lo out)
    gemm_fp16_kernel<<<dim3(8, 128, 1), 256, SMEM_BYTES>>>(
        k_hi, 1024, 0, wqk_hi, wqk_lo, 1024, 0,
        (float*)0, kp_hi, kp_lo, (half*)0, (half*)0, (const float*)0,
        1024, 0, 0, 1024, (const float*)0, 0, 2);

    // 5) build vT (gathered) / tT
    transpose_conv_kernel<<<dim3(16, 16, NB), 256>>>(v, vT_hi, vT_lo, 1);
    transpose_conv_kernel<<<dim3(16, 16, NB), 256>>>(tsp, tT_hi, tT_lo, 0);

    // 6) scores_full = qp @ kp^T  (fp32, N=1024, batched)
    gemm_fp16_kernel<<<dim3(8, 4, NB), 256, SMEM_BYTES>>>(
        qp_hi, 1024, (long long)NLQ * ND, kp_hi, kp_lo, 1024, (long long)NT * ND,
        attn, (half*)0, (half*)0, (half*)0, (half*)0, (const float*)0,
        1024, (long long)NLQ * NT, 0, 1024, (const float*)0, 0, 0);

    // 7) softmax (gather + dummy column in-kernel) -> attn fp16
    softmax_kernel<<<NB * NLQ, 256>>>(dummy);

    // 8) out = attn @ v_sel, fused x1 = out*q, x2 = q-out  (mode 3)
    gemm_fp16_kernel<<<dim3(8, 4, NB), 256, SMEM_BYTES>>>(
        at_hi, 1024, (long long)NLQ * ND, vT_hi, vT_lo, 1024, (long long)ND * NT,
        (float*)0, (half*)0, (half*)0, x1_hi, x2_hi, q,
        1024, (long long)NLQ * ND, 0, 1024, (const float*)0, 0, 3);

    // 9) tsp_out = attn @ tsp -> second output (fp32)
    gemm_fp16_kernel<<<dim3(8, 4, NB), 256, SMEM_BYTES>>>(
        at_hi, 1024, (long long)NLQ * ND, tT_hi, tT_lo, 1024, (long long)ND * NT,
        tsp_outp, (half*)0, (half*)0, (half*)0, (half*)0, (const float*)0,
        1024, (long long)NLQ * ND, 0, 1024, (const float*)0, 0, 0);

    // 10) o1 = relu(x1 @ w1^T + b1) -> xcat[:, 0:512] (hi)
    gemm_fp16_kernel<<<dim3(4, 128, 1), 256, SMEM_BYTES>>>(
        x1_hi, 1024, 0, w1_hi, w1_lo, 1024, 0,
        (float*)0, xcat_hi, (half*)0, (half*)0, (half*)0, (const float*)0,
        2048, 0, 0, 1024, b1, 1, 1);

    // 11) o2 = relu(x2 @ w2^T + b2) -> xcat[:, 512:1024] (hi)
    gemm_fp16_kernel<<<dim3(4, 128, 1), 256, SMEM_BYTES>>>(
        x2_hi, 1024, 0, w2_hi, w2_lo, 1024, 0,
        (float*)0, xcat_hi, (half*)0, (half*)0, (half*)0, (const float*)0,
        2048, 0, 512, 1024, b2, 1, 1);

    // 12) output = xcat @ w3^T + b3 -> first output (fp32)
    gemm_fp16_kernel<<<dim3(8, 128, 1), 256, SMEM_BYTES>>>(
        xcat_hi, 2048, 0, w3_hi, w3_lo, 2048, 0,
        outp, (half*)0, (half*)0, (half*)0, (half*)0, (const float*)0,
        1024, 0, 0, 2048, b3, 0, 0);
}

// round 12
// speedup vs baseline: 4.1153x; 1.1477x over previous
#include <cuda_runtime.h>
#include <cuda_fp16.h>
#include <stdint.h>

#define DUMMY_CLASS 100
#define NB   32
#define NLQ  1024
#define NT   1024
#define ND   1024

// ---------------- scratch (device globals; no allocation allowed) ------------
__device__ __align__(16) half g_xcat_hi[67108864];  // (B*LQ, 2048): [o1|o2|q]
__device__ __align__(16) half g_k_hi  [33554432];
__device__ __align__(16) half g_wqk_hi[1048576];
__device__ __align__(16) half g_wqk_lo[1048576];
__device__ __align__(16) half g_w1_hi [524288];
__device__ __align__(16) half g_w1_lo [524288];
__device__ __align__(16) half g_w2_hi [524288];
__device__ __align__(16) half g_w2_lo [524288];
__device__ __align__(16) half g_w3_hi [2097152];
__device__ __align__(16) half g_w3_lo [2097152];
__device__ __align__(16) half g_qp_hi [33554432];
__device__ __align__(16) half g_kp_hi [33554432];
__device__ __align__(16) half g_kp_lo [33554432];
__device__ __align__(16) half g_vT_hi [33554432];
__device__ __align__(16) half g_vT_lo [33554432];
__device__ __align__(16) half g_tT_hi [33554432];
__device__ __align__(16) half g_tT_lo [33554432];
__device__ float g_attn[33554432];                   // 32*1024*1024 scores
__device__ __align__(16) half g_at_hi [33554432];
__device__ __align__(16) half g_x1_hi [33554432];
__device__ __align__(16) half g_x2_hi [33554432];
__device__ int g_pos [1024];
__device__ int g_mask[1024];

// ---------------- helpers ----------------------------------------------------
__device__ __forceinline__ uint32_t smem_u32(const void* p) {
    uint32_t a;
    asm("{ .reg .u64 t; cvta.to.shared.u64 t, %1; cvt.u32.u64 %0, t; }"
        : "=r"(a) : "l"(p));
    return a;
}
__device__ __forceinline__ void cp16(uint32_t dst, const void* src) {
    asm volatile("cp.async.cg.shared.global [%0], [%1], 16;"
                 :: "r"(dst), "l"(src) : "memory");
}
__device__ __forceinline__ void cp_commit() {
    asm volatile("cp.async.commit_group;" ::: "memory");
}
__device__ __forceinline__ void ldm4(uint32_t* r, uint32_t addr) {
    asm volatile("ldmatrix.sync.aligned.m8n8.x4.shared.b16 {%0,%1,%2,%3}, [%4];"
                 : "=r"(r[0]), "=r"(r[1]), "=r"(r[2]), "=r"(r[3]) : "r"(addr));
}
__device__ __forceinline__ void mma16816(float* c, const uint32_t* a, const uint32_t* b) {
    asm volatile("mma.sync.aligned.m16n8k16.row.col.f32.f16.f16.f32 "
                 "{%0,%1,%2,%3}, {%4,%5,%6,%7}, {%8,%9}, {%0,%1,%2,%3};"
                 : "+f"(c[0]), "+f"(c[1]), "+f"(c[2]), "+f"(c[3])
                 : "r"(a[0]), "r"(a[1]), "r"(a[2]), "r"(a[3]), "r"(b[0]), "r"(b[1]));
}
__device__ __forceinline__ void hilo(float v, half& h, half& l) {
    h = __float2half_rn(v);
    l = __float2half_rn(v - __half2float(h));
}
__device__ __forceinline__ uint32_t pack2(half a, half b) {
    return (uint32_t)__half_as_ushort(a) | ((uint32_t)__half_as_ushort(b) << 16);
}

// ---------------- pos / mask scan --------------------------------------------
__global__ void pos_kernel(const int* __restrict__ supp) {
    __shared__ int s[1024];
    int t = threadIdx.x;
    int m = (supp[t] != DUMMY_CLASS) ? 1 : 0;
    g_mask[t] = m;
    s[t] = m;
    __syncthreads();
    for (int off = 1; off < 1024; off <<= 1) {
        int v = (t >= off) ? s[t - off] : 0;
        __syncthreads();
        s[t] += v;
        __syncthreads();
    }
    int p = s[t] - 1;
    g_pos[t] = p < 0 ? 0 : p;
}

// ---------------- fp32 -> fp16 hi(/lo) conversion ----------------------------
__global__ void conv_kernel(const float* __restrict__ src,
                            half* __restrict__ hi, half* __restrict__ lo,
                            int cols4, int lddst) {
    int i4 = blockIdx.x * 256 + threadIdx.x;
    float4 v = ((const float4*)src)[i4];
    long long row = i4 / cols4;
    int c4 = i4 % cols4;
    long long o = row * (long long)lddst + (long long)c4 * 4;
    half h0, h1, h2, h3, l0, l1, l2, l3;
    hilo(v.x, h0, l0); hilo(v.y, h1, l1); hilo(v.z, h2, l2); hilo(v.w, h3, l3);
    uint2 uh; uh.x = pack2(h0, h1); uh.y = pack2(h2, h3);
    *(uint2*)(hi + o) = uh;
    if (lo) {
        uint2 ul; ul.x = pack2(l0, l1); ul.y = pack2(l2, l3);
        *(uint2*)(lo + o) = ul;
    }
}

// ---------------- transpose + convert (optionally gathered) ------------------
__global__ void transpose_conv_kernel(const float* __restrict__ src,
                                      half* __restrict__ dhi, half* __restrict__ dlo,
                                      int gathered) {
    __shared__ float tile[64][65];
    int b = blockIdx.z;
    int t0 = blockIdx.y * 64;
    int d0 = blockIdx.x * 64;
    int tid = threadIdx.x;
#pragma unroll
    for (int j = 0; j < 4; j++) {
        int i = tid + j * 256;
        int r = i >> 4;
        int c4 = i & 15;
        int tg = t0 + r;
        int srow = tg;
        bool z = false;
        if (gathered) { z = (g_mask[tg] == 0); srow = g_pos[tg]; }
        float4 v = z ? make_float4(0.f, 0.f, 0.f, 0.f)
                     : ((const float4*)src)[((long long)b * NT + srow) * 256 + (d0 >> 2) + c4];
        tile[r][c4 * 4 + 0] = v.x; tile[r][c4 * 4 + 1] = v.y;
        tile[r][c4 * 4 + 2] = v.z; tile[r][c4 * 4 + 3] = v.w;
    }
    __syncthreads();
#pragma unroll
    for (int j = 0; j < 4; j++) {
        int i = tid + j * 256;
        int r = i >> 4;
        int c4 = i & 15;
        half h[4], l[4];
#pragma unroll
        for (int e = 0; e < 4; e++) hilo(tile[c4 * 4 + e][r], h[e], l[e]);
        long long o = ((long long)b * ND + d0 + r) * (long long)NT + t0 + c4 * 4;
        uint2 uh; uh.x = pack2(h[0], h[1]); uh.y = pack2(h[2], h[3]);
        uint2 ul; ul.x = pack2(l[0], l[1]); ul.y = pack2(l[2], l[3]);
        *(uint2*)(dhi + o) = uh;
        *(uint2*)(dlo + o) = ul;
    }
}

// ---------------- split-fp16 HMMA GEMM (NT): C = Ah*(Bh+Bl)^T ----------------
// CTA tile 128x128, 8 warps (2m x 4n), warp tile 64x32, K-chunk 64,
// 2-stage cp.async double buffer (prefetch issued BEFORE wait, into the other
// buffer; trailing sync protects against overwrite), 96 KB smem -> 2 CTAs/SM.
// mode: 0 = fp32 C (+bias), 1 = fp16-hi C (+bias+relu), 2 = fp16 hi+lo C,
//       3 = fused: out -> X1=out*q, X2=q-out (fp16 hi).
#define KC      64
#define STAGES  2
#define OFF_AH  0
#define OFF_BH  16384
#define OFF_BL  32768
#define STAGE_B 49152
#define SMEM_BYTES (STAGES * STAGE_B)

__global__ void __launch_bounds__(256, 2) gemm_fp16_kernel(
    const half* __restrict__ Ahi, int lda, long long sA,
    const half* __restrict__ Bhi, const half* __restrict__ Blo, int ldb, long long sB,
    float* __restrict__ Cf, half* __restrict__ Chi, half* __restrict__ Clo,
    half* __restrict__ X1, half* __restrict__ X2, const float* __restrict__ qsrc,
    int ldc, long long sC, int coloff,
    int K, const float* __restrict__ bias, int relu, int mode)
{
    extern __shared__ __align__(1024) char smem[];
    const uint32_t sb = smem_u32(smem);
    const int tid = threadIdx.x;
    const int wid = tid >> 5;
    const int l   = tid & 31;

    const long long bz = blockIdx.z;
    const half* pAh = Ahi + bz * sA + (long long)(blockIdx.y * 128) * lda;
    const half* pBh = Bhi + bz * sB + (long long)(blockIdx.x * 128) * ldb;
    const half* pBl = Blo + bz * sB + (long long)(blockIdx.x * 128) * ldb;
    const int S = K / KC;

    // loaders: 2 threads per row, 4 x 16B chunks each (128 rows)
    const int crow = tid >> 1;
    const int cc0  = (tid & 1) << 2;

    auto load_stage = [&](int s) {
        uint32_t bp = sb + (s & 1) * STAGE_B;
        long long k0 = (long long)s * KC;
        const half* rA = pAh + (long long)crow * lda + k0;
        const half* rBh = pBh + (long long)crow * ldb + k0;
        const half* rBl = pBl + (long long)crow * ldb + k0;
        uint32_t rowo = (uint32_t)crow * 128;
        uint32_t x = (uint32_t)(crow & 7) << 4;
#pragma unroll
        for (int j = 0; j < 4; j++) {
            int c = cc0 + j;
            uint32_t o = rowo + (((uint32_t)c << 4) ^ x);
            cp16(bp + OFF_AH + o, rA + c * 8);
            cp16(bp + OFF_BH + o, rBh + c * 8);
            cp16(bp + OFF_BL + o, rBl + c * 8);
        }
    };

    load_stage(0); cp_commit();

    const int wm = wid & 1;          // 0..1 -> 64-row half
    const int wn = wid >> 1;         // 0..3 -> 32-col quarter
    const int arow = wm * 64 + (l & 15);
    const uint32_t aco = ((uint32_t)(l >> 4) << 4);
    const uint32_t axor = (uint32_t)(arow & 7) << 4;
    const int brow = wn * 32 + (l & 7) + ((l >> 4) << 3);
    const uint32_t bco = ((uint32_t)((l >> 3) & 1) << 4);
    const uint32_t bxor = (uint32_t)(brow & 7) << 4;

    float acc[4][4][4];
#pragma unroll
    for (int mf = 0; mf < 4; mf++)
#pragma unroll
        for (int nf = 0; nf < 4; nf++)
#pragma unroll
            for (int e = 0; e < 4; e++) acc[mf][nf][e] = 0.f;

    for (int s = 0; s < S; s++) {
        // prefetch next stage into the OTHER buffer (safe: compute(s-1) done)
        if (s + 1 < S) { load_stage(s + 1); cp_commit(); }
        if (s + 1 < S) asm volatile("cp.async.wait_group 1;" ::: "memory");
        else           asm volatile("cp.async.wait_group 0;" ::: "memory");
        __syncthreads();

        uint32_t bp = sb + (s & 1) * STAGE_B;
        uint32_t aBase = bp + OFF_AH + (uint32_t)arow * 128;
        uint32_t bBaseH = bp + OFF_BH + (uint32_t)brow * 128;
        uint32_t bBaseL = bp + OFF_BL + (uint32_t)brow * 128;

#pragma unroll
        for (int k16 = 0; k16 < KC / 16; k16++) {
            uint32_t ak = (((uint32_t)k16 << 5) + aco) ^ axor;
            uint32_t bk = (((uint32_t)k16 << 5) + bco) ^ bxor;
            uint32_t ah[4][4], bh[4][2], bl[4][2];
#pragma unroll
            for (int mf = 0; mf < 4; mf++)
                ldm4(ah[mf], aBase + (uint32_t)(mf * 16) * 128 + ak);
#pragma unroll
            for (int g = 0; g < 2; g++) {
                uint32_t r[4];
                ldm4(r, bBaseH + (uint32_t)(g * 16) * 128 + bk);
                bh[g*2][0] = r[0]; bh[g*2][1] = r[1];
                bh[g*2+1][0] = r[2]; bh[g*2+1][1] = r[3];
                ldm4(r, bBaseL + (uint32_t)(g * 16) * 128 + bk);
                bl[g*2][0] = r[0]; bl[g*2][1] = r[1];
                bl[g*2+1][0] = r[2]; bl[g*2+1][1] = r[3];
            }
#pragma unroll
            for (int mf = 0; mf < 4; mf++)
#pragma unroll
                for (int nf = 0; nf < 4; nf++) {
                    mma16816(acc[mf][nf], ah[mf], bh[nf]);
                    mma16816(acc[mf][nf], ah[mf], bl[nf]);
                }
        }
        __syncthreads();   // compute(s) done before next iter overwrites buf s&1
    }

    // ---- epilogue -----------------------------------------------------------
    const int gi0 = blockIdx.y * 128 + wm * 64 + (l >> 2);
    const int gj0 = blockIdx.x * 128 + wn * 32 + 2 * (l & 3);
#pragma unroll
    for (int mf = 0; mf < 4; mf++) {
        int gi = gi0 + mf * 16;
#pragma unroll
        for (int nf = 0; nf < 4; nf++) {
            int gj = gj0 + nf * 8;
            float v0 = acc[mf][nf][0], v1 = acc[mf][nf][1];
            float v2 = acc[mf][nf][2], v3 = acc[mf][nf][3];
            if (bias) {
                float b0 = bias[gj], b1 = bias[gj + 1];
                v0 += b0; v1 += b1; v2 += b0; v3 += b1;
            }
            if (relu) {
                v0 = fmaxf(v0, 0.f); v1 = fmaxf(v1, 0.f);
                v2 = fmaxf(v2, 0.f); v3 = fmaxf(v3, 0.f);
            }
            long long o0 = bz * sC + (long long)gi * ldc + coloff + gj;
            long long o1 = o0 + (long long)8 * ldc;
            if (mode == 0) {
                *(float2*)(Cf + o0) = make_float2(v0, v1);
                *(float2*)(Cf + o1) = make_float2(v2, v3);
            } else if (mode == 1) {
                *(uint32_t*)(Chi + o0) = pack2(__float2half_rn(v0), __float2half_rn(v1));
                *(uint32_t*)(Chi + o1) = pack2(__float2half_rn(v2), __float2half_rn(v3));
            } else if (mode == 2) {
                half h0, h1, h2, h3, l0, l1, l2, l3;
                hilo(v0, h0, l0); hilo(v1, h1, l1);
                hilo(v2, h2, l2); hilo(v3, h3, l3);
                *(uint32_t*)(Chi + o0) = pack2(h0, h1);
                *(uint32_t*)(Clo + o0) = pack2(l0, l1);
                *(uint32_t*)(Chi + o1) = pack2(h2, h3);
                *(uint32_t*)(Clo + o1) = pack2(l2, l3);
            } else {
                float2 q0 = *(const float2*)(qsrc + o0);
                float2 q1 = *(const float2*)(qsrc + o1);
                *(uint32_t*)(X1 + o0) = pack2(__float2half_rn(v0 * q0.x),
                                              __float2half_rn(v1 * q0.y));
                *(uint32_t*)(X1 + o1) = pack2(__float2half_rn(v2 * q1.x),
                                              __float2half_rn(v3 * q1.y));
                *(uint32_t*)(X2 + o0) = pack2(__float2half_rn(q0.x - v0),
                                              __float2half_rn(q0.y - v1));
                *(uint32_t*)(X2 + o1) = pack2(__float2half_rn(q1.x - v2),
                                              __float2half_rn(q1.y - v3));
            }
        }
    }
}

// ---------------- softmax with in-kernel gather + dummy column ---------------
__global__ void softmax_kernel(const float* __restrict__ dummy) {
    const long long r = blockIdx.x;
    const float* srow = g_attn + r * 1024;
    const half* qrow = g_qp_hi + r * 1024;
    const int tid = threadIdx.x;
    __shared__ float sred[8];
    __shared__ float sbc;

    float sd = 0.f;
    for (int j = tid; j < 1024; j += 256)
        sd += __half2float(qrow[j]) * dummy[j];
#pragma unroll
    for (int o = 16; o; o >>= 1) sd += __shfl_xor_sync(0xffffffffu, sd, o);
    if ((tid & 31) == 0) sred[tid >> 5] = sd;
    __syncthreads();
    if (tid == 0) {
        float t = 0.f;
#pragma unroll
        for (int i = 0; i < 8; i++) t += sred[i];
        sbc = t;
    }
    __syncthreads();
    const float sdum = sbc;

    float val[4];
    float lm = sdum;
#pragma unroll
    for (int jj = 0; jj < 4; jj++) {
        int j = tid + jj * 256;
        val[jj] = g_mask[j] ? srow[g_pos[j]] : sdum;
        lm = fmaxf(lm, val[jj]);
    }
#pragma unroll
    for (int o = 16; o; o >>= 1) lm = fmaxf(lm, __shfl_xor_sync(0xffffffffu, lm, o));
    if ((tid & 31) == 0) sred[tid >> 5] = lm;
    __syncthreads();
    float m = sred[0];
#pragma unroll
    for (int i = 1; i < 8; i++) m = fmaxf(m, sred[i]);

    const float invT = 0.03125f;
    float e[4];
    float ls = (tid == 0) ? __expf((sdum - m) * invT) : 0.f;
#pragma unroll
    for (int jj = 0; jj < 4; jj++) {
        e[jj] = __expf((val[jj] - m) * invT);
        ls += e[jj];
    }
#pragma unroll
    for (int o = 16; o; o >>= 1) ls += __shfl_xor_sync(0xffffffffu, ls, o);
    if ((tid & 31) == 0) sred[tid >> 5] = ls;
    __syncthreads();
    float s = 0.f;
#pragma unroll
    for (int i = 0; i < 8; i++) s += sred[i];
    float inv = 1.f / s;
    long long ob = r * (long long)NT;
#pragma unroll
    for (int jj = 0; jj < 4; jj++)
        g_at_hi[ob + tid + jj * 256] = __float2half_rn(e[jj] * inv);
}

// ---------------- host launcher ----------------------------------------------
extern "C" void kernel_launch(void* const* d_in, const int* in_sizes, int n_in,
                              void* d_out, int out_size) {
    const float* q     = (const float*)d_in[0];
    const float* k     = (const float*)d_in[1];
    const float* v     = (const float*)d_in[2];
    const float* tsp   = (const float*)d_in[3];
    const int*   supp  = (const int*)  d_in[4];
    const float* w_qk  = (const float*)d_in[5];
    const float* dummy = (const float*)d_in[6];
    const float* w1    = (const float*)d_in[7];
    const float* b1    = (const float*)d_in[8];
    const float* w2    = (const float*)d_in[9];
    const float* b2    = (const float*)d_in[10];
    const float* w3    = (const float*)d_in[11];
    const float* b3    = (const float*)d_in[12];
    float* outp = (float*)d_out;
    float* tsp_outp = outp + (long long)NB * NLQ * ND;

    cudaFuncSetAttribute(gemm_fp16_kernel,
                         cudaFuncAttributeMaxDynamicSharedMemorySize, SMEM_BYTES);

    half *xcat_hi, *k_hi, *wqk_hi, *wqk_lo;
    half *w1_hi, *w1_lo, *w2_hi, *w2_lo, *w3_hi, *w3_lo;
    half *qp_hi, *kp_hi, *kp_lo;
    half *vT_hi, *vT_lo, *tT_hi, *tT_lo, *at_hi, *x1_hi, *x2_hi;
    float *attn;
    cudaGetSymbolAddress((void**)&xcat_hi, g_xcat_hi);
    cudaGetSymbolAddress((void**)&k_hi, g_k_hi);
    cudaGetSymbolAddress((void**)&wqk_hi, g_wqk_hi);
    cudaGetSymbolAddress((void**)&wqk_lo, g_wqk_lo);
    cudaGetSymbolAddress((void**)&w1_hi, g_w1_hi);
    cudaGetSymbolAddress((void**)&w1_lo, g_w1_lo);
    cudaGetSymbolAddress((void**)&w2_hi, g_w2_hi);
    cudaGetSymbolAddress((void**)&w2_lo, g_w2_lo);
    cudaGetSymbolAddress((void**)&w3_hi, g_w3_hi);
    cudaGetSymbolAddress((void**)&w3_lo, g_w3_lo);
    cudaGetSymbolAddress((void**)&qp_hi, g_qp_hi);
    cudaGetSymbolAddress((void**)&kp_hi, g_kp_hi);
    cudaGetSymbolAddress((void**)&kp_lo, g_kp_lo);
    cudaGetSymbolAddress((void**)&vT_hi, g_vT_hi);
    cudaGetSymbolAddress((void**)&vT_lo, g_vT_lo);
    cudaGetSymbolAddress((void**)&tT_hi, g_tT_hi);
    cudaGetSymbolAddress((void**)&tT_lo, g_tT_lo);
    cudaGetSymbolAddress((void**)&at_hi, g_at_hi);
    cudaGetSymbolAddress((void**)&x1_hi, g_x1_hi);
    cudaGetSymbolAddress((void**)&x2_hi, g_x2_hi);
    cudaGetSymbolAddress((void**)&attn, g_attn);

    // 1) pos/mask
    pos_kernel<<<1, 1024>>>(supp);

    // 2) conversions (A-side: hi only; B-side weights: hi+lo)
    conv_kernel<<<32768, 256>>>(q, xcat_hi + 1024, (half*)0, 256, 2048);
    conv_kernel<<<32768, 256>>>(k, k_hi, (half*)0, 256, 1024);
    conv_kernel<<<1024, 256>>>(w_qk, wqk_hi, wqk_lo, 256, 1024);
    conv_kernel<<<512, 256>>>(w1, w1_hi, w1_lo, 256, 1024);
    conv_kernel<<<512, 256>>>(w2, w2_hi, w2_lo, 256, 1024);
    conv_kernel<<<2048, 256>>>(w3, w3_hi, w3_lo, 512, 2048);

    // 3) qp = q @ Wqk^T  (hi out)
    gemm_fp16_kernel<<<dim3(8, 256, 1), 256, SMEM_BYTES>>>(
        xcat_hi + 1024, 2048, 0, wqk_hi, wqk_lo, 1024, 0,
        (float*)0, qp_hi, (half*)0, (half*)0, (half*)0, (const float*)0,
        1024, 0, 0, 1024, (const float*)0, 0, 1);

    // 4) kp = k @ Wqk^T  (hi+lo out)
    gemm_fp16_kernel<<<dim3(8, 256, 1), 256, SMEM_BYTES>>>(
        k_hi, 1024, 0, wqk_hi, wqk_lo, 1024, 0,
        (float*)0, kp_hi, kp_lo, (half*)0, (half*)0, (const float*)0,
        1024, 0, 0, 1024, (const float*)0, 0, 2);

    // 5) build vT (gathered) / tT
    transpose_conv_kernel<<<dim3(16, 16, NB), 256>>>(v, vT_hi, vT_lo, 1);
    transpose_conv_kernel<<<dim3(16, 16, NB), 256>>>(tsp, tT_hi, tT_lo, 0);

    // 6) scores_full = qp @ kp^T  (fp32, N=1024, batched)
    gemm_fp16_kernel<<<dim3(8, 8, NB), 256, SMEM_BYTES>>>(
        qp_hi, 1024, (long long)NLQ * ND, kp_hi, kp_lo, 1024, (long long)NT * ND,
        attn, (half*)0, (half*)0, (half*)0, (half*)0, (const float*)0,
        1024, (long long)NLQ * NT, 0, 1024, (const float*)0, 0, 0);

    // 7) softmax (gather + dummy column in-kernel) -> attn fp16
    softmax_kernel<<<NB * NLQ, 256>>>(dummy);

    // 8) out = attn @ v_sel, fused x1 = out*q, x2 = q-out  (mode 3)
    gemm_fp16_kernel<<<dim3(8, 8, NB), 256, SMEM_BYTES>>>(
        at_hi, 1024, (long long)NLQ * ND, vT_hi, vT_lo, 1024, (long long)ND * NT,
        (float*)0, (half*)0, (half*)0, x1_hi, x2_hi, q,
        1024, (long long)NLQ * ND, 0, 1024, (const float*)0, 0, 3);

    // 9) tsp_out = attn @ tsp -> second output (fp32)
    gemm_fp16_kernel<<<dim3(8, 8, NB), 256, SMEM_BYTES>>>(
        at_hi, 1024, (long long)NLQ * ND, tT_hi, tT_lo, 1024, (long long)ND * NT,
        tsp_outp, (half*)0, (half*)0, (half*)0, (half*)0, (const float*)0,
        1024, (long long)NLQ * ND, 0, 1024, (const float*)0, 0, 0);

    // 10) o1 = relu(x1 @ w1^T + b1) -> xcat[:, 0:512] (hi)
    gemm_fp16_kernel<<<dim3(4, 256, 1), 256, SMEM_BYTES>>>(
        x1_hi, 1024, 0, w1_hi, w1_lo, 1024, 0,
        (float*)0, xcat_hi, (half*)0, (half*)0, (half*)0, (const float*)0,
        2048, 0, 0, 1024, b1, 1, 1);

    // 11) o2 = relu(x2 @ w2^T + b2) -> xcat[:, 512:1024] (hi)
    gemm_fp16_kernel<<<dim3(4, 256, 1), 256, SMEM_BYTES>>>(
        x2_hi, 1024, 0, w2_hi, w2_lo, 1024, 0,
        (float*)0, xcat_hi, (half*)0, (half*)0, (half*)0, (const float*)0,
        2048, 0, 512, 1024, b2, 1, 1);

    // 12) output = xcat @ w3^T + b3 -> first output (fp32)
    gemm_fp16_kernel<<<dim3(8, 256, 1), 256, SMEM_BYTES>>>(
        xcat_hi, 2048, 0, w3_hi, w3_lo, 2048, 0,
        outp, (half*)0, (half*)0, (half*)0, (half*)0, (const float*)0,
        1024, 0, 0, 2048, b3, 0, 0);
}

// round 14
// speedup vs baseline: 4.5129x; 1.0966x over previous
#include <cuda_runtime.h>
#include <cuda_fp16.h>
#include <stdint.h>

#define DUMMY_CLASS 100
#define NB   32
#define NLQ  1024
#define NT   1024
#define ND   1024

// ---------------- scratch (device globals; no allocation allowed) ------------
__device__ __align__(16) half g_xcat_hi[67108864];  // (B*LQ, 2048): [o1|o2|q]
__device__ __align__(16) half g_k_hi  [33554432];
__device__ __align__(16) half g_wT_hi [1048576];    // W^T (transposed w_qk)
__device__ __align__(16) half g_wT_lo [1048576];
__device__ __align__(16) half g_G_hi  [1048576];    // G = W^T W
__device__ __align__(16) half g_G_lo  [1048576];
__device__ __align__(16) half g_w1_hi [524288];
__device__ __align__(16) half g_w1_lo [524288];
__device__ __align__(16) half g_w2_hi [524288];
__device__ __align__(16) half g_w2_lo [524288];
__device__ __align__(16) half g_w3_hi [2097152];
__device__ __align__(16) half g_w3_lo [2097152];
__device__ __align__(16) half g_U_hi  [33554432];   // U = k @ G
__device__ __align__(16) half g_U_lo  [33554432];
__device__ __align__(16) half g_vT_hi [33554432];
__device__ __align__(16) half g_vT_lo [33554432];
__device__ __align__(16) half g_tT_hi [33554432];
__device__ __align__(16) half g_tT_lo [33554432];
__device__ float g_attn[33554432];                   // 32*1024*1024 scores
__device__ __align__(16) half g_at_hi [33554432];
__device__ __align__(16) half g_x1_hi [33554432];
__device__ __align__(16) half g_x2_hi [33554432];
__device__ float g_wtilde[1024];                     // W^T @ dummy
__device__ int g_pos [1024];
__device__ int g_mask[1024];

// ---------------- helpers ----------------------------------------------------
__device__ __forceinline__ uint32_t smem_u32(const void* p) {
    uint32_t a;
    asm("{ .reg .u64 t; cvta.to.shared.u64 t, %1; cvt.u32.u64 %0, t; }"
        : "=r"(a) : "l"(p));
    return a;
}
__device__ __forceinline__ void cp16(uint32_t dst, const void* src) {
    asm volatile("cp.async.cg.shared.global [%0], [%1], 16;"
                 :: "r"(dst), "l"(src) : "memory");
}
__device__ __forceinline__ void cp_commit() {
    asm volatile("cp.async.commit_group;" ::: "memory");
}
__device__ __forceinline__ void ldm4(uint32_t* r, uint32_t addr) {
    asm volatile("ldmatrix.sync.aligned.m8n8.x4.shared.b16 {%0,%1,%2,%3}, [%4];"
                 : "=r"(r[0]), "=r"(r[1]), "=r"(r[2]), "=r"(r[3]) : "r"(addr));
}
__device__ __forceinline__ void mma16816(float* c, const uint32_t* a, const uint32_t* b) {
    asm volatile("mma.sync.aligned.m16n8k16.row.col.f32.f16.f16.f32 "
                 "{%0,%1,%2,%3}, {%4,%5,%6,%7}, {%8,%9}, {%0,%1,%2,%3};"
                 : "+f"(c[0]), "+f"(c[1]), "+f"(c[2]), "+f"(c[3])
                 : "r"(a[0]), "r"(a[1]), "r"(a[2]), "r"(a[3]), "r"(b[0]), "r"(b[1]));
}
__device__ __forceinline__ void hilo(float v, half& h, half& l) {
    h = __float2half_rn(v);
    l = __float2half_rn(v - __half2float(h));
}
__device__ __forceinline__ uint32_t pack2(half a, half b) {
    return (uint32_t)__half_as_ushort(a) | ((uint32_t)__half_as_ushort(b) << 16);
}

// ---------------- pos / mask scan --------------------------------------------
__global__ void pos_kernel(const int* __restrict__ supp) {
    __shared__ int s[1024];
    int t = threadIdx.x;
    int m = (supp[t] != DUMMY_CLASS) ? 1 : 0;
    g_mask[t] = m;
    s[t] = m;
    __syncthreads();
    for (int off = 1; off < 1024; off <<= 1) {
        int v = (t >= off) ? s[t - off] : 0;
        __syncthreads();
        s[t] += v;
        __syncthreads();
    }
    int p = s[t] - 1;
    g_pos[t] = p < 0 ? 0 : p;
}

// ---------------- w~ = W^T @ dummy (fp32) -------------------------------------
__global__ void wtilde_kernel(const float* __restrict__ wqk,
                              const float* __restrict__ dummy) {
    int i = blockIdx.x * 256 + threadIdx.x;   // 0..1023
    float s = 0.f;
    for (int k2 = 0; k2 < 1024; k2++)
        s += wqk[k2 * 1024 + i] * dummy[k2];
    g_wtilde[i] = s;
}

// ---------------- fp32 -> fp16 hi(/lo) conversion ----------------------------
__global__ void conv_kernel(const float* __restrict__ src,
                            half* __restrict__ hi, half* __restrict__ lo,
                            int cols4, int lddst) {
    int i4 = blockIdx.x * 256 + threadIdx.x;
    float4 v = ((const float4*)src)[i4];
    long long row = i4 / cols4;
    int c4 = i4 % cols4;
    long long o = row * (long long)lddst + (long long)c4 * 4;
    half h0, h1, h2, h3, l0, l1, l2, l3;
    hilo(v.x, h0, l0); hilo(v.y, h1, l1); hilo(v.z, h2, l2); hilo(v.w, h3, l3);
    uint2 uh; uh.x = pack2(h0, h1); uh.y = pack2(h2, h3);
    *(uint2*)(hi + o) = uh;
    if (lo) {
        uint2 ul; ul.x = pack2(l0, l1); ul.y = pack2(l2, l3);
        *(uint2*)(lo + o) = ul;
    }
}

// ---------------- transpose + convert (optionally gathered) ------------------
__global__ void transpose_conv_kernel(const float* __restrict__ src,
                                      half* __restrict__ dhi, half* __restrict__ dlo,
                                      int gathered) {
    __shared__ float tile[64][65];
    int b = blockIdx.z;
    int t0 = blockIdx.y * 64;
    int d0 = blockIdx.x * 64;
    int tid = threadIdx.x;
#pragma unroll
    for (int j = 0; j < 4; j++) {
        int i = tid + j * 256;
        int r = i >> 4;
        int c4 = i & 15;
        int tg = t0 + r;
        int srow = tg;
        bool z = false;
        if (gathered) { z = (g_mask[tg] == 0); srow = g_pos[tg]; }
        float4 v = z ? make_float4(0.f, 0.f, 0.f, 0.f)
                     : ((const float4*)src)[((long long)b * NT + srow) * 256 + (d0 >> 2) + c4];
        tile[r][c4 * 4 + 0] = v.x; tile[r][c4 * 4 + 1] = v.y;
        tile[r][c4 * 4 + 2] = v.z; tile[r][c4 * 4 + 3] = v.w;
    }
    __syncthreads();
#pragma unroll
    for (int j = 0; j < 4; j++) {
        int i = tid + j * 256;
        int r = i >> 4;
        int c4 = i & 15;
        half h[4], l[4];
#pragma unroll
        for (int e = 0; e < 4; e++) hilo(tile[c4 * 4 + e][r], h[e], l[e]);
        long long o = ((long long)b * ND + d0 + r) * (long long)NT + t0 + c4 * 4;
        uint2 uh; uh.x = pack2(h[0], h[1]); uh.y = pack2(h[2], h[3]);
        uint2 ul; ul.x = pack2(l[0], l[1]); ul.y = pack2(l[2], l[3]);
        *(uint2*)(dhi + o) = uh;
        *(uint2*)(dlo + o) = ul;
    }
}

// ---------------- split-fp16 HMMA GEMM (NT): C = Ah*(Bh+Bl)^T ----------------
// CTA tile 128x128, 8 warps (2m x 4n), warp tile 64x32, K-chunk 64,
// 2-stage cp.async double buffer, 96 KB smem -> 2 CTAs/SM.
// mode: 0 = fp32 C (+bias), 1 = fp16-hi C (+bias+relu), 2 = fp16 hi+lo C,
//       3 = fused: out -> X1=out*q, X2=q-out (fp16 hi).
#define KC      64
#define STAGES  2
#define OFF_AH  0
#define OFF_BH  16384
#define OFF_BL  32768
#define STAGE_B 49152
#define SMEM_BYTES (STAGES * STAGE_B)

__global__ void __launch_bounds__(256, 2) gemm_fp16_kernel(
    const half* __restrict__ Ahi, int lda, long long sA,
    const half* __restrict__ Bhi, const half* __restrict__ Blo, int ldb, long long sB,
    float* __restrict__ Cf, half* __restrict__ Chi, half* __restrict__ Clo,
    half* __restrict__ X1, half* __restrict__ X2, const float* __restrict__ qsrc,
    int ldc, long long sC, int coloff,
    int K, const float* __restrict__ bias, int relu, int mode)
{
    extern __shared__ __align__(1024) char smem[];
    const uint32_t sb = smem_u32(smem);
    const int tid = threadIdx.x;
    const int wid = tid >> 5;
    const int l   = tid & 31;

    const long long bz = blockIdx.z;
    const half* pAh = Ahi + bz * sA + (long long)(blockIdx.y * 128) * lda;
    const half* pBh = Bhi + bz * sB + (long long)(blockIdx.x * 128) * ldb;
    const half* pBl = Blo + bz * sB + (long long)(blockIdx.x * 128) * ldb;
    const int S = K / KC;

    // loaders: 2 threads per row, 4 x 16B chunks each (128 rows)
    const int crow = tid >> 1;
    const int cc0  = (tid & 1) << 2;

    auto load_stage = [&](int s) {
        uint32_t bp = sb + (s & 1) * STAGE_B;
        long long k0 = (long long)s * KC;
        const half* rA = pAh + (long long)crow * lda + k0;
        const half* rBh = pBh + (long long)crow * ldb + k0;
        const half* rBl = pBl + (long long)crow * ldb + k0;
        uint32_t rowo = (uint32_t)crow * 128;
        uint32_t x = (uint32_t)(crow & 7) << 4;
#pragma unroll
        for (int j = 0; j < 4; j++) {
            int c = cc0 + j;
            uint32_t o = rowo + (((uint32_t)c << 4) ^ x);
            cp16(bp + OFF_AH + o, rA + c * 8);
            cp16(bp + OFF_BH + o, rBh + c * 8);
            cp16(bp + OFF_BL + o, rBl + c * 8);
        }
    };

    load_stage(0); cp_commit();

    const int wm = wid & 1;          // 0..1 -> 64-row half
    const int wn = wid >> 1;         // 0..3 -> 32-col quarter
    const int arow = wm * 64 + (l & 15);
    const uint32_t aco = ((uint32_t)(l >> 4) << 4);
    const uint32_t axor = (uint32_t)(arow & 7) << 4;
    const int brow = wn * 32 + (l & 7) + ((l >> 4) << 3);
    const uint32_t bco = ((uint32_t)((l >> 3) & 1) << 4);
    const uint32_t bxor = (uint32_t)(brow & 7) << 4;

    float acc[4][4][4];
#pragma unroll
    for (int mf = 0; mf < 4; mf++)
#pragma unroll
        for (int nf = 0; nf < 4; nf++)
#pragma unroll
            for (int e = 0; e < 4; e++) acc[mf][nf][e] = 0.f;

    for (int s = 0; s < S; s++) {
        // prefetch next stage into the OTHER buffer (safe: compute(s-1) done)
        if (s + 1 < S) { load_stage(s + 1); cp_commit(); }
        if (s + 1 < S) asm volatile("cp.async.wait_group 1;" ::: "memory");
        else           asm volatile("cp.async.wait_group 0;" ::: "memory");
        __syncthreads();

        uint32_t bp = sb + (s & 1) * STAGE_B;
        uint32_t aBase = bp + OFF_AH + (uint32_t)arow * 128;
        uint32_t bBaseH = bp + OFF_BH + (uint32_t)brow * 128;
        uint32_t bBaseL = bp + OFF_BL + (uint32_t)brow * 128;

#pragma unroll
        for (int k16 = 0; k16 < KC / 16; k16++) {
            uint32_t ak = (((uint32_t)k16 << 5) + aco) ^ axor;
            uint32_t bk = (((uint32_t)k16 << 5) + bco) ^ bxor;
            uint32_t ah[4][4], bh[4][2], bl[4][2];
#pragma unroll
            for (int mf = 0; mf < 4; mf++)
                ldm4(ah[mf], aBase + (uint32_t)(mf * 16) * 128 + ak);
#pragma unroll
            for (int g = 0; g < 2; g++) {
                uint32_t r[4];
                ldm4(r, bBaseH + (uint32_t)(g * 16) * 128 + bk);
                bh[g*2][0] = r[0]; bh[g*2][1] = r[1];
                bh[g*2+1][0] = r[2]; bh[g*2+1][1] = r[3];
                ldm4(r, bBaseL + (uint32_t)(g * 16) * 128 + bk);
                bl[g*2][0] = r[0]; bl[g*2][1] = r[1];
                bl[g*2+1][0] = r[2]; bl[g*2+1][1] = r[3];
            }
#pragma unroll
            for (int mf = 0; mf < 4; mf++)
#pragma unroll
                for (int nf = 0; nf < 4; nf++) {
                    mma16816(acc[mf][nf], ah[mf], bh[nf]);
                    mma16816(acc[mf][nf], ah[mf], bl[nf]);
                }
        }
        __syncthreads();   // compute(s) done before next iter overwrites buf s&1
    }

    // ---- epilogue -----------------------------------------------------------
    const int gi0 = blockIdx.y * 128 + wm * 64 + (l >> 2);
    const int gj0 = blockIdx.x * 128 + wn * 32 + 2 * (l & 3);
#pragma unroll
    for (int mf = 0; mf < 4; mf++) {
        int gi = gi0 + mf * 16;
#pragma unroll
        for (int nf = 0; nf < 4; nf++) {
            int gj = gj0 + nf * 8;
            float v0 = acc[mf][nf][0], v1 = acc[mf][nf][1];
            float v2 = acc[mf][nf][2], v3 = acc[mf][nf][3];
            if (bias) {
                float b0 = bias[gj], b1 = bias[gj + 1];
                v0 += b0; v1 += b1; v2 += b0; v3 += b1;
            }
            if (relu) {
                v0 = fmaxf(v0, 0.f); v1 = fmaxf(v1, 0.f);
                v2 = fmaxf(v2, 0.f); v3 = fmaxf(v3, 0.f);
            }
            long long o0 = bz * sC + (long long)gi * ldc + coloff + gj;
            long long o1 = o0 + (long long)8 * ldc;
            if (mode == 0) {
                *(float2*)(Cf + o0) = make_float2(v0, v1);
                *(float2*)(Cf + o1) = make_float2(v2, v3);
            } else if (mode == 1) {
                *(uint32_t*)(Chi + o0) = pack2(__float2half_rn(v0), __float2half_rn(v1));
                *(uint32_t*)(Chi + o1) = pack2(__float2half_rn(v2), __float2half_rn(v3));
            } else if (mode == 2) {
                half h0, h1, h2, h3, l0, l1, l2, l3;
                hilo(v0, h0, l0); hilo(v1, h1, l1);
                hilo(v2, h2, l2); hilo(v3, h3, l3);
                *(uint32_t*)(Chi + o0) = pack2(h0, h1);
                *(uint32_t*)(Clo + o0) = pack2(l0, l1);
                *(uint32_t*)(Chi + o1) = pack2(h2, h3);
                *(uint32_t*)(Clo + o1) = pack2(l2, l3);
            } else {
                float2 q0 = *(const float2*)(qsrc + o0);
                float2 q1 = *(const float2*)(qsrc + o1);
                *(uint32_t*)(X1 + o0) = pack2(__float2half_rn(v0 * q0.x),
                                              __float2half_rn(v1 * q0.y));
                *(uint32_t*)(X1 + o1) = pack2(__float2half_rn(v2 * q1.x),
                                              __float2half_rn(v3 * q1.y));
                *(uint32_t*)(X2 + o0) = pack2(__float2half_rn(q0.x - v0),
                                              __float2half_rn(q0.y - v1));
                *(uint32_t*)(X2 + o1) = pack2(__float2half_rn(q1.x - v2),
                                              __float2half_rn(q1.y - v3));
            }
        }
    }
}

// ---------------- softmax with in-kernel gather + dummy column ---------------
// sdum = q_row . wtilde  (fp32, exact), vals[t] = mask[t] ? s[pos[t]] : sdum.
__global__ void softmax_kernel(const float* __restrict__ q) {
    const long long r = blockIdx.x;
    const float* srow = g_attn + r * 1024;
    const float* qrow = q + r * 1024;
    const int tid = threadIdx.x;
    __shared__ float sred[8];
    __shared__ float sbc;

    float sd = 0.f;
    for (int j4 = tid; j4 < 256; j4 += 256) {
        float4 qv = ((const float4*)qrow)[j4];
        float4 wv = ((const float4*)g_wtilde)[j4];
        sd += qv.x * wv.x + qv.y * wv.y + qv.z * wv.z + qv.w * wv.w;
    }
#pragma unroll
    for (int o = 16; o; o >>= 1) sd += __shfl_xor_sync(0xffffffffu, sd, o);
    if ((tid & 31) == 0) sred[tid >> 5] = sd;
    __syncthreads();
    if (tid == 0) {
        float t = 0.f;
#pragma unroll
        for (int i = 0; i < 8; i++) t += sred[i];
        sbc = t;
    }
    __syncthreads();
    const float sdum = sbc;

    float val[4];
    float lm = sdum;
#pragma unroll
    for (int jj = 0; jj < 4; jj++) {
        int j = tid + jj * 256;
        val[jj] = g_mask[j] ? srow[g_pos[j]] : sdum;
        lm = fmaxf(lm, val[jj]);
    }
#pragma unroll
    for (int o = 16; o; o >>= 1) lm = fmaxf(lm, __shfl_xor_sync(0xffffffffu, lm, o));
    if ((tid & 31) == 0) sred[tid >> 5] = lm;
    __syncthreads();
    float m = sred[0];
#pragma unroll
    for (int i = 1; i < 8; i++) m = fmaxf(m, sred[i]);

    const float invT = 0.03125f;
    float e[4];
    float ls = (tid == 0) ? __expf((sdum - m) * invT) : 0.f;
#pragma unroll
    for (int jj = 0; jj < 4; jj++) {
        e[jj] = __expf((val[jj] - m) * invT);
        ls += e[jj];
    }
#pragma unroll
    for (int o = 16; o; o >>= 1) ls += __shfl_xor_sync(0xffffffffu, ls, o);
    if ((tid & 31) == 0) sred[tid >> 5] = ls;
    __syncthreads();
    float s = 0.f;
#pragma unroll
    for (int i = 0; i < 8; i++) s += sred[i];
    float inv = 1.f / s;
    long long ob = r * (long long)NT;
#pragma unroll
    for (int jj = 0; jj < 4; jj++)
        g_at_hi[ob + tid + jj * 256] = __float2half_rn(e[jj] * inv);
}

// ---------------- host launcher ----------------------------------------------
extern "C" void kernel_launch(void* const* d_in, const int* in_sizes, int n_in,
                              void* d_out, int out_size) {
    const float* q     = (const float*)d_in[0];
    const float* k     = (const float*)d_in[1];
    const float* v     = (const float*)d_in[2];
    const float* tsp   = (const float*)d_in[3];
    const int*   supp  = (const int*)  d_in[4];
    const float* w_qk  = (const float*)d_in[5];
    const float* dummy = (const float*)d_in[6];
    const float* w1    = (const float*)d_in[7];
    const float* b1    = (const float*)d_in[8];
    const float* w2    = (const float*)d_in[9];
    const float* b2    = (const float*)d_in[10];
    const float* w3    = (const float*)d_in[11];
    const float* b3    = (const float*)d_in[12];
    float* outp = (float*)d_out;
    float* tsp_outp = outp + (long long)NB * NLQ * ND;

    cudaFuncSetAttribute(gemm_fp16_kernel,
                         cudaFuncAttributeMaxDynamicSharedMemorySize, SMEM_BYTES);

    half *xcat_hi, *k_hi, *wT_hi, *wT_lo, *G_hi, *G_lo;
    half *w1_hi, *w1_lo, *w2_hi, *w2_lo, *w3_hi, *w3_lo;
    half *U_hi, *U_lo;
    half *vT_hi, *vT_lo, *tT_hi, *tT_lo, *at_hi, *x1_hi, *x2_hi;
    float *attn;
    cudaGetSymbolAddress((void**)&xcat_hi, g_xcat_hi);
    cudaGetSymbolAddress((void**)&k_hi, g_k_hi);
    cudaGetSymbolAddress((void**)&wT_hi, g_wT_hi);
    cudaGetSymbolAddress((void**)&wT_lo, g_wT_lo);
    cudaGetSymbolAddress((void**)&G_hi, g_G_hi);
    cudaGetSymbolAddress((void**)&G_lo, g_G_lo);
    cudaGetSymbolAddress((void**)&w1_hi, g_w1_hi);
    cudaGetSymbolAddress((void**)&w1_lo, g_w1_lo);
    cudaGetSymbolAddress((void**)&w2_hi, g_w2_hi);
    cudaGetSymbolAddress((void**)&w2_lo, g_w2_lo);
    cudaGetSymbolAddress((void**)&w3_hi, g_w3_hi);
    cudaGetSymbolAddress((void**)&w3_lo, g_w3_lo);
    cudaGetSymbolAddress((void**)&U_hi, g_U_hi);
    cudaGetSymbolAddress((void**)&U_lo, g_U_lo);
    cudaGetSymbolAddress((void**)&vT_hi, g_vT_hi);
    cudaGetSymbolAddress((void**)&vT_lo, g_vT_lo);
    cudaGetSymbolAddress((void**)&tT_hi, g_tT_hi);
    cudaGetSymbolAddress((void**)&tT_lo, g_tT_lo);
    cudaGetSymbolAddress((void**)&at_hi, g_at_hi);
    cudaGetSymbolAddress((void**)&x1_hi, g_x1_hi);
    cudaGetSymbolAddress((void**)&x2_hi, g_x2_hi);
    cudaGetSymbolAddress((void**)&attn, g_attn);

    // 1) pos/mask + w~ = W^T dummy
    pos_kernel<<<1, 1024>>>(supp);
    wtilde_kernel<<<4, 256>>>(w_qk, dummy);

    // 2) conversions
    conv_kernel<<<32768, 256>>>(q, xcat_hi + 1024, (half*)0, 256, 2048);
    conv_kernel<<<32768, 256>>>(k, k_hi, (half*)0, 256, 1024);
    conv_kernel<<<512, 256>>>(w1, w1_hi, w1_lo, 256, 1024);
    conv_kernel<<<512, 256>>>(w2, w2_hi, w2_lo, 256, 1024);
    conv_kernel<<<2048, 256>>>(w3, w3_hi, w3_lo, 512, 2048);

    // 3) W^T (hi+lo) via transpose; then G = W^T W (hi+lo out)
    transpose_conv_kernel<<<dim3(16, 16, 1), 256>>>(w_qk, wT_hi, wT_lo, 0);
    gemm_fp16_kernel<<<dim3(8, 8, 1), 256, SMEM_BYTES>>>(
        wT_hi, 1024, 0, wT_hi, wT_lo, 1024, 0,
        (float*)0, G_hi, G_lo, (half*)0, (half*)0, (const float*)0,
        1024, 0, 0, 1024, (const float*)0, 0, 2);

    // 4) U = k @ G  (hi+lo out, flat 32768 rows)
    gemm_fp16_kernel<<<dim3(8, 256, 1), 256, SMEM_BYTES>>>(
        k_hi, 1024, 0, G_hi, G_lo, 1024, 0,
        (float*)0, U_hi, U_lo, (half*)0, (half*)0, (const float*)0,
        1024, 0, 0, 1024, (const float*)0, 0, 2);

    // 5) build vT (gathered) / tT
    transpose_conv_kernel<<<dim3(16, 16, NB), 256>>>(v, vT_hi, vT_lo, 1);
    transpose_conv_kernel<<<dim3(16, 16, NB), 256>>>(tsp, tT_hi, tT_lo, 0);

    // 6) scores = q @ U^T  (fp32, batched; A = q_hi inside xcat, lda 2048)
    gemm_fp16_kernel<<<dim3(8, 8, NB), 256, SMEM_BYTES>>>(
        xcat_hi + 1024, 2048, (long long)NLQ * 2048,
        U_hi, U_lo, 1024, (long long)NT * ND,
        attn, (half*)0, (half*)0, (half*)0, (half*)0, (const float*)0,
        1024, (long long)NLQ * NT, 0, 1024, (const float*)0, 0, 0);

    // 7) softmax (gather + exact fp32 dummy column) -> attn fp16
    softmax_kernel<<<NB * NLQ, 256>>>(q);

    // 8) out = attn @ v_sel, fused x1 = out*q, x2 = q-out  (mode 3)
    gemm_fp16_kernel<<<dim3(8, 8, NB), 256, SMEM_BYTES>>>(
        at_hi, 1024, (long long)NLQ * ND, vT_hi, vT_lo, 1024, (long long)ND * NT,
        (float*)0, (half*)0, (half*)0, x1_hi, x2_hi, q,
        1024, (long long)NLQ * ND, 0, 1024, (const float*)0, 0, 3);

    // 9) tsp_out = attn @ tsp -> second output (fp32)
    gemm_fp16_kernel<<<dim3(8, 8, NB), 256, SMEM_BYTES>>>(
        at_hi, 1024, (long long)NLQ * ND, tT_hi, tT_lo, 1024, (long long)ND * NT,
        tsp_outp, (half*)0, (half*)0, (half*)0, (half*)0, (const float*)0,
        1024, (long long)NLQ * ND, 0, 1024, (const float*)0, 0, 0);

    // 10) o1 = relu(x1 @ w1^T + b1) -> xcat[:, 0:512] (hi)
    gemm_fp16_kernel<<<dim3(4, 256, 1), 256, SMEM_BYTES>>>(
        x1_hi, 1024, 0, w1_hi, w1_lo, 1024, 0,
        (float*)0, xcat_hi, (half*)0, (half*)0, (half*)0, (const float*)0,
        2048, 0, 0, 1024, b1, 1, 1);

    // 11) o2 = relu(x2 @ w2^T + b2) -> xcat[:, 512:1024] (hi)
    gemm_fp16_kernel<<<dim3(4, 256, 1), 256, SMEM_BYTES>>>(
        x2_hi, 1024, 0, w2_hi, w2_lo, 1024, 0,
        (float*)0, xcat_hi, (half*)0, (half*)0, (half*)0, (const float*)0,
        2048, 0, 512, 1024, b2, 1, 1);

    // 12) output = xcat @ w3^T + b3 -> first output (fp32)
    gemm_fp16_kernel<<<dim3(8, 256, 1), 256, SMEM_BYTES>>>(
        xcat_hi, 2048, 0, w3_hi, w3_lo, 2048, 0,
        outp, (half*)0, (half*)0, (half*)0, (half*)0, (const float*)0,
        1024, 0, 0, 2048, b3, 0, 0);
}

// round 15
// speedup vs baseline: 4.7623x; 1.0553x over previous
#include <cuda_runtime.h>
#include <cuda_fp16.h>
#include <stdint.h>

#define DUMMY_CLASS 100
#define NB   32
#define NLQ  1024
#define NT   1024
#define ND   1024

// ---------------- scratch (device globals; no allocation allowed) ------------
__device__ __align__(16) half g_xcat_hi[67108864];  // (B*LQ, 2048): [o1|o2|q]
__device__ __align__(16) half g_k_hi  [33554432];
__device__ __align__(16) half g_wT_hi [1048576];    // W^T (transposed w_qk)
__device__ __align__(16) half g_wT_lo [1048576];
__device__ __align__(16) half g_G_hi  [1048576];    // G = W^T W
__device__ __align__(16) half g_G_lo  [1048576];
__device__ __align__(16) half g_w1_hi [524288];
__device__ __align__(16) half g_w1_lo [524288];
__device__ __align__(16) half g_w2_hi [524288];
__device__ __align__(16) half g_w2_lo [524288];
__device__ __align__(16) half g_w3_hi [2097152];
__device__ __align__(16) half g_w3_lo [2097152];
__device__ __align__(16) half g_U_hi  [33554432];   // U = k @ G
__device__ __align__(16) half g_U_lo  [33554432];
__device__ __align__(16) half g_vT_hi [33554432];
__device__ __align__(16) half g_tT_hi [33554432];
__device__ float g_attn[33554432];                   // 32*1024*1024 scores
__device__ __align__(16) half g_at_hi [33554432];
__device__ __align__(16) half g_x1_hi [33554432];
__device__ __align__(16) half g_x2_hi [33554432];
__device__ float g_wtilde[1024];                     // W^T @ dummy
__device__ int g_pos [1024];
__device__ int g_mask[1024];

// ---------------- helpers ----------------------------------------------------
__device__ __forceinline__ uint32_t smem_u32(const void* p) {
    uint32_t a;
    asm("{ .reg .u64 t; cvta.to.shared.u64 t, %1; cvt.u32.u64 %0, t; }"
        : "=r"(a) : "l"(p));
    return a;
}
__device__ __forceinline__ void cp16(uint32_t dst, const void* src) {
    asm volatile("cp.async.cg.shared.global [%0], [%1], 16;"
                 :: "r"(dst), "l"(src) : "memory");
}
__device__ __forceinline__ void cp_commit() {
    asm volatile("cp.async.commit_group;" ::: "memory");
}
__device__ __forceinline__ void ldm4(uint32_t* r, uint32_t addr) {
    asm volatile("ldmatrix.sync.aligned.m8n8.x4.shared.b16 {%0,%1,%2,%3}, [%4];"
                 : "=r"(r[0]), "=r"(r[1]), "=r"(r[2]), "=r"(r[3]) : "r"(addr));
}
__device__ __forceinline__ void mma16816(float* c, const uint32_t* a, const uint32_t* b) {
    asm volatile("mma.sync.aligned.m16n8k16.row.col.f32.f16.f16.f32 "
                 "{%0,%1,%2,%3}, {%4,%5,%6,%7}, {%8,%9}, {%0,%1,%2,%3};"
                 : "+f"(c[0]), "+f"(c[1]), "+f"(c[2]), "+f"(c[3])
                 : "r"(a[0]), "r"(a[1]), "r"(a[2]), "r"(a[3]), "r"(b[0]), "r"(b[1]));
}
__device__ __forceinline__ void hilo(float v, half& h, half& l) {
    h = __float2half_rn(v);
    l = __float2half_rn(v - __half2float(h));
}
__device__ __forceinline__ uint32_t pack2(half a, half b) {
    return (uint32_t)__half_as_ushort(a) | ((uint32_t)__half_as_ushort(b) << 16);
}

// ---------------- pos / mask scan --------------------------------------------
__global__ void pos_kernel(const int* __restrict__ supp) {
    __shared__ int s[1024];
    int t = threadIdx.x;
    int m = (supp[t] != DUMMY_CLASS) ? 1 : 0;
    g_mask[t] = m;
    s[t] = m;
    __syncthreads();
    for (int off = 1; off < 1024; off <<= 1) {
        int v = (t >= off) ? s[t - off] : 0;
        __syncthreads();
        s[t] += v;
        __syncthreads();
    }
    int p = s[t] - 1;
    g_pos[t] = p < 0 ? 0 : p;
}

// ---------------- w~ = W^T @ dummy (fp32) -------------------------------------
__global__ void wtilde_kernel(const float* __restrict__ wqk,
                              const float* __restrict__ dummy) {
    int i = blockIdx.x * 256 + threadIdx.x;   // 0..1023
    float s = 0.f;
    for (int k2 = 0; k2 < 1024; k2++)
        s += wqk[k2 * 1024 + i] * dummy[k2];
    g_wtilde[i] = s;
}

// ---------------- fp32 -> fp16 hi(/lo) conversion ----------------------------
__global__ void conv_kernel(const float* __restrict__ src,
                            half* __restrict__ hi, half* __restrict__ lo,
                            int cols4, int lddst) {
    int i4 = blockIdx.x * 256 + threadIdx.x;
    float4 v = ((const float4*)src)[i4];
    long long row = i4 / cols4;
    int c4 = i4 % cols4;
    long long o = row * (long long)lddst + (long long)c4 * 4;
    half h0, h1, h2, h3, l0, l1, l2, l3;
    hilo(v.x, h0, l0); hilo(v.y, h1, l1); hilo(v.z, h2, l2); hilo(v.w, h3, l3);
    uint2 uh; uh.x = pack2(h0, h1); uh.y = pack2(h2, h3);
    *(uint2*)(hi + o) = uh;
    if (lo) {
        uint2 ul; ul.x = pack2(l0, l1); ul.y = pack2(l2, l3);
        *(uint2*)(lo + o) = ul;
    }
}

// ---------------- transpose + convert (optionally gathered, lo optional) -----
__global__ void transpose_conv_kernel(const float* __restrict__ src,
                                      half* __restrict__ dhi, half* __restrict__ dlo,
                                      int gathered) {
    __shared__ float tile[64][65];
    int b = blockIdx.z;
    int t0 = blockIdx.y * 64;
    int d0 = blockIdx.x * 64;
    int tid = threadIdx.x;
#pragma unroll
    for (int j = 0; j < 4; j++) {
        int i = tid + j * 256;
        int r = i >> 4;
        int c4 = i & 15;
        int tg = t0 + r;
        int srow = tg;
        bool z = false;
        if (gathered) { z = (g_mask[tg] == 0); srow = g_pos[tg]; }
        float4 v = z ? make_float4(0.f, 0.f, 0.f, 0.f)
                     : ((const float4*)src)[((long long)b * NT + srow) * 256 + (d0 >> 2) + c4];
        tile[r][c4 * 4 + 0] = v.x; tile[r][c4 * 4 + 1] = v.y;
        tile[r][c4 * 4 + 2] = v.z; tile[r][c4 * 4 + 3] = v.w;
    }
    __syncthreads();
#pragma unroll
    for (int j = 0; j < 4; j++) {
        int i = tid + j * 256;
        int r = i >> 4;
        int c4 = i & 15;
        half h[4], l[4];
#pragma unroll
        for (int e = 0; e < 4; e++) hilo(tile[c4 * 4 + e][r], h[e], l[e]);
        long long o = ((long long)b * ND + d0 + r) * (long long)NT + t0 + c4 * 4;
        uint2 uh; uh.x = pack2(h[0], h[1]); uh.y = pack2(h[2], h[3]);
        *(uint2*)(dhi + o) = uh;
        if (dlo) {
            uint2 ul; ul.x = pack2(l[0], l[1]); ul.y = pack2(l[2], l[3]);
            *(uint2*)(dlo + o) = ul;
        }
    }
}

// ---------------- split-fp16 HMMA GEMM (NT): C = Ah*(Bh[+Bl])^T --------------
// CTA tile 128x128, 8 warps (2m x 4n), warp tile 64x32, K-chunk 64,
// 2-stage cp.async double buffer, 96 KB smem -> 2 CTAs/SM.
// Blo == nullptr -> hi-only B (half the MMA work).
// mode: 0 = fp32 C (+bias), 1 = fp16-hi C (+bias+relu), 2 = fp16 hi+lo C,
//       3 = fused: out -> X1=out*q, X2=q-out (fp16 hi).
#define KC      64
#define STAGES  2
#define OFF_AH  0
#define OFF_BH  16384
#define OFF_BL  32768
#define STAGE_B 49152
#define SMEM_BYTES (STAGES * STAGE_B)

__global__ void __launch_bounds__(256, 2) gemm_fp16_kernel(
    const half* __restrict__ Ahi, int lda, long long sA,
    const half* __restrict__ Bhi, const half* __restrict__ Blo, int ldb, long long sB,
    float* __restrict__ Cf, half* __restrict__ Chi, half* __restrict__ Clo,
    half* __restrict__ X1, half* __restrict__ X2, const float* __restrict__ qsrc,
    int ldc, long long sC, int coloff,
    int K, const float* __restrict__ bias, int relu, int mode)
{
    extern __shared__ __align__(1024) char smem[];
    const uint32_t sb = smem_u32(smem);
    const int tid = threadIdx.x;
    const int wid = tid >> 5;
    const int l   = tid & 31;
    const bool has_lo = (Blo != nullptr);

    const long long bz = blockIdx.z;
    const half* pAh = Ahi + bz * sA + (long long)(blockIdx.y * 128) * lda;
    const half* pBh = Bhi + bz * sB + (long long)(blockIdx.x * 128) * ldb;
    const half* pBl = has_lo ? Blo + bz * sB + (long long)(blockIdx.x * 128) * ldb : pBh;
    const int S = K / KC;

    // loaders: 2 threads per row, 4 x 16B chunks each (128 rows)
    const int crow = tid >> 1;
    const int cc0  = (tid & 1) << 2;

    auto load_stage = [&](int s) {
        uint32_t bp = sb + (s & 1) * STAGE_B;
        long long k0 = (long long)s * KC;
        const half* rA = pAh + (long long)crow * lda + k0;
        const half* rBh = pBh + (long long)crow * ldb + k0;
        const half* rBl = pBl + (long long)crow * ldb + k0;
        uint32_t rowo = (uint32_t)crow * 128;
        uint32_t x = (uint32_t)(crow & 7) << 4;
#pragma unroll
        for (int j = 0; j < 4; j++) {
            int c = cc0 + j;
            uint32_t o = rowo + (((uint32_t)c << 4) ^ x);
            cp16(bp + OFF_AH + o, rA + c * 8);
            cp16(bp + OFF_BH + o, rBh + c * 8);
            if (has_lo) cp16(bp + OFF_BL + o, rBl + c * 8);
        }
    };

    load_stage(0); cp_commit();

    const int wm = wid & 1;          // 0..1 -> 64-row half
    const int wn = wid >> 1;         // 0..3 -> 32-col quarter
    const int arow = wm * 64 + (l & 15);
    const uint32_t aco = ((uint32_t)(l >> 4) << 4);
    const uint32_t axor = (uint32_t)(arow & 7) << 4;
    const int brow = wn * 32 + (l & 7) + ((l >> 4) << 3);
    const uint32_t bco = ((uint32_t)((l >> 3) & 1) << 4);
    const uint32_t bxor = (uint32_t)(brow & 7) << 4;

    float acc[4][4][4];
#pragma unroll
    for (int mf = 0; mf < 4; mf++)
#pragma unroll
        for (int nf = 0; nf < 4; nf++)
#pragma unroll
            for (int e = 0; e < 4; e++) acc[mf][nf][e] = 0.f;

    for (int s = 0; s < S; s++) {
        // prefetch next stage into the OTHER buffer (safe: compute(s-1) done)
        if (s + 1 < S) { load_stage(s + 1); cp_commit(); }
        if (s + 1 < S) asm volatile("cp.async.wait_group 1;" ::: "memory");
        else           asm volatile("cp.async.wait_group 0;" ::: "memory");
        __syncthreads();

        uint32_t bp = sb + (s & 1) * STAGE_B;
        uint32_t aBase = bp + OFF_AH + (uint32_t)arow * 128;
        uint32_t bBaseH = bp + OFF_BH + (uint32_t)brow * 128;
        uint32_t bBaseL = bp + OFF_BL + (uint32_t)brow * 128;

#pragma unroll
        for (int k16 = 0; k16 < KC / 16; k16++) {
            uint32_t ak = (((uint32_t)k16 << 5) + aco) ^ axor;
            uint32_t bk = (((uint32_t)k16 << 5) + bco) ^ bxor;
            uint32_t ah[4][4], bh[4][2], bl[4][2];
#pragma unroll
            for (int mf = 0; mf < 4; mf++)
                ldm4(ah[mf], aBase + (uint32_t)(mf * 16) * 128 + ak);
#pragma unroll
            for (int g = 0; g < 2; g++) {
                uint32_t r[4];
                ldm4(r, bBaseH + (uint32_t)(g * 16) * 128 + bk);
                bh[g*2][0] = r[0]; bh[g*2][1] = r[1];
                bh[g*2+1][0] = r[2]; bh[g*2+1][1] = r[3];
                if (has_lo) {
                    ldm4(r, bBaseL + (uint32_t)(g * 16) * 128 + bk);
                    bl[g*2][0] = r[0]; bl[g*2][1] = r[1];
                    bl[g*2+1][0] = r[2]; bl[g*2+1][1] = r[3];
                }
            }
#pragma unroll
            for (int mf = 0; mf < 4; mf++)
#pragma unroll
                for (int nf = 0; nf < 4; nf++) {
                    mma16816(acc[mf][nf], ah[mf], bh[nf]);
                    if (has_lo) mma16816(acc[mf][nf], ah[mf], bl[nf]);
                }
        }
        __syncthreads();   // compute(s) done before next iter overwrites buf s&1
    }

    // ---- epilogue -----------------------------------------------------------
    const int gi0 = blockIdx.y * 128 + wm * 64 + (l >> 2);
    const int gj0 = blockIdx.x * 128 + wn * 32 + 2 * (l & 3);
#pragma unroll
    for (int mf = 0; mf < 4; mf++) {
        int gi = gi0 + mf * 16;
#pragma unroll
        for (int nf = 0; nf < 4; nf++) {
            int gj = gj0 + nf * 8;
            float v0 = acc[mf][nf][0], v1 = acc[mf][nf][1];
            float v2 = acc[mf][nf][2], v3 = acc[mf][nf][3];
            if (bias) {
                float b0 = bias[gj], b1 = bias[gj + 1];
                v0 += b0; v1 += b1; v2 += b0; v3 += b1;
            }
            if (relu) {
                v0 = fmaxf(v0, 0.f); v1 = fmaxf(v1, 0.f);
                v2 = fmaxf(v2, 0.f); v3 = fmaxf(v3, 0.f);
            }
            long long o0 = bz * sC + (long long)gi * ldc + coloff + gj;
            long long o1 = o0 + (long long)8 * ldc;
            if (mode == 0) {
                *(float2*)(Cf + o0) = make_float2(v0, v1);
                *(float2*)(Cf + o1) = make_float2(v2, v3);
            } else if (mode == 1) {
                *(uint32_t*)(Chi + o0) = pack2(__float2half_rn(v0), __float2half_rn(v1));
                *(uint32_t*)(Chi + o1) = pack2(__float2half_rn(v2), __float2half_rn(v3));
            } else if (mode == 2) {
                half h0, h1, h2, h3, l0, l1, l2, l3;
                hilo(v0, h0, l0); hilo(v1, h1, l1);
                hilo(v2, h2, l2); hilo(v3, h3, l3);
                *(uint32_t*)(Chi + o0) = pack2(h0, h1);
                *(uint32_t*)(Clo + o0) = pack2(l0, l1);
                *(uint32_t*)(Chi + o1) = pack2(h2, h3);
                *(uint32_t*)(Clo + o1) = pack2(l2, l3);
            } else {
                float2 q0 = *(const float2*)(qsrc + o0);
                float2 q1 = *(const float2*)(qsrc + o1);
                *(uint32_t*)(X1 + o0) = pack2(__float2half_rn(v0 * q0.x),
                                              __float2half_rn(v1 * q0.y));
                *(uint32_t*)(X1 + o1) = pack2(__float2half_rn(v2 * q1.x),
                                              __float2half_rn(v3 * q1.y));
                *(uint32_t*)(X2 + o0) = pack2(__float2half_rn(q0.x - v0),
                                              __float2half_rn(q0.y - v1));
                *(uint32_t*)(X2 + o1) = pack2(__float2half_rn(q1.x - v2),
                                              __float2half_rn(q1.y - v3));
            }
        }
    }
}

// ---------------- softmax with in-kernel gather + dummy column ---------------
// sdum = q_row . wtilde  (fp32, exact), vals[t] = mask[t] ? s[pos[t]] : sdum.
__global__ void softmax_kernel(const float* __restrict__ q) {
    const long long r = blockIdx.x;
    const float* srow = g_attn + r * 1024;
    const float* qrow = q + r * 1024;
    const int tid = threadIdx.x;
    __shared__ float sred[8];
    __shared__ float sbc;

    float sd = 0.f;
    for (int j4 = tid; j4 < 256; j4 += 256) {
        float4 qv = ((const float4*)qrow)[j4];
        float4 wv = ((const float4*)g_wtilde)[j4];
        sd += qv.x * wv.x + qv.y * wv.y + qv.z * wv.z + qv.w * wv.w;
    }
#pragma unroll
    for (int o = 16; o; o >>= 1) sd += __shfl_xor_sync(0xffffffffu, sd, o);
    if ((tid & 31) == 0) sred[tid >> 5] = sd;
    __syncthreads();
    if (tid == 0) {
        float t = 0.f;
#pragma unroll
        for (int i = 0; i < 8; i++) t += sred[i];
        sbc = t;
    }
    __syncthreads();
    const float sdum = sbc;

    float val[4];
    float lm = sdum;
#pragma unroll
    for (int jj = 0; jj < 4; jj++) {
        int j = tid + jj * 256;
        val[jj] = g_mask[j] ? srow[g_pos[j]] : sdum;
        lm = fmaxf(lm, val[jj]);
    }
#pragma unroll
    for (int o = 16; o; o >>= 1) lm = fmaxf(lm, __shfl_xor_sync(0xffffffffu, lm, o));
    if ((tid & 31) == 0) sred[tid >> 5] = lm;
    __syncthreads();
    float m = sred[0];
#pragma unroll
    for (int i = 1; i < 8; i++) m = fmaxf(m, sred[i]);

    const float invT = 0.03125f;
    float e[4];
    float ls = (tid == 0) ? __expf((sdum - m) * invT) : 0.f;
#pragma unroll
    for (int jj = 0; jj < 4; jj++) {
        e[jj] = __expf((val[jj] - m) * invT);
        ls += e[jj];
    }
#pragma unroll
    for (int o = 16; o; o >>= 1) ls += __shfl_xor_sync(0xffffffffu, ls, o);
    if ((tid & 31) == 0) sred[tid >> 5] = ls;
    __syncthreads();
    float s = 0.f;
#pragma unroll
    for (int i = 0; i < 8; i++) s += sred[i];
    float inv = 1.f / s;
    long long ob = r * (long long)NT;
#pragma unroll
    for (int jj = 0; jj < 4; jj++)
        g_at_hi[ob + tid + jj * 256] = __float2half_rn(e[jj] * inv);
}

// ---------------- host launcher ----------------------------------------------
extern "C" void kernel_launch(void* const* d_in, const int* in_sizes, int n_in,
                              void* d_out, int out_size) {
    const float* q     = (const float*)d_in[0];
    const float* k     = (const float*)d_in[1];
    const float* v     = (const float*)d_in[2];
    const float* tsp   = (const float*)d_in[3];
    const int*   supp  = (const int*)  d_in[4];
    const float* w_qk  = (const float*)d_in[5];
    const float* dummy = (const float*)d_in[6];
    const float* w1    = (const float*)d_in[7];
    const float* b1    = (const float*)d_in[8];
    const float* w2    = (const float*)d_in[9];
    const float* b2    = (const float*)d_in[10];
    const float* w3    = (const float*)d_in[11];
    const float* b3    = (const float*)d_in[12];
    float* outp = (float*)d_out;
    float* tsp_outp = outp + (long long)NB * NLQ * ND;

    cudaFuncSetAttribute(gemm_fp16_kernel,
                         cudaFuncAttributeMaxDynamicSharedMemorySize, SMEM_BYTES);

    half *xcat_hi, *k_hi, *wT_hi, *wT_lo, *G_hi, *G_lo;
    half *w1_hi, *w1_lo, *w2_hi, *w2_lo, *w3_hi, *w3_lo;
    half *U_hi, *U_lo;
    half *vT_hi, *tT_hi, *at_hi, *x1_hi, *x2_hi;
    float *attn;
    cudaGetSymbolAddress((void**)&xcat_hi, g_xcat_hi);
    cudaGetSymbolAddress((void**)&k_hi, g_k_hi);
    cudaGetSymbolAddress((void**)&wT_hi, g_wT_hi);
    cudaGetSymbolAddress((void**)&wT_lo, g_wT_lo);
    cudaGetSymbolAddress((void**)&G_hi, g_G_hi);
    cudaGetSymbolAddress((void**)&G_lo, g_G_lo);
    cudaGetSymbolAddress((void**)&w1_hi, g_w1_hi);
    cudaGetSymbolAddress((void**)&w1_lo, g_w1_lo);
    cudaGetSymbolAddress((void**)&w2_hi, g_w2_hi);
    cudaGetSymbolAddress((void**)&w2_lo, g_w2_lo);
    cudaGetSymbolAddress((void**)&w3_hi, g_w3_hi);
    cudaGetSymbolAddress((void**)&w3_lo, g_w3_lo);
    cudaGetSymbolAddress((void**)&U_hi, g_U_hi);
    cudaGetSymbolAddress((void**)&U_lo, g_U_lo);
    cudaGetSymbolAddress((void**)&vT_hi, g_vT_hi);
    cudaGetSymbolAddress((void**)&tT_hi, g_tT_hi);
    cudaGetSymbolAddress((void**)&at_hi, g_at_hi);
    cudaGetSymbolAddress((void**)&x1_hi, g_x1_hi);
    cudaGetSymbolAddress((void**)&x2_hi, g_x2_hi);
    cudaGetSymbolAddress((void**)&attn, g_attn);

    // 1) pos/mask + w~ = W^T dummy
    pos_kernel<<<1, 1024>>>(supp);
    wtilde_kernel<<<4, 256>>>(w_qk, dummy);

    // 2) conversions
    conv_kernel<<<32768, 256>>>(q, xcat_hi + 1024, (half*)0, 256, 2048);
    conv_kernel<<<32768, 256>>>(k, k_hi, (half*)0, 256, 1024);
    conv_kernel<<<512, 256>>>(w1, w1_hi, w1_lo, 256, 1024);
    conv_kernel<<<512, 256>>>(w2, w2_hi, w2_lo, 256, 1024);
    conv_kernel<<<2048, 256>>>(w3, w3_hi, w3_lo, 512, 2048);

    // 3) W^T (hi+lo) via transpose; then G = W^T W (hi+lo out)
    transpose_conv_kernel<<<dim3(16, 16, 1), 256>>>(w_qk, wT_hi, wT_lo, 0);
    gemm_fp16_kernel<<<dim3(8, 8, 1), 256, SMEM_BYTES>>>(
        wT_hi, 1024, 0, wT_hi, wT_lo, 1024, 0,
        (float*)0, G_hi, G_lo, (half*)0, (half*)0, (const float*)0,
        1024, 0, 0, 1024, (const float*)0, 0, 2);

    // 4) U = k @ G  (hi+lo out, flat 32768 rows)
    gemm_fp16_kernel<<<dim3(8, 256, 1), 256, SMEM_BYTES>>>(
        k_hi, 1024, 0, G_hi, G_lo, 1024, 0,
        (float*)0, U_hi, U_lo, (half*)0, (half*)0, (const float*)0,
        1024, 0, 0, 1024, (const float*)0, 0, 2);

    // 5) build vT (gathered) / tT — hi only
    transpose_conv_kernel<<<dim3(16, 16, NB), 256>>>(v, vT_hi, (half*)0, 1);
    transpose_conv_kernel<<<dim3(16, 16, NB), 256>>>(tsp, tT_hi, (half*)0, 0);

    // 6) scores = q @ U^T  (fp32, batched; A = q_hi inside xcat, lda 2048)
    gemm_fp16_kernel<<<dim3(8, 8, NB), 256, SMEM_BYTES>>>(
        xcat_hi + 1024, 2048, (long long)NLQ * 2048,
        U_hi, U_lo, 1024, (long long)NT * ND,
        attn, (half*)0, (half*)0, (half*)0, (half*)0, (const float*)0,
        1024, (long long)NLQ * NT, 0, 1024, (const float*)0, 0, 0);

    // 7) softmax (gather + exact fp32 dummy column) -> attn fp16
    softmax_kernel<<<NB * NLQ, 256>>>(q);

    // 8) out = attn @ v_sel (hi-only B), fused x1 = out*q, x2 = q-out
    gemm_fp16_kernel<<<dim3(8, 8, NB), 256, SMEM_BYTES>>>(
        at_hi, 1024, (long long)NLQ * ND, vT_hi, (half*)0, 1024, (long long)ND * NT,
        (float*)0, (half*)0, (half*)0, x1_hi, x2_hi, q,
        1024, (long long)NLQ * ND, 0, 1024, (const float*)0, 0, 3);

    // 9) tsp_out = attn @ tsp (hi-only B) -> second output (fp32)
    gemm_fp16_kernel<<<dim3(8, 8, NB), 256, SMEM_BYTES>>>(
        at_hi, 1024, (long long)NLQ * ND, tT_hi, (half*)0, 1024, (long long)ND * NT,
        tsp_outp, (half*)0, (half*)0, (half*)0, (half*)0, (const float*)0,
        1024, (long long)NLQ * ND, 0, 1024, (const float*)0, 0, 0);

    // 10) o1 = relu(x1 @ w1^T + b1) -> xcat[:, 0:512] (hi)
    gemm_fp16_kernel<<<dim3(4, 256, 1), 256, SMEM_BYTES>>>(
        x1_hi, 1024, 0, w1_hi, w1_lo, 1024, 0,
        (float*)0, xcat_hi, (half*)0, (half*)0, (half*)0, (const float*)0,
        2048, 0, 0, 1024, b1, 1, 1);

    // 11) o2 = relu(x2 @ w2^T + b2) -> xcat[:, 512:1024] (hi)
    gemm_fp16_kernel<<<dim3(4, 256, 1), 256, SMEM_BYTES>>>(
        x2_hi, 1024, 0, w2_hi, w2_lo, 1024, 0,
        (float*)0, xcat_hi, (half*)0, (half*)0, (half*)0, (const float*)0,
        2048, 0, 512, 1024, b2, 1, 1);

    // 12) output = xcat @ w3^T + b3 -> first output (fp32)
    gemm_fp16_kernel<<<dim3(8, 256, 1), 256, SMEM_BYTES>>>(
        xcat_hi, 2048, 0, w3_hi, w3_lo, 2048, 0,
        outp, (half*)0, (half*)0, (half*)0, (half*)0, (const float*)0,
        1024, 0, 0, 2048, b3, 0, 0);
}

// round 16
// speedup vs baseline: 5.0324x; 1.0567x over previous
#include <cuda_runtime.h>
#include <cuda_fp16.h>
#include <stdint.h>

#define DUMMY_CLASS 100
#define NB   32
#define NLQ  1024
#define NT   1024
#define ND   1024

// ---------------- scratch (device globals; no allocation allowed) ------------
__device__ __align__(16) half g_xcat_hi[67108864];  // (B*LQ, 2048): [o1|o2|q]
__device__ __align__(16) half g_k_hi  [33554432];
__device__ __align__(16) half g_wT_hi [1048576];    // W^T (transposed w_qk)
__device__ __align__(16) half g_wT_lo [1048576];
__device__ __align__(16) half g_G_hi  [1048576];    // G = W^T W
__device__ __align__(16) half g_G_lo  [1048576];
__device__ __align__(16) half g_w1_hi [524288];
__device__ __align__(16) half g_w1_lo [524288];
__device__ __align__(16) half g_w2_hi [524288];
__device__ __align__(16) half g_w2_lo [524288];
__device__ __align__(16) half g_w3_hi [2097152];
__device__ __align__(16) half g_U_hi  [33554432];   // U = k @ G
__device__ __align__(16) half g_vT_hi [33554432];
__device__ __align__(16) half g_tT_hi [33554432];
__device__ float g_attn[33554432];                   // 32*1024*1024 scores
__device__ __align__(16) half g_at_hi [33554432];
__device__ __align__(16) half g_x1_hi [33554432];
__device__ __align__(16) half g_x2_hi [33554432];
__device__ float g_wtilde[1024];                     // W^T @ dummy
__device__ int g_pos [1024];
__device__ int g_mask[1024];

// ---------------- helpers ----------------------------------------------------
__device__ __forceinline__ uint32_t smem_u32(const void* p) {
    uint32_t a;
    asm("{ .reg .u64 t; cvta.to.shared.u64 t, %1; cvt.u32.u64 %0, t; }"
        : "=r"(a) : "l"(p));
    return a;
}
__device__ __forceinline__ void cp16(uint32_t dst, const void* src) {
    asm volatile("cp.async.cg.shared.global [%0], [%1], 16;"
                 :: "r"(dst), "l"(src) : "memory");
}
__device__ __forceinline__ void cp_commit() {
    asm volatile("cp.async.commit_group;" ::: "memory");
}
__device__ __forceinline__ void ldm4(uint32_t* r, uint32_t addr) {
    asm volatile("ldmatrix.sync.aligned.m8n8.x4.shared.b16 {%0,%1,%2,%3}, [%4];"
                 : "=r"(r[0]), "=r"(r[1]), "=r"(r[2]), "=r"(r[3]) : "r"(addr));
}
__device__ __forceinline__ void mma16816(float* c, const uint32_t* a, const uint32_t* b) {
    asm volatile("mma.sync.aligned.m16n8k16.row.col.f32.f16.f16.f32 "
                 "{%0,%1,%2,%3}, {%4,%5,%6,%7}, {%8,%9}, {%0,%1,%2,%3};"
                 : "+f"(c[0]), "+f"(c[1]), "+f"(c[2]), "+f"(c[3])
                 : "r"(a[0]), "r"(a[1]), "r"(a[2]), "r"(a[3]), "r"(b[0]), "r"(b[1]));
}
__device__ __forceinline__ void hilo(float v, half& h, half& l) {
    h = __float2half_rn(v);
    l = __float2half_rn(v - __half2float(h));
}
__device__ __forceinline__ uint32_t pack2(half a, half b) {
    return (uint32_t)__half_as_ushort(a) | ((uint32_t)__half_as_ushort(b) << 16);
}

// ---------------- pos / mask scan --------------------------------------------
__global__ void pos_kernel(const int* __restrict__ supp) {
    __shared__ int s[1024];
    int t = threadIdx.x;
    int m = (supp[t] != DUMMY_CLASS) ? 1 : 0;
    g_mask[t] = m;
    s[t] = m;
    __syncthreads();
    for (int off = 1; off < 1024; off <<= 1) {
        int v = (t >= off) ? s[t - off] : 0;
        __syncthreads();
        s[t] += v;
        __syncthreads();
    }
    int p = s[t] - 1;
    g_pos[t] = p < 0 ? 0 : p;
}

// ---------------- w~ = W^T @ dummy (fp32) -------------------------------------
__global__ void wtilde_kernel(const float* __restrict__ wqk,
                              const float* __restrict__ dummy) {
    int i = blockIdx.x * 256 + threadIdx.x;   // 0..1023
    float s = 0.f;
    for (int k2 = 0; k2 < 1024; k2++)
        s += wqk[k2 * 1024 + i] * dummy[k2];
    g_wtilde[i] = s;
}

// ---------------- fp32 -> fp16 hi(/lo) conversion ----------------------------
__global__ void conv_kernel(const float* __restrict__ src,
                            half* __restrict__ hi, half* __restrict__ lo,
                            int cols4, int lddst) {
    int i4 = blockIdx.x * 256 + threadIdx.x;
    float4 v = ((const float4*)src)[i4];
    long long row = i4 / cols4;
    int c4 = i4 % cols4;
    long long o = row * (long long)lddst + (long long)c4 * 4;
    half h0, h1, h2, h3, l0, l1, l2, l3;
    hilo(v.x, h0, l0); hilo(v.y, h1, l1); hilo(v.z, h2, l2); hilo(v.w, h3, l3);
    uint2 uh; uh.x = pack2(h0, h1); uh.y = pack2(h2, h3);
    *(uint2*)(hi + o) = uh;
    if (lo) {
        uint2 ul; ul.x = pack2(l0, l1); ul.y = pack2(l2, l3);
        *(uint2*)(lo + o) = ul;
    }
}

// ---------------- transpose + convert (optionally gathered, lo optional) -----
__global__ void transpose_conv_kernel(const float* __restrict__ src,
                                      half* __restrict__ dhi, half* __restrict__ dlo,
                                      int gathered) {
    __shared__ float tile[64][65];
    int b = blockIdx.z;
    int t0 = blockIdx.y * 64;
    int d0 = blockIdx.x * 64;
    int tid = threadIdx.x;
#pragma unroll
    for (int j = 0; j < 4; j++) {
        int i = tid + j * 256;
        int r = i >> 4;
        int c4 = i & 15;
        int tg = t0 + r;
        int srow = tg;
        bool z = false;
        if (gathered) { z = (g_mask[tg] == 0); srow = g_pos[tg]; }
        float4 v = z ? make_float4(0.f, 0.f, 0.f, 0.f)
                     : ((const float4*)src)[((long long)b * NT + srow) * 256 + (d0 >> 2) + c4];
        tile[r][c4 * 4 + 0] = v.x; tile[r][c4 * 4 + 1] = v.y;
        tile[r][c4 * 4 + 2] = v.z; tile[r][c4 * 4 + 3] = v.w;
    }
    __syncthreads();
#pragma unroll
    for (int j = 0; j < 4; j++) {
        int i = tid + j * 256;
        int r = i >> 4;
        int c4 = i & 15;
        half h[4], l[4];
#pragma unroll
        for (int e = 0; e < 4; e++) hilo(tile[c4 * 4 + e][r], h[e], l[e]);
        long long o = ((long long)b * ND + d0 + r) * (long long)NT + t0 + c4 * 4;
        uint2 uh; uh.x = pack2(h[0], h[1]); uh.y = pack2(h[2], h[3]);
        *(uint2*)(dhi + o) = uh;
        if (dlo) {
            uint2 ul; ul.x = pack2(l[0], l[1]); ul.y = pack2(l[2], l[3]);
            *(uint2*)(dlo + o) = ul;
        }
    }
}

// ---------------- split-fp16 HMMA GEMM (NT): C = Ah*(Bh[+Bl])^T --------------
// CTA tile 128x128, 8 warps (2m x 4n), warp tile 64x32, K-chunk 64,
// 2-stage cp.async double buffer, 96 KB smem -> 2 CTAs/SM.
// Blo == nullptr -> hi-only B (half the MMA work).
// mode: 0 = fp32 C (+bias), 1 = fp16-hi C (+bias+relu), 2 = fp16 hi+lo C,
//       3 = fused: out -> X1=out*q, X2=q-out (fp16 hi).
#define KC      64
#define STAGES  2
#define OFF_AH  0
#define OFF_BH  16384
#define OFF_BL  32768
#define STAGE_B 49152
#define SMEM_BYTES (STAGES * STAGE_B)

__global__ void __launch_bounds__(256, 2) gemm_fp16_kernel(
    const half* __restrict__ Ahi, int lda, long long sA,
    const half* __restrict__ Bhi, const half* __restrict__ Blo, int ldb, long long sB,
    float* __restrict__ Cf, half* __restrict__ Chi, half* __restrict__ Clo,
    half* __restrict__ X1, half* __restrict__ X2, const float* __restrict__ qsrc,
    int ldc, long long sC, int coloff,
    int K, const float* __restrict__ bias, int relu, int mode)
{
    extern __shared__ __align__(1024) char smem[];
    const uint32_t sb = smem_u32(smem);
    const int tid = threadIdx.x;
    const int wid = tid >> 5;
    const int l   = tid & 31;
    const bool has_lo = (Blo != nullptr);

    const long long bz = blockIdx.z;
    const half* pAh = Ahi + bz * sA + (long long)(blockIdx.y * 128) * lda;
    const half* pBh = Bhi + bz * sB + (long long)(blockIdx.x * 128) * ldb;
    const half* pBl = has_lo ? Blo + bz * sB + (long long)(blockIdx.x * 128) * ldb : pBh;
    const int S = K / KC;

    // loaders: 2 threads per row, 4 x 16B chunks each (128 rows)
    const int crow = tid >> 1;
    const int cc0  = (tid & 1) << 2;

    auto load_stage = [&](int s) {
        uint32_t bp = sb + (s & 1) * STAGE_B;
        long long k0 = (long long)s * KC;
        const half* rA = pAh + (long long)crow * lda + k0;
        const half* rBh = pBh + (long long)crow * ldb + k0;
        const half* rBl = pBl + (long long)crow * ldb + k0;
        uint32_t rowo = (uint32_t)crow * 128;
        uint32_t x = (uint32_t)(crow & 7) << 4;
#pragma unroll
        for (int j = 0; j < 4; j++) {
            int c = cc0 + j;
            uint32_t o = rowo + (((uint32_t)c << 4) ^ x);
            cp16(bp + OFF_AH + o, rA + c * 8);
            cp16(bp + OFF_BH + o, rBh + c * 8);
            if (has_lo) cp16(bp + OFF_BL + o, rBl + c * 8);
        }
    };

    load_stage(0); cp_commit();

    const int wm = wid & 1;          // 0..1 -> 64-row half
    const int wn = wid >> 1;         // 0..3 -> 32-col quarter
    const int arow = wm * 64 + (l & 15);
    const uint32_t aco = ((uint32_t)(l >> 4) << 4);
    const uint32_t axor = (uint32_t)(arow & 7) << 4;
    const int brow = wn * 32 + (l & 7) + ((l >> 4) << 3);
    const uint32_t bco = ((uint32_t)((l >> 3) & 1) << 4);
    const uint32_t bxor = (uint32_t)(brow & 7) << 4;

    float acc[4][4][4];
#pragma unroll
    for (int mf = 0; mf < 4; mf++)
#pragma unroll
        for (int nf = 0; nf < 4; nf++)
#pragma unroll
            for (int e = 0; e < 4; e++) acc[mf][nf][e] = 0.f;

    for (int s = 0; s < S; s++) {
        // prefetch next stage into the OTHER buffer (safe: compute(s-1) done)
        if (s + 1 < S) { load_stage(s + 1); cp_commit(); }
        if (s + 1 < S) asm volatile("cp.async.wait_group 1;" ::: "memory");
        else           asm volatile("cp.async.wait_group 0;" ::: "memory");
        __syncthreads();

        uint32_t bp = sb + (s & 1) * STAGE_B;
        uint32_t aBase = bp + OFF_AH + (uint32_t)arow * 128;
        uint32_t bBaseH = bp + OFF_BH + (uint32_t)brow * 128;
        uint32_t bBaseL = bp + OFF_BL + (uint32_t)brow * 128;

#pragma unroll
        for (int k16 = 0; k16 < KC / 16; k16++) {
            uint32_t ak = (((uint32_t)k16 << 5) + aco) ^ axor;
            uint32_t bk = (((uint32_t)k16 << 5) + bco) ^ bxor;
            uint32_t ah[4][4], bh[4][2], bl[4][2];
#pragma unroll
            for (int mf = 0; mf < 4; mf++)
                ldm4(ah[mf], aBase + (uint32_t)(mf * 16) * 128 + ak);
#pragma unroll
            for (int g = 0; g < 2; g++) {
                uint32_t r[4];
                ldm4(r, bBaseH + (uint32_t)(g * 16) * 128 + bk);
                bh[g*2][0] = r[0]; bh[g*2][1] = r[1];
                bh[g*2+1][0] = r[2]; bh[g*2+1][1] = r[3];
                if (has_lo) {
                    ldm4(r, bBaseL + (uint32_t)(g * 16) * 128 + bk);
                    bl[g*2][0] = r[0]; bl[g*2][1] = r[1];
                    bl[g*2+1][0] = r[2]; bl[g*2+1][1] = r[3];
                }
            }
#pragma unroll
            for (int mf = 0; mf < 4; mf++)
#pragma unroll
                for (int nf = 0; nf < 4; nf++) {
                    mma16816(acc[mf][nf], ah[mf], bh[nf]);
                    if (has_lo) mma16816(acc[mf][nf], ah[mf], bl[nf]);
                }
        }
        __syncthreads();   // compute(s) done before next iter overwrites buf s&1
    }

    // ---- epilogue -----------------------------------------------------------
    const int gi0 = blockIdx.y * 128 + wm * 64 + (l >> 2);
    const int gj0 = blockIdx.x * 128 + wn * 32 + 2 * (l & 3);
#pragma unroll
    for (int mf = 0; mf < 4; mf++) {
        int gi = gi0 + mf * 16;
#pragma unroll
        for (int nf = 0; nf < 4; nf++) {
            int gj = gj0 + nf * 8;
            float v0 = acc[mf][nf][0], v1 = acc[mf][nf][1];
            float v2 = acc[mf][nf][2], v3 = acc[mf][nf][3];
            if (bias) {
                float b0 = bias[gj], b1 = bias[gj + 1];
                v0 += b0; v1 += b1; v2 += b0; v3 += b1;
            }
            if (relu) {
                v0 = fmaxf(v0, 0.f); v1 = fmaxf(v1, 0.f);
                v2 = fmaxf(v2, 0.f); v3 = fmaxf(v3, 0.f);
            }
            long long o0 = bz * sC + (long long)gi * ldc + coloff + gj;
            long long o1 = o0 + (long long)8 * ldc;
            if (mode == 0) {
                *(float2*)(Cf + o0) = make_float2(v0, v1);
                *(float2*)(Cf + o1) = make_float2(v2, v3);
            } else if (mode == 1) {
                *(uint32_t*)(Chi + o0) = pack2(__float2half_rn(v0), __float2half_rn(v1));
                *(uint32_t*)(Chi + o1) = pack2(__float2half_rn(v2), __float2half_rn(v3));
            } else if (mode == 2) {
                half h0, h1, h2, h3, l0, l1, l2, l3;
                hilo(v0, h0, l0); hilo(v1, h1, l1);
                hilo(v2, h2, l2); hilo(v3, h3, l3);
                *(uint32_t*)(Chi + o0) = pack2(h0, h1);
                *(uint32_t*)(Clo + o0) = pack2(l0, l1);
                *(uint32_t*)(Chi + o1) = pack2(h2, h3);
                *(uint32_t*)(Clo + o1) = pack2(l2, l3);
            } else {
                float2 q0 = *(const float2*)(qsrc + o0);
                float2 q1 = *(const float2*)(qsrc + o1);
                *(uint32_t*)(X1 + o0) = pack2(__float2half_rn(v0 * q0.x),
                                              __float2half_rn(v1 * q0.y));
                *(uint32_t*)(X1 + o1) = pack2(__float2half_rn(v2 * q1.x),
                                              __float2half_rn(v3 * q1.y));
                *(uint32_t*)(X2 + o0) = pack2(__float2half_rn(q0.x - v0),
                                              __float2half_rn(q0.y - v1));
                *(uint32_t*)(X2 + o1) = pack2(__float2half_rn(q1.x - v2),
                                              __float2half_rn(q1.y - v3));
            }
        }
    }
}

// ---------------- softmax with in-kernel gather + dummy column ---------------
// sdum = q_row . wtilde  (fp32, exact), vals[t] = mask[t] ? s[pos[t]] : sdum.
__global__ void softmax_kernel(const float* __restrict__ q) {
    const long long r = blockIdx.x;
    const float* srow = g_attn + r * 1024;
    const float* qrow = q + r * 1024;
    const int tid = threadIdx.x;
    __shared__ float sred[8];
    __shared__ float sbc;

    float sd = 0.f;
    for (int j4 = tid; j4 < 256; j4 += 256) {
        float4 qv = ((const float4*)qrow)[j4];
        float4 wv = ((const float4*)g_wtilde)[j4];
        sd += qv.x * wv.x + qv.y * wv.y + qv.z * wv.z + qv.w * wv.w;
    }
#pragma unroll
    for (int o = 16; o; o >>= 1) sd += __shfl_xor_sync(0xffffffffu, sd, o);
    if ((tid & 31) == 0) sred[tid >> 5] = sd;
    __syncthreads();
    if (tid == 0) {
        float t = 0.f;
#pragma unroll
        for (int i = 0; i < 8; i++) t += sred[i];
        sbc = t;
    }
    __syncthreads();
    const float sdum = sbc;

    float val[4];
    float lm = sdum;
#pragma unroll
    for (int jj = 0; jj < 4; jj++) {
        int j = tid + jj * 256;
        val[jj] = g_mask[j] ? srow[g_pos[j]] : sdum;
        lm = fmaxf(lm, val[jj]);
    }
#pragma unroll
    for (int o = 16; o; o >>= 1) lm = fmaxf(lm, __shfl_xor_sync(0xffffffffu, lm, o));
    if ((tid & 31) == 0) sred[tid >> 5] = lm;
    __syncthreads();
    float m = sred[0];
#pragma unroll
    for (int i = 1; i < 8; i++) m = fmaxf(m, sred[i]);

    const float invT = 0.03125f;
    float e[4];
    float ls = (tid == 0) ? __expf((sdum - m) * invT) : 0.f;
#pragma unroll
    for (int jj = 0; jj < 4; jj++) {
        e[jj] = __expf((val[jj] - m) * invT);
        ls += e[jj];
    }
#pragma unroll
    for (int o = 16; o; o >>= 1) ls += __shfl_xor_sync(0xffffffffu, ls, o);
    if ((tid & 31) == 0) sred[tid >> 5] = ls;
    __syncthreads();
    float s = 0.f;
#pragma unroll
    for (int i = 0; i < 8; i++) s += sred[i];
    float inv = 1.f / s;
    long long ob = r * (long long)NT;
#pragma unroll
    for (int jj = 0; jj < 4; jj++)
        g_at_hi[ob + tid + jj * 256] = __float2half_rn(e[jj] * inv);
}

// ---------------- host launcher ----------------------------------------------
extern "C" void kernel_launch(void* const* d_in, const int* in_sizes, int n_in,
                              void* d_out, int out_size) {
    const float* q     = (const float*)d_in[0];
    const float* k     = (const float*)d_in[1];
    const float* v     = (const float*)d_in[2];
    const float* tsp   = (const float*)d_in[3];
    const int*   supp  = (const int*)  d_in[4];
    const float* w_qk  = (const float*)d_in[5];
    const float* dummy = (const float*)d_in[6];
    const float* w1    = (const float*)d_in[7];
    const float* b1    = (const float*)d_in[8];
    const float* w2    = (const float*)d_in[9];
    const float* b2    = (const float*)d_in[10];
    const float* w3    = (const float*)d_in[11];
    const float* b3    = (const float*)d_in[12];
    float* outp = (float*)d_out;
    float* tsp_outp = outp + (long long)NB * NLQ * ND;

    cudaFuncSetAttribute(gemm_fp16_kernel,
                         cudaFuncAttributeMaxDynamicSharedMemorySize, SMEM_BYTES);

    half *xcat_hi, *k_hi, *wT_hi, *wT_lo, *G_hi, *G_lo;
    half *w1_hi, *w1_lo, *w2_hi, *w2_lo, *w3_hi;
    half *U_hi;
    half *vT_hi, *tT_hi, *at_hi, *x1_hi, *x2_hi;
    float *attn;
    cudaGetSymbolAddress((void**)&xcat_hi, g_xcat_hi);
    cudaGetSymbolAddress((void**)&k_hi, g_k_hi);
    cudaGetSymbolAddress((void**)&wT_hi, g_wT_hi);
    cudaGetSymbolAddress((void**)&wT_lo, g_wT_lo);
    cudaGetSymbolAddress((void**)&G_hi, g_G_hi);
    cudaGetSymbolAddress((void**)&G_lo, g_G_lo);
    cudaGetSymbolAddress((void**)&w1_hi, g_w1_hi);
    cudaGetSymbolAddress((void**)&w1_lo, g_w1_lo);
    cudaGetSymbolAddress((void**)&w2_hi, g_w2_hi);
    cudaGetSymbolAddress((void**)&w2_lo, g_w2_lo);
    cudaGetSymbolAddress((void**)&w3_hi, g_w3_hi);
    cudaGetSymbolAddress((void**)&U_hi, g_U_hi);
    cudaGetSymbolAddress((void**)&vT_hi, g_vT_hi);
    cudaGetSymbolAddress((void**)&tT_hi, g_tT_hi);
    cudaGetSymbolAddress((void**)&at_hi, g_at_hi);
    cudaGetSymbolAddress((void**)&x1_hi, g_x1_hi);
    cudaGetSymbolAddress((void**)&x2_hi, g_x2_hi);
    cudaGetSymbolAddress((void**)&attn, g_attn);

    // 1) pos/mask + w~ = W^T dummy
    pos_kernel<<<1, 1024>>>(supp);
    wtilde_kernel<<<4, 256>>>(w_qk, dummy);

    // 2) conversions
    conv_kernel<<<32768, 256>>>(q, xcat_hi + 1024, (half*)0, 256, 2048);
    conv_kernel<<<32768, 256>>>(k, k_hi, (half*)0, 256, 1024);
    conv_kernel<<<512, 256>>>(w1, w1_hi, w1_lo, 256, 1024);
    conv_kernel<<<512, 256>>>(w2, w2_hi, w2_lo, 256, 1024);
    conv_kernel<<<2048, 256>>>(w3, w3_hi, (half*)0, 512, 2048);

    // 3) W^T (hi+lo) via transpose; then G = W^T W (hi+lo out)
    transpose_conv_kernel<<<dim3(16, 16, 1), 256>>>(w_qk, wT_hi, wT_lo, 0);
    gemm_fp16_kernel<<<dim3(8, 8, 1), 256, SMEM_BYTES>>>(
        wT_hi, 1024, 0, wT_hi, wT_lo, 1024, 0,
        (float*)0, G_hi, G_lo, (half*)0, (half*)0, (const float*)0,
        1024, 0, 0, 1024, (const float*)0, 0, 2);

    // 4) U = k @ G  (hi out; B keeps G hi+lo for accuracy)
    gemm_fp16_kernel<<<dim3(8, 256, 1), 256, SMEM_BYTES>>>(
        k_hi, 1024, 0, G_hi, G_lo, 1024, 0,
        (float*)0, U_hi, (half*)0, (half*)0, (half*)0, (const float*)0,
        1024, 0, 0, 1024, (const float*)0, 0, 1);

    // 5) build vT (gathered) / tT — hi only
    transpose_conv_kernel<<<dim3(16, 16, NB), 256>>>(v, vT_hi, (half*)0, 1);
    transpose_conv_kernel<<<dim3(16, 16, NB), 256>>>(tsp, tT_hi, (half*)0, 0);

    // 6) scores = q @ U^T  (fp32, batched; B hi-only now)
    gemm_fp16_kernel<<<dim3(8, 8, NB), 256, SMEM_BYTES>>>(
        xcat_hi + 1024, 2048, (long long)NLQ * 2048,
        U_hi, (half*)0, 1024, (long long)NT * ND,
        attn, (half*)0, (half*)0, (half*)0, (half*)0, (const float*)0,
        1024, (long long)NLQ * NT, 0, 1024, (const float*)0, 0, 0);

    // 7) softmax (gather + exact fp32 dummy column) -> attn fp16
    softmax_kernel<<<NB * NLQ, 256>>>(q);

    // 8) out = attn @ v_sel (hi-only B), fused x1 = out*q, x2 = q-out
    gemm_fp16_kernel<<<dim3(8, 8, NB), 256, SMEM_BYTES>>>(
        at_hi, 1024, (long long)NLQ * ND, vT_hi, (half*)0, 1024, (long long)ND * NT,
        (float*)0, (half*)0, (half*)0, x1_hi, x2_hi, q,
        1024, (long long)NLQ * ND, 0, 1024, (const float*)0, 0, 3);

    // 9) tsp_out = attn @ tsp (hi-only B) -> second output (fp32)
    gemm_fp16_kernel<<<dim3(8, 8, NB), 256, SMEM_BYTES>>>(
        at_hi, 1024, (long long)NLQ * ND, tT_hi, (half*)0, 1024, (long long)ND * NT,
        tsp_outp, (half*)0, (half*)0, (half*)0, (half*)0, (const float*)0,
        1024, (long long)NLQ * ND, 0, 1024, (const float*)0, 0, 0);

    // 10) o1 = relu(x1 @ w1^T + b1) -> xcat[:, 0:512] (hi; w1 keeps lo)
    gemm_fp16_kernel<<<dim3(4, 256, 1), 256, SMEM_BYTES>>>(
        x1_hi, 1024, 0, w1_hi, w1_lo, 1024, 0,
        (float*)0, xcat_hi, (half*)0, (half*)0, (half*)0, (const float*)0,
        2048, 0, 0, 1024, b1, 1, 1);

    // 11) o2 = relu(x2 @ w2^T + b2) -> xcat[:, 512:1024] (hi; w2 keeps lo)
    gemm_fp16_kernel<<<dim3(4, 256, 1), 256, SMEM_BYTES>>>(
        x2_hi, 1024, 0, w2_hi, w2_lo, 1024, 0,
        (float*)0, xcat_hi, (half*)0, (half*)0, (half*)0, (const float*)0,
        2048, 0, 512, 1024, b2, 1, 1);

    // 12) output = xcat @ w3^T + b3 -> first output (fp32; w3 hi-only now)
    gemm_fp16_kernel<<<dim3(8, 256, 1), 256, SMEM_BYTES>>>(
        xcat_hi, 2048, 0, w3_hi, (half*)0, 2048, 0,
        outp, (half*)0, (half*)0, (half*)0, (half*)0, (const float*)0,
        1024, 0, 0, 2048, b3, 0, 0);
}

// round 17
// speedup vs baseline: 6.0598x; 1.2041x over previous
#include <cuda_runtime.h>
#include <cuda_fp16.h>
#include <stdint.h>

#define DUMMY_CLASS 100
#define NB   32
#define NLQ  1024
#define NT   1024
#define ND   1024

// ---------------- scratch (device globals; no allocation allowed) ------------
__device__ __align__(16) half g_xcat_hi[67108864];  // (B*LQ, 2048): [o1|o2|q]
__device__ __align__(16) half g_k_hi  [33554432];
__device__ __align__(16) half g_wT_hi [1048576];    // W^T (transposed w_qk)
__device__ __align__(16) half g_wT_lo [1048576];
__device__ __align__(16) half g_G_hi  [1048576];    // G = W^T W
__device__ __align__(16) half g_G_lo  [1048576];
__device__ __align__(16) half g_w1_hi [524288];
__device__ __align__(16) half g_w1_lo [524288];
__device__ __align__(16) half g_w2_hi [524288];
__device__ __align__(16) half g_w2_lo [524288];
__device__ __align__(16) half g_w3_hi [2097152];
__device__ __align__(16) half g_U_hi  [33554432];   // U = k @ G
__device__ __align__(16) half g_vT_hi [33554432];
__device__ __align__(16) half g_tT_hi [33554432];
__device__ float g_attn[33554432];                   // 32*1024*1024 scores
__device__ __align__(16) half g_at_hi [33554432];
__device__ __align__(16) half g_x1_hi [33554432];
__device__ __align__(16) half g_x2_hi [33554432];
__device__ float g_wtilde[1024];                     // W^T @ dummy
__device__ int g_pos [1024];
__device__ int g_mask[1024];

// ---------------- helpers ----------------------------------------------------
__device__ __forceinline__ uint32_t smem_u32(const void* p) {
    uint32_t a;
    asm("{ .reg .u64 t; cvta.to.shared.u64 t, %1; cvt.u32.u64 %0, t; }"
        : "=r"(a) : "l"(p));
    return a;
}
__device__ __forceinline__ void cp16(uint32_t dst, const void* src) {
    asm volatile("cp.async.cg.shared.global [%0], [%1], 16;"
                 :: "r"(dst), "l"(src) : "memory");
}
__device__ __forceinline__ void cp_commit() {
    asm volatile("cp.async.commit_group;" ::: "memory");
}
__device__ __forceinline__ void ldm4(uint32_t* r, uint32_t addr) {
    asm volatile("ldmatrix.sync.aligned.m8n8.x4.shared.b16 {%0,%1,%2,%3}, [%4];"
                 : "=r"(r[0]), "=r"(r[1]), "=r"(r[2]), "=r"(r[3]) : "r"(addr));
}
__device__ __forceinline__ void mma16816(float* c, const uint32_t* a, const uint32_t* b) {
    asm volatile("mma.sync.aligned.m16n8k16.row.col.f32.f16.f16.f32 "
                 "{%0,%1,%2,%3}, {%4,%5,%6,%7}, {%8,%9}, {%0,%1,%2,%3};"
                 : "+f"(c[0]), "+f"(c[1]), "+f"(c[2]), "+f"(c[3])
                 : "r"(a[0]), "r"(a[1]), "r"(a[2]), "r"(a[3]), "r"(b[0]), "r"(b[1]));
}
__device__ __forceinline__ void hilo(float v, half& h, half& l) {
    h = __float2half_rn(v);
    l = __float2half_rn(v - __half2float(h));
}
__device__ __forceinline__ uint32_t pack2(half a, half b) {
    return (uint32_t)__half_as_ushort(a) | ((uint32_t)__half_as_ushort(b) << 16);
}

// ---------------- pos / mask scan --------------------------------------------
__global__ void pos_kernel(const int* __restrict__ supp) {
    __shared__ int s[1024];
    int t = threadIdx.x;
    int m = (supp[t] != DUMMY_CLASS) ? 1 : 0;
    g_mask[t] = m;
    s[t] = m;
    __syncthreads();
    for (int off = 1; off < 1024; off <<= 1) {
        int v = (t >= off) ? s[t - off] : 0;
        __syncthreads();
        s[t] += v;
        __syncthreads();
    }
    int p = s[t] - 1;
    g_pos[t] = p < 0 ? 0 : p;
}

// ---------------- w~ = W^T @ dummy (fp32) -------------------------------------
__global__ void wtilde_kernel(const float* __restrict__ wqk,
                              const float* __restrict__ dummy) {
    int i = blockIdx.x * 256 + threadIdx.x;   // 0..1023
    float s = 0.f;
    for (int k2 = 0; k2 < 1024; k2++)
        s += wqk[k2 * 1024 + i] * dummy[k2];
    g_wtilde[i] = s;
}

// ---------------- fp32 -> fp16 hi(/lo) conversion ----------------------------
__global__ void conv_kernel(const float* __restrict__ src,
                            half* __restrict__ hi, half* __restrict__ lo,
                            int cols4, int lddst) {
    int i4 = blockIdx.x * 256 + threadIdx.x;
    float4 v = ((const float4*)src)[i4];
    long long row = i4 / cols4;
    int c4 = i4 % cols4;
    long long o = row * (long long)lddst + (long long)c4 * 4;
    half h0, h1, h2, h3, l0, l1, l2, l3;
    hilo(v.x, h0, l0); hilo(v.y, h1, l1); hilo(v.z, h2, l2); hilo(v.w, h3, l3);
    uint2 uh; uh.x = pack2(h0, h1); uh.y = pack2(h2, h3);
    *(uint2*)(hi + o) = uh;
    if (lo) {
        uint2 ul; ul.x = pack2(l0, l1); ul.y = pack2(l2, l3);
        *(uint2*)(lo + o) = ul;
    }
}

// ---------------- transpose + convert (optionally gathered, lo optional) -----
__global__ void transpose_conv_kernel(const float* __restrict__ src,
                                      half* __restrict__ dhi, half* __restrict__ dlo,
                                      int gathered) {
    __shared__ float tile[64][65];
    int b = blockIdx.z;
    int t0 = blockIdx.y * 64;
    int d0 = blockIdx.x * 64;
    int tid = threadIdx.x;
#pragma unroll
    for (int j = 0; j < 4; j++) {
        int i = tid + j * 256;
        int r = i >> 4;
        int c4 = i & 15;
        int tg = t0 + r;
        int srow = tg;
        bool z = false;
        if (gathered) { z = (g_mask[tg] == 0); srow = g_pos[tg]; }
        float4 v = z ? make_float4(0.f, 0.f, 0.f, 0.f)
                     : ((const float4*)src)[((long long)b * NT + srow) * 256 + (d0 >> 2) + c4];
        tile[r][c4 * 4 + 0] = v.x; tile[r][c4 * 4 + 1] = v.y;
        tile[r][c4 * 4 + 2] = v.z; tile[r][c4 * 4 + 3] = v.w;
    }
    __syncthreads();
#pragma unroll
    for (int j = 0; j < 4; j++) {
        int i = tid + j * 256;
        int r = i >> 4;
        int c4 = i & 15;
        half h[4], l[4];
#pragma unroll
        for (int e = 0; e < 4; e++) hilo(tile[c4 * 4 + e][r], h[e], l[e]);
        long long o = ((long long)b * ND + d0 + r) * (long long)NT + t0 + c4 * 4;
        uint2 uh; uh.x = pack2(h[0], h[1]); uh.y = pack2(h[2], h[3]);
        *(uint2*)(dhi + o) = uh;
        if (dlo) {
            uint2 ul; ul.x = pack2(l[0], l[1]); ul.y = pack2(l[2], l[3]);
            *(uint2*)(dlo + o) = ul;
        }
    }
}

// ---------------- split-fp16 HMMA GEMM (NT): C = Ah*(Bh[+Bl])^T --------------
// CTA tile 128x128, 8 warps (2m x 4n), warp tile 64x32, K-chunk 64.
// HAS_LO=1: 2-stage x 48KB (A+Bh+Bl). HAS_LO=0: 3-stage x 32KB (A+Bh).
// Both = 96KB smem -> 2 CTAs/SM.
// mode: 0 = fp32 C (+bias), 1 = fp16-hi C (+bias+relu), 2 = fp16 hi+lo C,
//       3 = fused: out -> X1=out*q, X2=q-out (fp16 hi).
#define KC      64
#define SMEM_BYTES 98304

template <int HAS_LO>
__global__ void __launch_bounds__(256, 2) gemm_fp16_kernel(
    const half* __restrict__ Ahi, int lda, long long sA,
    const half* __restrict__ Bhi, const half* __restrict__ Blo, int ldb, long long sB,
    float* __restrict__ Cf, half* __restrict__ Chi, half* __restrict__ Clo,
    half* __restrict__ X1, half* __restrict__ X2, const float* __restrict__ qsrc,
    int ldc, long long sC, int coloff,
    int K, const float* __restrict__ bias, int relu, int mode)
{
    constexpr int STAGES  = HAS_LO ? 2 : 3;
    constexpr int STAGE_B = HAS_LO ? 49152 : 32768;
    constexpr int OFF_BH  = 16384;
    constexpr int OFF_BL  = 32768;   // only used when HAS_LO

    extern __shared__ __align__(1024) char smem[];
    const uint32_t sb = smem_u32(smem);
    const int tid = threadIdx.x;
    const int wid = tid >> 5;
    const int l   = tid & 31;

    const long long bz = blockIdx.z;
    const half* pAh = Ahi + bz * sA + (long long)(blockIdx.y * 128) * lda;
    const half* pBh = Bhi + bz * sB + (long long)(blockIdx.x * 128) * ldb;
    const half* pBl = HAS_LO ? Blo + bz * sB + (long long)(blockIdx.x * 128) * ldb : pBh;
    const int S = K / KC;

    // loaders: 2 threads per row, 4 x 16B chunks each (128 rows)
    const int crow = tid >> 1;
    const int cc0  = (tid & 1) << 2;

    auto load_stage = [&](int s) {
        uint32_t bp = sb + (uint32_t)(s % STAGES) * STAGE_B;
        long long k0 = (long long)s * KC;
        const half* rA = pAh + (long long)crow * lda + k0;
        const half* rBh = pBh + (long long)crow * ldb + k0;
        const half* rBl = pBl + (long long)crow * ldb + k0;
        uint32_t rowo = (uint32_t)crow * 128;
        uint32_t x = (uint32_t)(crow & 7) << 4;
#pragma unroll
        for (int j = 0; j < 4; j++) {
            int c = cc0 + j;
            uint32_t o = rowo + (((uint32_t)c << 4) ^ x);
            cp16(bp + o, rA + c * 8);
            cp16(bp + OFF_BH + o, rBh + c * 8);
            if (HAS_LO) cp16(bp + OFF_BL + o, rBl + c * 8);
        }
    };

    // prologue: fill STAGES-1 buffers
#pragma unroll
    for (int p = 0; p < STAGES - 1; p++) { load_stage(p); cp_commit(); }

    const int wm = wid & 1;          // 0..1 -> 64-row half
    const int wn = wid >> 1;         // 0..3 -> 32-col quarter
    const int arow = wm * 64 + (l & 15);
    const uint32_t aco = ((uint32_t)(l >> 4) << 4);
    const uint32_t axor = (uint32_t)(arow & 7) << 4;
    const int brow = wn * 32 + (l & 7) + ((l >> 4) << 3);
    const uint32_t bco = ((uint32_t)((l >> 3) & 1) << 4);
    const uint32_t bxor = (uint32_t)(brow & 7) << 4;

    float acc[4][4][4];
#pragma unroll
    for (int mf = 0; mf < 4; mf++)
#pragma unroll
        for (int nf = 0; nf < 4; nf++)
#pragma unroll
            for (int e = 0; e < 4; e++) acc[mf][nf][e] = 0.f;

    for (int s = 0; s < S; s++) {
        // issue next prefetch into buffer (s+STAGES-1)%STAGES — disjoint from
        // compute buffer s%STAGES and all other in-flight buffers; overwrite of
        // s%STAGES happens only at load(s+STAGES), after compute(s)'s sync.
        if (s + STAGES - 1 < S) { load_stage(s + STAGES - 1); cp_commit(); }
        int pend = S - 1 - s;
        if (pend > STAGES - 1) pend = STAGES - 1;
        if (pend >= 2)      asm volatile("cp.async.wait_group 2;" ::: "memory");
        else if (pend == 1) asm volatile("cp.async.wait_group 1;" ::: "memory");
        else                asm volatile("cp.async.wait_group 0;" ::: "memory");
        __syncthreads();

        uint32_t bp = sb + (uint32_t)(s % STAGES) * STAGE_B;
        uint32_t aBase = bp + (uint32_t)arow * 128;
        uint32_t bBaseH = bp + OFF_BH + (uint32_t)brow * 128;
        uint32_t bBaseL = bp + OFF_BL + (uint32_t)brow * 128;

#pragma unroll
        for (int k16 = 0; k16 < KC / 16; k16++) {
            uint32_t ak = (((uint32_t)k16 << 5) + aco) ^ axor;
            uint32_t bk = (((uint32_t)k16 << 5) + bco) ^ bxor;
            uint32_t ah[4][4], bh[4][2], bl[4][2];
#pragma unroll
            for (int mf = 0; mf < 4; mf++)
                ldm4(ah[mf], aBase + (uint32_t)(mf * 16) * 128 + ak);
#pragma unroll
            for (int g = 0; g < 2; g++) {
                uint32_t r[4];
                ldm4(r, bBaseH + (uint32_t)(g * 16) * 128 + bk);
                bh[g*2][0] = r[0]; bh[g*2][1] = r[1];
                bh[g*2+1][0] = r[2]; bh[g*2+1][1] = r[3];
                if (HAS_LO) {
                    ldm4(r, bBaseL + (uint32_t)(g * 16) * 128 + bk);
                    bl[g*2][0] = r[0]; bl[g*2][1] = r[1];
                    bl[g*2+1][0] = r[2]; bl[g*2+1][1] = r[3];
                }
            }
#pragma unroll
            for (int mf = 0; mf < 4; mf++)
#pragma unroll
                for (int nf = 0; nf < 4; nf++) {
                    mma16816(acc[mf][nf], ah[mf], bh[nf]);
                    if (HAS_LO) mma16816(acc[mf][nf], ah[mf], bl[nf]);
                }
        }
        __syncthreads();   // compute(s) done before buffer s%STAGES is reloaded
    }

    // ---- epilogue -----------------------------------------------------------
    const int gi0 = blockIdx.y * 128 + wm * 64 + (l >> 2);
    const int gj0 = blockIdx.x * 128 + wn * 32 + 2 * (l & 3);
#pragma unroll
    for (int mf = 0; mf < 4; mf++) {
        int gi = gi0 + mf * 16;
#pragma unroll
        for (int nf = 0; nf < 4; nf++) {
            int gj = gj0 + nf * 8;
            float v0 = acc[mf][nf][0], v1 = acc[mf][nf][1];
            float v2 = acc[mf][nf][2], v3 = acc[mf][nf][3];
            if (bias) {
                float b0 = bias[gj], b1 = bias[gj + 1];
                v0 += b0; v1 += b1; v2 += b0; v3 += b1;
            }
            if (relu) {
                v0 = fmaxf(v0, 0.f); v1 = fmaxf(v1, 0.f);
                v2 = fmaxf(v2, 0.f); v3 = fmaxf(v3, 0.f);
            }
            long long o0 = bz * sC + (long long)gi * ldc + coloff + gj;
            long long o1 = o0 + (long long)8 * ldc;
            if (mode == 0) {
                *(float2*)(Cf + o0) = make_float2(v0, v1);
                *(float2*)(Cf + o1) = make_float2(v2, v3);
            } else if (mode == 1) {
                *(uint32_t*)(Chi + o0) = pack2(__float2half_rn(v0), __float2half_rn(v1));
                *(uint32_t*)(Chi + o1) = pack2(__float2half_rn(v2), __float2half_rn(v3));
            } else if (mode == 2) {
                half h0, h1, h2, h3, l0, l1, l2, l3;
                hilo(v0, h0, l0); hilo(v1, h1, l1);
                hilo(v2, h2, l2); hilo(v3, h3, l3);
                *(uint32_t*)(Chi + o0) = pack2(h0, h1);
                *(uint32_t*)(Clo + o0) = pack2(l0, l1);
                *(uint32_t*)(Chi + o1) = pack2(h2, h3);
                *(uint32_t*)(Clo + o1) = pack2(l2, l3);
            } else {
                float2 q0 = *(const float2*)(qsrc + o0);
                float2 q1 = *(const float2*)(qsrc + o1);
                *(uint32_t*)(X1 + o0) = pack2(__float2half_rn(v0 * q0.x),
                                              __float2half_rn(v1 * q0.y));
                *(uint32_t*)(X1 + o1) = pack2(__float2half_rn(v2 * q1.x),
                                              __float2half_rn(v3 * q1.y));
                *(uint32_t*)(X2 + o0) = pack2(__float2half_rn(q0.x - v0),
                                              __float2half_rn(q0.y - v1));
                *(uint32_t*)(X2 + o1) = pack2(__float2half_rn(q1.x - v2),
                                              __float2half_rn(q1.y - v3));
            }
        }
    }
}

// ---------------- softmax with in-kernel gather + dummy column ---------------
// sdum = q_row . wtilde  (fp32, exact), vals[t] = mask[t] ? s[pos[t]] : sdum.
__global__ void softmax_kernel(const float* __restrict__ q) {
    const long long r = blockIdx.x;
    const float* srow = g_attn + r * 1024;
    const float* qrow = q + r * 1024;
    const int tid = threadIdx.x;
    __shared__ float sred[8];
    __shared__ float sbc;

    float sd = 0.f;
    for (int j4 = tid; j4 < 256; j4 += 256) {
        float4 qv = ((const float4*)qrow)[j4];
        float4 wv = ((const float4*)g_wtilde)[j4];
        sd += qv.x * wv.x + qv.y * wv.y + qv.z * wv.z + qv.w * wv.w;
    }
#pragma unroll
    for (int o = 16; o; o >>= 1) sd += __shfl_xor_sync(0xffffffffu, sd, o);
    if ((tid & 31) == 0) sred[tid >> 5] = sd;
    __syncthreads();
    if (tid == 0) {
        float t = 0.f;
#pragma unroll
        for (int i = 0; i < 8; i++) t += sred[i];
        sbc = t;
    }
    __syncthreads();
    const float sdum = sbc;

    float val[4];
    float lm = sdum;
#pragma unroll
    for (int jj = 0; jj < 4; jj++) {
        int j = tid + jj * 256;
        val[jj] = g_mask[j] ? srow[g_pos[j]] : sdum;
        lm = fmaxf(lm, val[jj]);
    }
#pragma unroll
    for (int o = 16; o; o >>= 1) lm = fmaxf(lm, __shfl_xor_sync(0xffffffffu, lm, o));
    if ((tid & 31) == 0) sred[tid >> 5] = lm;
    __syncthreads();
    float m = sred[0];
#pragma unroll
    for (int i = 1; i < 8; i++) m = fmaxf(m, sred[i]);

    const float invT = 0.03125f;
    float e[4];
    float ls = (tid == 0) ? __expf((sdum - m) * invT) : 0.f;
#pragma unroll
    for (int jj = 0; jj < 4; jj++) {
        e[jj] = __expf((val[jj] - m) * invT);
        ls += e[jj];
    }
#pragma unroll
    for (int o = 16; o; o >>= 1) ls += __shfl_xor_sync(0xffffffffu, ls, o);
    if ((tid & 31) == 0) sred[tid >> 5] = ls;
    __syncthreads();
    float s = 0.f;
#pragma unroll
    for (int i = 0; i < 8; i++) s += sred[i];
    float inv = 1.f / s;
    long long ob = r * (long long)NT;
#pragma unroll
    for (int jj = 0; jj < 4; jj++)
        g_at_hi[ob + tid + jj * 256] = __float2half_rn(e[jj] * inv);
}

// ---------------- host launcher ----------------------------------------------
extern "C" void kernel_launch(void* const* d_in, const int* in_sizes, int n_in,
                              void* d_out, int out_size) {
    const float* q     = (const float*)d_in[0];
    const float* k     = (const float*)d_in[1];
    const float* v     = (const float*)d_in[2];
    const float* tsp   = (const float*)d_in[3];
    const int*   supp  = (const int*)  d_in[4];
    const float* w_qk  = (const float*)d_in[5];
    const float* dummy = (const float*)d_in[6];
    const float* w1    = (const float*)d_in[7];
    const float* b1    = (const float*)d_in[8];
    const float* w2    = (const float*)d_in[9];
    const float* b2    = (const float*)d_in[10];
    const float* w3    = (const float*)d_in[11];
    const float* b3    = (const float*)d_in[12];
    float* outp = (float*)d_out;
    float* tsp_outp = outp + (long long)NB * NLQ * ND;

    cudaFuncSetAttribute(gemm_fp16_kernel<1>,
                         cudaFuncAttributeMaxDynamicSharedMemorySize, SMEM_BYTES);
    cudaFuncSetAttribute(gemm_fp16_kernel<0>,
                         cudaFuncAttributeMaxDynamicSharedMemorySize, SMEM_BYTES);

    half *xcat_hi, *k_hi, *wT_hi, *wT_lo, *G_hi, *G_lo;
    half *w1_hi, *w1_lo, *w2_hi, *w2_lo, *w3_hi;
    half *U_hi;
    half *vT_hi, *tT_hi, *at_hi, *x1_hi, *x2_hi;
    float *attn;
    cudaGetSymbolAddress((void**)&xcat_hi, g_xcat_hi);
    cudaGetSymbolAddress((void**)&k_hi, g_k_hi);
    cudaGetSymbolAddress((void**)&wT_hi, g_wT_hi);
    cudaGetSymbolAddress((void**)&wT_lo, g_wT_lo);
    cudaGetSymbolAddress((void**)&G_hi, g_G_hi);
    cudaGetSymbolAddress((void**)&G_lo, g_G_lo);
    cudaGetSymbolAddress((void**)&w1_hi, g_w1_hi);
    cudaGetSymbolAddress((void**)&w1_lo, g_w1_lo);
    cudaGetSymbolAddress((void**)&w2_hi, g_w2_hi);
    cudaGetSymbolAddress((void**)&w2_lo, g_w2_lo);
    cudaGetSymbolAddress((void**)&w3_hi, g_w3_hi);
    cudaGetSymbolAddress((void**)&U_hi, g_U_hi);
    cudaGetSymbolAddress((void**)&vT_hi, g_vT_hi);
    cudaGetSymbolAddress((void**)&tT_hi, g_tT_hi);
    cudaGetSymbolAddress((void**)&at_hi, g_at_hi);
    cudaGetSymbolAddress((void**)&x1_hi, g_x1_hi);
    cudaGetSymbolAddress((void**)&x2_hi, g_x2_hi);
    cudaGetSymbolAddress((void**)&attn, g_attn);

    // 1) pos/mask + w~ = W^T dummy
    pos_kernel<<<1, 1024>>>(supp);
    wtilde_kernel<<<4, 256>>>(w_qk, dummy);

    // 2) conversions
    conv_kernel<<<32768, 256>>>(q, xcat_hi + 1024, (half*)0, 256, 2048);
    conv_kernel<<<32768, 256>>>(k, k_hi, (half*)0, 256, 1024);
    conv_kernel<<<512, 256>>>(w1, w1_hi, w1_lo, 256, 1024);
    conv_kernel<<<512, 256>>>(w2, w2_hi, w2_lo, 256, 1024);
    conv_kernel<<<2048, 256>>>(w3, w3_hi, (half*)0, 512, 2048);

    // 3) W^T (hi+lo) via transpose; then G = W^T W (hi+lo out)
    transpose_conv_kernel<<<dim3(16, 16, 1), 256>>>(w_qk, wT_hi, wT_lo, 0);
    gemm_fp16_kernel<1><<<dim3(8, 8, 1), 256, SMEM_BYTES>>>(
        wT_hi, 1024, 0, wT_hi, wT_lo, 1024, 0,
        (float*)0, G_hi, G_lo, (half*)0, (half*)0, (const float*)0,
        1024, 0, 0, 1024, (const float*)0, 0, 2);

    // 4) U = k @ G  (hi out; B keeps G hi+lo for accuracy)
    gemm_fp16_kernel<1><<<dim3(8, 256, 1), 256, SMEM_BYTES>>>(
        k_hi, 1024, 0, G_hi, G_lo, 1024, 0,
        (float*)0, U_hi, (half*)0, (half*)0, (half*)0, (const float*)0,
        1024, 0, 0, 1024, (const float*)0, 0, 1);

    // 5) build vT (gathered) / tT — hi only
    transpose_conv_kernel<<<dim3(16, 16, NB), 256>>>(v, vT_hi, (half*)0, 1);
    transpose_conv_kernel<<<dim3(16, 16, NB), 256>>>(tsp, tT_hi, (half*)0, 0);

    // 6) scores = q @ U^T  (fp32, batched; hi-only, 3-stage)
    gemm_fp16_kernel<0><<<dim3(8, 8, NB), 256, SMEM_BYTES>>>(
        xcat_hi + 1024, 2048, (long long)NLQ * 2048,
        U_hi, (half*)0, 1024, (long long)NT * ND,
        attn, (half*)0, (half*)0, (half*)0, (half*)0, (const float*)0,
        1024, (long long)NLQ * NT, 0, 1024, (const float*)0, 0, 0);

    // 7) softmax (gather + exact fp32 dummy column) -> attn fp16
    softmax_kernel<<<NB * NLQ, 256>>>(q);

    // 8) out = attn @ v_sel (hi-only, 3-stage), fused x1 = out*q, x2 = q-out
    gemm_fp16_kernel<0><<<dim3(8, 8, NB), 256, SMEM_BYTES>>>(
        at_hi, 1024, (long long)NLQ * ND, vT_hi, (half*)0, 1024, (long long)ND * NT,
        (float*)0, (half*)0, (half*)0, x1_hi, x2_hi, q,
        1024, (long long)NLQ * ND, 0, 1024, (const float*)0, 0, 3);

    // 9) tsp_out = attn @ tsp (hi-only, 3-stage) -> second output (fp32)
    gemm_fp16_kernel<0><<<dim3(8, 8, NB), 256, SMEM_BYTES>>>(
        at_hi, 1024, (long long)NLQ * ND, tT_hi, (half*)0, 1024, (long long)ND * NT,
        tsp_outp, (half*)0, (half*)0, (half*)0, (half*)0, (const float*)0,
        1024, (long long)NLQ * ND, 0, 1024, (const float*)0, 0, 0);

    // 10) o1 = relu(x1 @ w1^T + b1) -> xcat[:, 0:512] (hi; w1 keeps lo)
    gemm_fp16_kernel<1><<<dim3(4, 256, 1), 256, SMEM_BYTES>>>(
        x1_hi, 1024, 0, w1_hi, w1_lo, 1024, 0,
        (float*)0, xcat_hi, (half*)0, (half*)0, (half*)0, (const float*)0,
        2048, 0, 0, 1024, b1, 1, 1);

    // 11) o2 = relu(x2 @ w2^T + b2) -> xcat[:, 512:1024] (hi; w2 keeps lo)
    gemm_fp16_kernel<1><<<dim3(4, 256, 1), 256, SMEM_BYTES>>>(
        x2_hi, 1024, 0, w2_hi, w2_lo, 1024, 0,
        (float*)0, xcat_hi, (half*)0, (half*)0, (half*)0, (const float*)0,
        2048, 0, 512, 1024, b2, 1, 1);

    // 12) output = xcat @ w3^T + b3 -> first output (fp32; hi-only, 3-stage)
    gemm_fp16_kernel<0><<<dim3(8, 256, 1), 256, SMEM_BYTES>>>(
        xcat_hi, 2048, 0, w3_hi, (half*)0, 2048, 0,
        outp, (half*)0, (half*)0, (half*)0, (half*)0, (const float*)0,
        1024, 0, 0, 2048, b3, 0, 0);
}